// round 2
// baseline (speedup 1.0000x reference)
#include <cuda_runtime.h>
#include <cuda_bf16.h>
#include <math.h>

// Problem dims
#define BATCH 2
#define SEQN 2048
#define SEQM 2048
#define DIM 512
#define NH 8
#define HE 64
#define FF 2048
#define ROWS (BATCH * SEQN)   // 4096
#define LN_EPS 1e-5f
#define ATTN_EPS 1e-6f

// ---------------- scratch (device globals; no allocations allowed) ----------
__device__ float g_qvk [ROWS * 3 * DIM];   // 25 MB
__device__ float g_attn1[ROWS * DIM];      // 8 MB
__device__ float g_ln1 [ROWS * DIM];       // 8 MB
__device__ float g_kv  [ROWS * 2 * DIM];   // 16 MB
__device__ float g_q2  [ROWS * DIM];       // 8 MB
__device__ float g_colmax[BATCH * DIM];
__device__ float g_colsum[BATCH * DIM];
__device__ float g_ctx [BATCH * NH * HE * HE];  // 256 KB
__device__ float g_ln2 [ROWS * DIM];       // 8 MB
__device__ float g_ff1 [ROWS * FF];        // 32 MB
__device__ float g_pre3[ROWS * DIM];       // 8 MB

// ---------------- tiled fp32 GEMM: C = A(MxK) * B(KxN) + bias, opt relu -----
// 128x128 block tile, BK=8, 256 threads, 8x8 micro-tile (4+4 split).
#define BM 128
#define BN 128
#define BK 8

__global__ __launch_bounds__(256)
void gemm_kernel(const float* __restrict__ A, const float* __restrict__ B,
                 const float* __restrict__ bias, float* __restrict__ C,
                 int M, int N, int K, int relu)
{
    __shared__ __align__(16) float As[BK][BM];
    __shared__ __align__(16) float Bs[BK][BN];
    const int tid = threadIdx.x;
    const int tx = tid & 15, ty = tid >> 4;
    const int row0 = blockIdx.y * BM, col0 = blockIdx.x * BN;

    // load indices
    const int ar = tid >> 1;            // 0..127
    const int ac = (tid & 1) * 4;       // 0 or 4
    const int br = tid >> 5;            // 0..7
    const int bc = (tid & 31) * 4;      // 0..124

    float acc[8][8] = {};
    for (int k0 = 0; k0 < K; k0 += BK) {
        float4 a = *(const float4*)(A + (size_t)(row0 + ar) * K + k0 + ac);
        As[ac + 0][ar] = a.x; As[ac + 1][ar] = a.y;
        As[ac + 2][ar] = a.z; As[ac + 3][ar] = a.w;
        *(float4*)&Bs[br][bc] = *(const float4*)(B + (size_t)(k0 + br) * N + col0 + bc);
        __syncthreads();
        #pragma unroll
        for (int kk = 0; kk < BK; kk++) {
            float4 a0 = *(const float4*)&As[kk][ty * 4];
            float4 a1 = *(const float4*)&As[kk][64 + ty * 4];
            float4 b0 = *(const float4*)&Bs[kk][tx * 4];
            float4 b1 = *(const float4*)&Bs[kk][64 + tx * 4];
            float av[8] = {a0.x, a0.y, a0.z, a0.w, a1.x, a1.y, a1.z, a1.w};
            float bv[8] = {b0.x, b0.y, b0.z, b0.w, b1.x, b1.y, b1.z, b1.w};
            #pragma unroll
            for (int i = 0; i < 8; i++)
                #pragma unroll
                for (int j = 0; j < 8; j++)
                    acc[i][j] += av[i] * bv[j];
        }
        __syncthreads();
    }
    // epilogue: rows {ty*4+i, 64+ty*4+i}, cols {tx*4.., 64+tx*4..}
    #pragma unroll
    for (int i = 0; i < 8; i++) {
        int r = row0 + ((i < 4) ? (ty * 4 + i) : (64 + ty * 4 + i - 4));
        #pragma unroll
        for (int jh = 0; jh < 2; jh++) {
            int c = col0 + jh * 64 + tx * 4;
            float4 o;
            o.x = acc[i][jh * 4 + 0] + bias[c + 0];
            o.y = acc[i][jh * 4 + 1] + bias[c + 1];
            o.z = acc[i][jh * 4 + 2] + bias[c + 2];
            o.w = acc[i][jh * 4 + 3] + bias[c + 3];
            if (relu) {
                o.x = fmaxf(o.x, 0.f); o.y = fmaxf(o.y, 0.f);
                o.z = fmaxf(o.z, 0.f); o.w = fmaxf(o.w, 0.f);
            }
            *(float4*)(C + (size_t)r * N + c) = o;
        }
    }
}

// ---------------- causal linear attention -----------------------------------
// One block per (b,h). 256 threads = 4 d-groups x 64 e. 64x64 state in regs.
// out[e] = (sum_d t[d]*S[d][e]) / (sum_d t[d]*(kcum[d]+eps)),  t = exp(q-max)
// (softmax normalization of q and the e^-0.5 scale cancel against d_inv)
__global__ void causal_attn_kernel(const float* __restrict__ qvk, float* __restrict__ out)
{
    const int bh = blockIdx.x;
    const int b = bh >> 3, h = bh & 7;
    const int tid = threadIdx.x;
    const int e = tid & 63, dg = tid >> 6;

    __shared__ float q_s[64], ks_s[64], v_s[64], t_s[64], kcum[64];
    __shared__ float part[4][64];
    __shared__ float s_dinv;

    float S[16];
    #pragma unroll
    for (int i = 0; i < 16; i++) S[i] = 0.f;
    if (tid < 64) kcum[tid] = 0.f;
    __syncthreads();

    const float* base = qvk + (size_t)b * SEQN * (3 * DIM) + h * HE;
    float* obase = out + (size_t)b * SEQN * DIM + h * HE;

    for (int n = 0; n < SEQN; n++) {
        const float* row = base + (size_t)n * (3 * DIM);
        if (tid < 64) {
            q_s[tid] = row[tid];                 // q
            float kk = expf(row[2 * DIM + tid]); // k
            ks_s[tid] = kk;
            kcum[tid] += kk;
            v_s[tid] = row[DIM + tid];           // v
        }
        __syncthreads();
        if (tid < 32) {
            float a0 = q_s[tid], a1 = q_s[tid + 32];
            float m = fmaxf(a0, a1);
            #pragma unroll
            for (int o = 16; o > 0; o >>= 1) m = fmaxf(m, __shfl_xor_sync(0xffffffffu, m, o));
            float t0 = expf(a0 - m), t1 = expf(a1 - m);
            t_s[tid] = t0; t_s[tid + 32] = t1;
            float den = t0 * (kcum[tid] + ATTN_EPS) + t1 * (kcum[tid + 32] + ATTN_EPS);
            #pragma unroll
            for (int o = 16; o > 0; o >>= 1) den += __shfl_xor_sync(0xffffffffu, den, o);
            if (tid == 0) s_dinv = 1.0f / den;
        }
        __syncthreads();
        {
            float p = 0.f;
            const float vv = v_s[e];
            #pragma unroll
            for (int i = 0; i < 16; i++) {
                int d = dg * 16 + i;
                S[i] += ks_s[d] * vv;       // inclusive state update
                p += t_s[d] * S[i];
            }
            part[dg][e] = p;
        }
        __syncthreads();
        if (tid < 64) {
            float o = (part[0][tid] + part[1][tid] + part[2][tid] + part[3][tid]) * s_dinv;
            obase[(size_t)n * DIM + tid] = o;
        }
    }
}

// ---------------- residual + layernorm (512 cols, 256 threads, 1 row/block) -
__global__ void ln_res_kernel(const float* __restrict__ a, const float* __restrict__ r,
                              const float* __restrict__ g, const float* __restrict__ beta,
                              float* __restrict__ out)
{
    const int row = blockIdx.x;
    const int tid = threadIdx.x;
    const int w = tid >> 5, lane = tid & 31;
    __shared__ float red[16];

    float pre[2], sum = 0.f, sumsq = 0.f;
    #pragma unroll
    for (int it = 0; it < 2; it++) {
        int o = tid + it * 256;
        float p = a[(size_t)row * DIM + o] + r[(size_t)row * DIM + o];
        pre[it] = p; sum += p; sumsq += p * p;
    }
    #pragma unroll
    for (int o = 16; o > 0; o >>= 1) {
        sum   += __shfl_xor_sync(0xffffffffu, sum, o);
        sumsq += __shfl_xor_sync(0xffffffffu, sumsq, o);
    }
    if (lane == 0) { red[w] = sum; red[8 + w] = sumsq; }
    __syncthreads();
    if (tid == 0) {
        float s = 0.f, q = 0.f;
        #pragma unroll
        for (int i = 0; i < 8; i++) { s += red[i]; q += red[8 + i]; }
        float mu = s / (float)DIM;
        float var = q / (float)DIM - mu * mu;
        red[0] = mu; red[1] = rsqrtf(var + LN_EPS);
    }
    __syncthreads();
    float mu = red[0], rstd = red[1];
    #pragma unroll
    for (int it = 0; it < 2; it++) {
        int o = tid + it * 256;
        out[(size_t)row * DIM + o] = (pre[it] - mu) * rstd * g[o] + beta[o];
    }
}

// ---------------- cross-attn: per-column softmax stats over memory rows -----
// grid (DIM/32, BATCH), 256 threads = 32 d-lanes x 8 row-groups
__global__ void col_stats_kernel(const float* __restrict__ kv,
                                 float* __restrict__ colmax, float* __restrict__ colsum)
{
    const int b = blockIdx.y;
    const int lane = threadIdx.x & 31;
    const int r = threadIdx.x >> 5;
    const int d = blockIdx.x * 32 + lane;
    const float* base = kv + (size_t)b * SEQM * (2 * DIM) + d;

    __shared__ float sm[8][32];
    __shared__ float cm[32];

    float m = -1e30f;
    for (int n = r; n < SEQM; n += 8) m = fmaxf(m, base[(size_t)n * (2 * DIM)]);
    sm[r][lane] = m;
    __syncthreads();
    if (threadIdx.x < 32) {
        float mm = sm[0][threadIdx.x];
        #pragma unroll
        for (int i = 1; i < 8; i++) mm = fmaxf(mm, sm[i][threadIdx.x]);
        cm[threadIdx.x] = mm;
        colmax[b * DIM + blockIdx.x * 32 + threadIdx.x] = mm;
    }
    __syncthreads();
    float s = 0.f;
    float mref = cm[lane];
    for (int n = r; n < SEQM; n += 8) s += expf(base[(size_t)n * (2 * DIM)] - mref);
    sm[r][lane] = s;
    __syncthreads();
    if (threadIdx.x < 32) {
        float ss = sm[0][threadIdx.x];
        #pragma unroll
        for (int i = 1; i < 8; i++) ss += sm[i][threadIdx.x];
        colsum[b * DIM + blockIdx.x * 32 + threadIdx.x] = ss;
    }
}

// ---------------- cross-attn: ctx[b,h,d,e] = sum_n softk(k)[n,d] * v[n,e] ---
// grid = B*H blocks, 256 threads (16x16, 4x4 micro-tile), k-loop over n tiles of 32
__global__ void cross_ctx_kernel(const float* __restrict__ kv,
                                 const float* __restrict__ colmax, const float* __restrict__ colsum,
                                 float* __restrict__ ctx)
{
    const int bh = blockIdx.x;
    const int b = bh >> 3, h = bh & 7;
    const int tid = threadIdx.x;
    const int tx = tid & 15, ty = tid >> 4;

    __shared__ __align__(16) float Ks[32][64];
    __shared__ __align__(16) float Vs[32][64];
    __shared__ float cm[64], ci[64];

    if (tid < 64) {
        cm[tid] = colmax[b * DIM + h * HE + tid];
        ci[tid] = 1.0f / colsum[b * DIM + h * HE + tid];
    }
    __syncthreads();

    float acc[4][4] = {};
    const float* base = kv + (size_t)b * SEQM * (2 * DIM) + h * HE;
    for (int n0 = 0; n0 < SEQM; n0 += 32) {
        #pragma unroll
        for (int it = 0; it < 2; it++) {
            int f4 = tid + it * 256;      // 0..511 (float4 units over 32x64)
            int r = f4 >> 4;
            int c = (f4 & 15) * 4;
            const float* rp = base + (size_t)(n0 + r) * (2 * DIM);
            float4 kk = *(const float4*)(rp + c);
            float4 vv = *(const float4*)(rp + DIM + c);
            Ks[r][c + 0] = expf(kk.x - cm[c + 0]) * ci[c + 0];
            Ks[r][c + 1] = expf(kk.y - cm[c + 1]) * ci[c + 1];
            Ks[r][c + 2] = expf(kk.z - cm[c + 2]) * ci[c + 2];
            Ks[r][c + 3] = expf(kk.w - cm[c + 3]) * ci[c + 3];
            *(float4*)&Vs[r][c] = vv;
        }
        __syncthreads();
        #pragma unroll
        for (int r = 0; r < 32; r++) {
            float4 av = *(const float4*)&Ks[r][ty * 4];
            float4 bv = *(const float4*)&Vs[r][tx * 4];
            float a[4] = {av.x, av.y, av.z, av.w};
            float bb[4] = {bv.x, bv.y, bv.z, bv.w};
            #pragma unroll
            for (int i = 0; i < 4; i++)
                #pragma unroll
                for (int j = 0; j < 4; j++)
                    acc[i][j] += a[i] * bb[j];
        }
        __syncthreads();
    }
    float* cb = ctx + (size_t)bh * (HE * HE);
    #pragma unroll
    for (int i = 0; i < 4; i++)
        #pragma unroll
        for (int j = 0; j < 4; j++)
            cb[(ty * 4 + i) * HE + tx * 4 + j] = acc[i][j];
}

// ---------------- cross-attn output + residual + LN2 (fused, 1 row/block) --
__global__ void cross_out_ln2_kernel(const float* __restrict__ q2, const float* __restrict__ ctx,
                                     const float* __restrict__ res, const float* __restrict__ g,
                                     const float* __restrict__ beta, float* __restrict__ out)
{
    const int row = blockIdx.x;
    const int b = row >> 11;
    const int tid = threadIdx.x;
    const int w = tid >> 5, lane = tid & 31;

    __shared__ float qs_s[DIM];
    __shared__ float red[16];

    const float* qr = q2 + (size_t)row * DIM;
    { // per-head softmax of q (warp w handles head w)
        float a0 = qr[w * HE + lane], a1 = qr[w * HE + 32 + lane];
        float m = fmaxf(a0, a1);
        #pragma unroll
        for (int o = 16; o > 0; o >>= 1) m = fmaxf(m, __shfl_xor_sync(0xffffffffu, m, o));
        float t0 = expf(a0 - m), t1 = expf(a1 - m);
        float s = t0 + t1;
        #pragma unroll
        for (int o = 16; o > 0; o >>= 1) s += __shfl_xor_sync(0xffffffffu, s, o);
        float sc = 0.125f / s;   // * HE^-0.5
        qs_s[w * HE + lane] = t0 * sc;
        qs_s[w * HE + 32 + lane] = t1 * sc;
    }
    __syncthreads();

    float pre[2], sum = 0.f, sumsq = 0.f;
    #pragma unroll
    for (int it = 0; it < 2; it++) {
        int o = tid + it * 256;
        int h = o >> 6, e = o & 63;
        const float* cb = ctx + ((size_t)(b * NH + h)) * (HE * HE) + e;
        const float* qh = qs_s + h * HE;
        float acc = 0.f;
        #pragma unroll 8
        for (int d = 0; d < HE; d++) acc += qh[d] * cb[d * HE];
        float p = acc + res[(size_t)row * DIM + o];
        pre[it] = p; sum += p; sumsq += p * p;
    }
    #pragma unroll
    for (int o = 16; o > 0; o >>= 1) {
        sum   += __shfl_xor_sync(0xffffffffu, sum, o);
        sumsq += __shfl_xor_sync(0xffffffffu, sumsq, o);
    }
    if (lane == 0) { red[w] = sum; red[8 + w] = sumsq; }
    __syncthreads();
    if (tid == 0) {
        float s = 0.f, q = 0.f;
        #pragma unroll
        for (int i = 0; i < 8; i++) { s += red[i]; q += red[8 + i]; }
        float mu = s / (float)DIM;
        float var = q / (float)DIM - mu * mu;
        red[0] = mu; red[1] = rsqrtf(var + LN_EPS);
    }
    __syncthreads();
    float mu = red[0], rstd = red[1];
    #pragma unroll
    for (int it = 0; it < 2; it++) {
        int o = tid + it * 256;
        out[(size_t)row * DIM + o] = (pre[it] - mu) * rstd * g[o] + beta[o];
    }
}

// ---------------- host launch ------------------------------------------------
extern "C" void kernel_launch(void* const* d_in, const int* in_sizes, int n_in,
                              void* d_out, int out_size)
{
    const float* x      = (const float*)d_in[0];
    const float* memory = (const float*)d_in[1];
    const float* W_qvk  = (const float*)d_in[2];
    const float* b_qvk  = (const float*)d_in[3];
    const float* W_kv   = (const float*)d_in[4];
    const float* b_kv   = (const float*)d_in[5];
    const float* W_q    = (const float*)d_in[6];
    const float* b_q    = (const float*)d_in[7];
    const float* W_ff1  = (const float*)d_in[8];
    const float* b_ff1  = (const float*)d_in[9];
    const float* W_ff2  = (const float*)d_in[10];
    const float* b_ff2  = (const float*)d_in[11];
    const float* ln1_g  = (const float*)d_in[12];
    const float* ln1_b  = (const float*)d_in[13];
    const float* ln2_g  = (const float*)d_in[14];
    const float* ln2_b  = (const float*)d_in[15];
    const float* ln3_g  = (const float*)d_in[16];
    const float* ln3_b  = (const float*)d_in[17];
    float* outp = (float*)d_out;

    float *qvk, *attn1, *ln1, *kv, *q2, *colmax, *colsum, *ctx, *ln2, *ff1, *pre3;
    cudaGetSymbolAddress((void**)&qvk,   g_qvk);
    cudaGetSymbolAddress((void**)&attn1, g_attn1);
    cudaGetSymbolAddress((void**)&ln1,   g_ln1);
    cudaGetSymbolAddress((void**)&kv,    g_kv);
    cudaGetSymbolAddress((void**)&q2,    g_q2);
    cudaGetSymbolAddress((void**)&colmax,g_colmax);
    cudaGetSymbolAddress((void**)&colsum,g_colsum);
    cudaGetSymbolAddress((void**)&ctx,   g_ctx);
    cudaGetSymbolAddress((void**)&ln2,   g_ln2);
    cudaGetSymbolAddress((void**)&ff1,   g_ff1);
    cudaGetSymbolAddress((void**)&pre3,  g_pre3);

    // 1) qvk = x @ W_qvk + b
    gemm_kernel<<<dim3((3 * DIM) / BN, ROWS / BM), 256>>>(x, W_qvk, b_qvk, qvk, ROWS, 3 * DIM, DIM, 0);
    // 2) causal linear self-attention (merged heads)
    causal_attn_kernel<<<BATCH * NH, 256>>>(qvk, attn1);
    // 3) LN1(attn + x)
    ln_res_kernel<<<ROWS, 256>>>(attn1, x, ln1_g, ln1_b, ln1);
    // 4) kv = memory @ W_kv + b
    gemm_kernel<<<dim3((2 * DIM) / BN, ROWS / BM), 256>>>(memory, W_kv, b_kv, kv, ROWS, 2 * DIM, DIM, 0);
    // 5) q2 = ln1 @ W_q + b
    gemm_kernel<<<dim3(DIM / BN, ROWS / BM), 256>>>(ln1, W_q, b_q, q2, ROWS, DIM, DIM, 0);
    // 6) column softmax stats of k over memory rows
    col_stats_kernel<<<dim3(DIM / 32, BATCH), 256>>>(kv, colmax, colsum);
    // 7) ctx = softk^T @ v per head
    cross_ctx_kernel<<<BATCH * NH, 256>>>(kv, colmax, colsum, ctx);
    // 8) out2 = softmax(q2) @ ctx, + res, LN2 (fused)
    cross_out_ln2_kernel<<<ROWS, 256>>>(q2, ctx, ln1, ln2_g, ln2_b, ln2);
    // 9) ff1 = relu(ln2 @ W_ff1 + b)
    gemm_kernel<<<dim3(FF / BN, ROWS / BM), 256>>>(ln2, W_ff1, b_ff1, ff1, ROWS, FF, DIM, 1);
    // 10) pre3 = ff1 @ W_ff2 + b
    gemm_kernel<<<dim3(DIM / BN, ROWS / BM), 256>>>(ff1, W_ff2, b_ff2, pre3, ROWS, DIM, FF, 0);
    // 11) LN3(pre3 + ln2) -> output
    ln_res_kernel<<<ROWS, 256>>>(pre3, ln2, ln3_g, ln3_b, outp);
}

// round 4
// speedup vs baseline: 2.4039x; 2.4039x over previous
#include <cuda_runtime.h>
#include <cuda_bf16.h>
#include <math.h>

// Problem dims
#define BATCH 2
#define SEQN 2048
#define SEQM 2048
#define DIM 512
#define NH 8
#define HE 64
#define FF 2048
#define ROWS (BATCH * SEQN)   // 4096
#define LN_EPS 1e-5f
#define ATTN_EPS 1e-6f

// chunked causal linear attention
#define CC 64
#define NC (SEQN / CC)        // 32
#define BH (BATCH * NH)       // 16

// ---------------- scratch (device globals; no allocations allowed) ----------
__device__ float g_qvk [ROWS * 3 * DIM];   // 25 MB
__device__ float g_attn1[ROWS * DIM];      // 8 MB
__device__ float g_ln1 [ROWS * DIM];       // 8 MB
__device__ float g_kv  [ROWS * 2 * DIM];   // 16 MB
__device__ float g_q2  [ROWS * DIM];       // 8 MB
__device__ float g_colmax[BATCH * DIM];
__device__ float g_colsum[BATCH * DIM];
__device__ float g_ctx [BATCH * NH * HE * HE];  // 256 KB
__device__ float g_ln2 [ROWS * DIM];       // 8 MB
__device__ float g_ff1 [ROWS * FF];        // 32 MB
__device__ float g_pre3[ROWS * DIM];       // 8 MB
// causal-chunk state
__device__ float g_csumK [BH * NC * HE];            // 128 KB
__device__ float g_csumKV[BH * NC * HE * HE];       // 8 MB
__device__ float g_kcp   [BH * NC * HE];            // 128 KB
__device__ float g_Sp    [BH * NC * HE * HE];       // 8 MB

// ---------------- tiled fp32 GEMM: C = A(MxK) * B(KxN) + bias, opt relu -----
#define BM 128
#define BN 128
#define BK 8

__global__ __launch_bounds__(256)
void gemm_kernel(const float* __restrict__ A, const float* __restrict__ B,
                 const float* __restrict__ bias, float* __restrict__ C,
                 int M, int N, int K, int relu)
{
    __shared__ __align__(16) float As[BK][BM];
    __shared__ __align__(16) float Bs[BK][BN];
    const int tid = threadIdx.x;
    const int tx = tid & 15, ty = tid >> 4;
    const int row0 = blockIdx.y * BM, col0 = blockIdx.x * BN;

    const int ar = tid >> 1;
    const int ac = (tid & 1) * 4;
    const int br = tid >> 5;
    const int bc = (tid & 31) * 4;

    float acc[8][8] = {};
    for (int k0 = 0; k0 < K; k0 += BK) {
        float4 a = *(const float4*)(A + (size_t)(row0 + ar) * K + k0 + ac);
        As[ac + 0][ar] = a.x; As[ac + 1][ar] = a.y;
        As[ac + 2][ar] = a.z; As[ac + 3][ar] = a.w;
        *(float4*)&Bs[br][bc] = *(const float4*)(B + (size_t)(k0 + br) * N + col0 + bc);
        __syncthreads();
        #pragma unroll
        for (int kk = 0; kk < BK; kk++) {
            float4 a0 = *(const float4*)&As[kk][ty * 4];
            float4 a1 = *(const float4*)&As[kk][64 + ty * 4];
            float4 b0 = *(const float4*)&Bs[kk][tx * 4];
            float4 b1 = *(const float4*)&Bs[kk][64 + tx * 4];
            float av[8] = {a0.x, a0.y, a0.z, a0.w, a1.x, a1.y, a1.z, a1.w};
            float bv[8] = {b0.x, b0.y, b0.z, b0.w, b1.x, b1.y, b1.z, b1.w};
            #pragma unroll
            for (int i = 0; i < 8; i++)
                #pragma unroll
                for (int j = 0; j < 8; j++)
                    acc[i][j] += av[i] * bv[j];
        }
        __syncthreads();
    }
    #pragma unroll
    for (int i = 0; i < 8; i++) {
        int r = row0 + ((i < 4) ? (ty * 4 + i) : (64 + ty * 4 + i - 4));
        #pragma unroll
        for (int jh = 0; jh < 2; jh++) {
            int c = col0 + jh * 64 + tx * 4;
            float4 o;
            o.x = acc[i][jh * 4 + 0] + bias[c + 0];
            o.y = acc[i][jh * 4 + 1] + bias[c + 1];
            o.z = acc[i][jh * 4 + 2] + bias[c + 2];
            o.w = acc[i][jh * 4 + 3] + bias[c + 3];
            if (relu) {
                o.x = fmaxf(o.x, 0.f); o.y = fmaxf(o.y, 0.f);
                o.z = fmaxf(o.z, 0.f); o.w = fmaxf(o.w, 0.f);
            }
            *(float4*)(C + (size_t)r * N + c) = o;
        }
    }
}

// ---------------- causal chunk phase 1: per-chunk sums ----------------------
// grid = BH*NC, 256 threads. sumK[d] = sum_n exp(k), sumKV[d][e] = sum_n exp(k_d) v_e
__global__ __launch_bounds__(256)
void chunk_sum_kernel(const float* __restrict__ qvk,
                      float* __restrict__ csumK, float* __restrict__ csumKV)
{
    const int blk = blockIdx.x;
    const int bh = blk / NC, c = blk % NC;
    const int b = bh >> 3, h = bh & 7;
    const int tid = threadIdx.x;

    __shared__ __align__(16) float Ks[CC][68];
    __shared__ __align__(16) float Vs[CC][68];

    const float* base = qvk + (size_t)b * SEQN * (3 * DIM) + (size_t)c * CC * (3 * DIM) + h * HE;
    #pragma unroll
    for (int i = tid; i < CC * 16; i += 256) {       // 1024 float4s
        int r = i >> 4;
        int col = (i & 15) * 4;
        const float* rp = base + (size_t)r * (3 * DIM);
        float4 kk = *(const float4*)(rp + 2 * DIM + col);
        float4 vv = *(const float4*)(rp + DIM + col);
        Ks[r][col + 0] = expf(kk.x); Ks[r][col + 1] = expf(kk.y);
        Ks[r][col + 2] = expf(kk.z); Ks[r][col + 3] = expf(kk.w);
        *(float4*)&Vs[r][col] = vv;
    }
    __syncthreads();

    const int ty = tid >> 4, tx = tid & 15;
    const int d0 = ty * 4, e0 = tx * 4;
    float acc[4][4] = {};
    #pragma unroll 8
    for (int n = 0; n < CC; n++) {
        float4 a = *(const float4*)&Ks[n][d0];
        float4 bb = *(const float4*)&Vs[n][e0];
        float av[4] = {a.x, a.y, a.z, a.w};
        float bv[4] = {bb.x, bb.y, bb.z, bb.w};
        #pragma unroll
        for (int i = 0; i < 4; i++)
            #pragma unroll
            for (int j = 0; j < 4; j++)
                acc[i][j] += av[i] * bv[j];
    }
    float* outKV = csumKV + ((size_t)bh * NC + c) * (HE * HE);
    #pragma unroll
    for (int i = 0; i < 4; i++) {
        float4 o = {acc[i][0], acc[i][1], acc[i][2], acc[i][3]};
        *(float4*)(outKV + (d0 + i) * HE + e0) = o;
    }
    if (tid < HE) {
        float s = 0.f;
        #pragma unroll 8
        for (int n = 0; n < CC; n++) s += Ks[n][tid];
        csumK[((size_t)bh * NC + c) * HE + tid] = s;
    }
}

// ---------------- causal chunk phase 2: exclusive prefix over chunks --------
// grid = BH, 256 threads. Each thread owns 16 entries of the 64x64 state.
__global__ __launch_bounds__(256)
void prefix_kernel(const float* __restrict__ csumK, const float* __restrict__ csumKV,
                   float* __restrict__ kcp, float* __restrict__ Sp)
{
    const int bh = blockIdx.x;
    const int tid = threadIdx.x;
    float4 run[4];
    #pragma unroll
    for (int i = 0; i < 4; i++) run[i] = make_float4(0.f, 0.f, 0.f, 0.f);
    for (int c = 0; c < NC; c++) {
        size_t base = ((size_t)bh * NC + c) * (HE * HE) + (size_t)tid * 16;
        float4* dst = (float4*)(Sp + base);
        const float4* src = (const float4*)(csumKV + base);
        #pragma unroll
        for (int i = 0; i < 4; i++) {
            dst[i] = run[i];
            float4 s = src[i];
            run[i].x += s.x; run[i].y += s.y; run[i].z += s.z; run[i].w += s.w;
        }
    }
    if (tid < HE) {
        float rk = 0.f;
        for (int c = 0; c < NC; c++) {
            size_t o = ((size_t)bh * NC + c) * HE + tid;
            kcp[o] = rk;
            rk += csumK[o];
        }
    }
}

// ---------------- causal chunk phase 3: per-chunk output --------------------
// grid = BH*NC, 256 threads, ~88KB dynamic smem (2 CTA/SM).
// out_t = (masked(T K^T) V + T S_prev)_t / (rowsum(masked(T K^T)) + T.(kcp+eps))_t
__global__ __launch_bounds__(256)
void causal_chunk_kernel(const float* __restrict__ qvk,
                         const float* __restrict__ kcp, const float* __restrict__ Sp,
                         float* __restrict__ out)
{
    extern __shared__ __align__(16) float sm[];
    float (*TsT)[68] = (float(*)[68])sm;          // [64][68]  T transposed: TsT[d][t]
    float (*KsT)[68] = TsT + 64;                  // exp(k) transposed: KsT[d][s]
    float (*AT)[68]  = KsT + 64;                  // masked A transposed: AT[s][t]
    float (*Vs)[68]  = AT + 64;                   // V rows
    float (*SpS)[68] = Vs + 64;                   // S_prev rows
    float* kcpe = (float*)(SpS + 64);             // 64
    float* den  = kcpe + 64;                      // 64 (reciprocal)

    const int blk = blockIdx.x;
    const int bh = blk / NC, c = blk % NC;
    const int b = bh >> 3, h = bh & 7;
    const int tid = threadIdx.x;
    const float* base = qvk + (size_t)b * SEQN * (3 * DIM) + (size_t)c * CC * (3 * DIM) + h * HE;

    { // q -> rowmax -> T transposed; k -> exp -> transposed
        int r = tid >> 2;            // row 0..63
        int g = tid & 3;             // 4 threads/row, 16 cols each
        const float* rp = base + (size_t)r * (3 * DIM) + g * 16;
        float qv[16];
        float m = -1e30f;
        #pragma unroll
        for (int j = 0; j < 16; j++) { qv[j] = rp[j]; m = fmaxf(m, qv[j]); }
        m = fmaxf(m, __shfl_xor_sync(0xffffffffu, m, 1));
        m = fmaxf(m, __shfl_xor_sync(0xffffffffu, m, 2));
        #pragma unroll
        for (int j = 0; j < 16; j++) TsT[g * 16 + j][r] = expf(qv[j] - m);
        const float* rpk = rp + 2 * DIM;
        #pragma unroll
        for (int j = 0; j < 16; j++) KsT[g * 16 + j][r] = expf(rpk[j]);
    }
    #pragma unroll
    for (int i = tid; i < CC * 16; i += 256) {
        int r = i >> 4, col = (i & 15) * 4;
        *(float4*)&Vs[r][col] = *(const float4*)(base + (size_t)r * (3 * DIM) + DIM + col);
    }
    const float* spb = Sp + ((size_t)bh * NC + c) * (HE * HE);
    #pragma unroll
    for (int i = tid; i < HE * 16; i += 256) {
        int r = i >> 4, col = (i & 15) * 4;
        *(float4*)&SpS[r][col] = *(const float4*)(spb + r * HE + col);
    }
    if (tid < HE) kcpe[tid] = kcp[((size_t)bh * NC + c) * HE + tid] + ATTN_EPS;
    __syncthreads();

    const int ty = tid >> 4, tx = tid & 15;
    const int t0 = ty * 4, s0 = tx * 4;

    { // A[t][s] = sum_d T[t][d] ks[s][d]; store masked transposed
        float acc[4][4] = {};
        #pragma unroll 8
        for (int d = 0; d < HE; d++) {
            float4 a = *(const float4*)&TsT[d][t0];
            float4 bb = *(const float4*)&KsT[d][s0];
            float av[4] = {a.x, a.y, a.z, a.w};
            float bv[4] = {bb.x, bb.y, bb.z, bb.w};
            #pragma unroll
            for (int i = 0; i < 4; i++)
                #pragma unroll
                for (int j = 0; j < 4; j++)
                    acc[i][j] += av[i] * bv[j];
        }
        #pragma unroll
        for (int i = 0; i < 4; i++)
            #pragma unroll
            for (int j = 0; j < 4; j++) {
                int t = t0 + i, s = s0 + j;
                AT[s][t] = (s <= t) ? acc[i][j] : 0.f;
            }
    }
    __syncthreads();

    if (tid < 128) { // den[t] = sum_s AT[s][t] + sum_d T[t][d]*kcpe[d]
        int t = tid >> 1, half = tid & 1;
        float sd = 0.f;
        int lo = half * 32;
        #pragma unroll 8
        for (int s = lo; s < lo + 32; s++) sd += AT[s][t];
        #pragma unroll 8
        for (int d = lo; d < lo + 32; d++) sd += TsT[d][t] * kcpe[d];
        sd += __shfl_xor_sync(0xffffffffu, sd, 1);
        if (!half) den[t] = 1.0f / sd;
    }
    __syncthreads();

    { // num = A_masked @ V + T @ S_prev, then scale and store
        const int e0 = tx * 4;
        float o[4][4] = {};
        #pragma unroll 8
        for (int s = 0; s < CC; s++) {
            float4 a = *(const float4*)&AT[s][t0];
            float4 bb = *(const float4*)&Vs[s][e0];
            float av[4] = {a.x, a.y, a.z, a.w};
            float bv[4] = {bb.x, bb.y, bb.z, bb.w};
            #pragma unroll
            for (int i = 0; i < 4; i++)
                #pragma unroll
                for (int j = 0; j < 4; j++)
                    o[i][j] += av[i] * bv[j];
        }
        #pragma unroll 8
        for (int d = 0; d < HE; d++) {
            float4 a = *(const float4*)&TsT[d][t0];
            float4 bb = *(const float4*)&SpS[d][e0];
            float av[4] = {a.x, a.y, a.z, a.w};
            float bv[4] = {bb.x, bb.y, bb.z, bb.w};
            #pragma unroll
            for (int i = 0; i < 4; i++)
                #pragma unroll
                for (int j = 0; j < 4; j++)
                    o[i][j] += av[i] * bv[j];
        }
        float* ob = out + (size_t)b * SEQN * DIM + (size_t)c * CC * DIM + h * HE;
        #pragma unroll
        for (int i = 0; i < 4; i++) {
            float rcp = den[t0 + i];
            float4 ov = {o[i][0] * rcp, o[i][1] * rcp, o[i][2] * rcp, o[i][3] * rcp};
            *(float4*)(ob + (size_t)(t0 + i) * DIM + e0) = ov;
        }
    }
}

// ---------------- residual + layernorm (512 cols, 256 threads, 1 row/block) -
__global__ void ln_res_kernel(const float* __restrict__ a, const float* __restrict__ r,
                              const float* __restrict__ g, const float* __restrict__ beta,
                              float* __restrict__ out)
{
    const int row = blockIdx.x;
    const int tid = threadIdx.x;
    const int w = tid >> 5, lane = tid & 31;
    __shared__ float red[16];

    float pre[2], sum = 0.f, sumsq = 0.f;
    #pragma unroll
    for (int it = 0; it < 2; it++) {
        int o = tid + it * 256;
        float p = a[(size_t)row * DIM + o] + r[(size_t)row * DIM + o];
        pre[it] = p; sum += p; sumsq += p * p;
    }
    #pragma unroll
    for (int o = 16; o > 0; o >>= 1) {
        sum   += __shfl_xor_sync(0xffffffffu, sum, o);
        sumsq += __shfl_xor_sync(0xffffffffu, sumsq, o);
    }
    if (lane == 0) { red[w] = sum; red[8 + w] = sumsq; }
    __syncthreads();
    if (tid == 0) {
        float s = 0.f, q = 0.f;
        #pragma unroll
        for (int i = 0; i < 8; i++) { s += red[i]; q += red[8 + i]; }
        float mu = s / (float)DIM;
        float var = q / (float)DIM - mu * mu;
        red[0] = mu; red[1] = rsqrtf(var + LN_EPS);
    }
    __syncthreads();
    float mu = red[0], rstd = red[1];
    #pragma unroll
    for (int it = 0; it < 2; it++) {
        int o = tid + it * 256;
        out[(size_t)row * DIM + o] = (pre[it] - mu) * rstd * g[o] + beta[o];
    }
}

// ---------------- cross-attn: per-column softmax stats over memory rows -----
__global__ void col_stats_kernel(const float* __restrict__ kv,
                                 float* __restrict__ colmax, float* __restrict__ colsum)
{
    const int b = blockIdx.y;
    const int lane = threadIdx.x & 31;
    const int r = threadIdx.x >> 5;
    const int d = blockIdx.x * 32 + lane;
    const float* base = kv + (size_t)b * SEQM * (2 * DIM) + d;

    __shared__ float sm[8][32];
    __shared__ float cm[32];

    float m = -1e30f;
    for (int n = r; n < SEQM; n += 8) m = fmaxf(m, base[(size_t)n * (2 * DIM)]);
    sm[r][lane] = m;
    __syncthreads();
    if (threadIdx.x < 32) {
        float mm = sm[0][threadIdx.x];
        #pragma unroll
        for (int i = 1; i < 8; i++) mm = fmaxf(mm, sm[i][threadIdx.x]);
        cm[threadIdx.x] = mm;
        colmax[b * DIM + blockIdx.x * 32 + threadIdx.x] = mm;
    }
    __syncthreads();
    float s = 0.f;
    float mref = cm[lane];
    for (int n = r; n < SEQM; n += 8) s += expf(base[(size_t)n * (2 * DIM)] - mref);
    sm[r][lane] = s;
    __syncthreads();
    if (threadIdx.x < 32) {
        float ss = sm[0][threadIdx.x];
        #pragma unroll
        for (int i = 1; i < 8; i++) ss += sm[i][threadIdx.x];
        colsum[b * DIM + blockIdx.x * 32 + threadIdx.x] = ss;
    }
}

// ---------------- cross-attn: ctx[b,h,d,e] = sum_n softk(k)[n,d] * v[n,e] ---
__global__ void cross_ctx_kernel(const float* __restrict__ kv,
                                 const float* __restrict__ colmax, const float* __restrict__ colsum,
                                 float* __restrict__ ctx)
{
    const int bh = blockIdx.x;
    const int b = bh >> 3, h = bh & 7;
    const int tid = threadIdx.x;
    const int tx = tid & 15, ty = tid >> 4;

    __shared__ __align__(16) float Ks[32][64];
    __shared__ __align__(16) float Vs[32][64];
    __shared__ float cm[64], ci[64];

    if (tid < 64) {
        cm[tid] = colmax[b * DIM + h * HE + tid];
        ci[tid] = 1.0f / colsum[b * DIM + h * HE + tid];
    }
    __syncthreads();

    float acc[4][4] = {};
    const float* base = kv + (size_t)b * SEQM * (2 * DIM) + h * HE;
    for (int n0 = 0; n0 < SEQM; n0 += 32) {
        #pragma unroll
        for (int it = 0; it < 2; it++) {
            int f4 = tid + it * 256;
            int r = f4 >> 4;
            int c = (f4 & 15) * 4;
            const float* rp = base + (size_t)(n0 + r) * (2 * DIM);
            float4 kk = *(const float4*)(rp + c);
            float4 vv = *(const float4*)(rp + DIM + c);
            Ks[r][c + 0] = expf(kk.x - cm[c + 0]) * ci[c + 0];
            Ks[r][c + 1] = expf(kk.y - cm[c + 1]) * ci[c + 1];
            Ks[r][c + 2] = expf(kk.z - cm[c + 2]) * ci[c + 2];
            Ks[r][c + 3] = expf(kk.w - cm[c + 3]) * ci[c + 3];
            *(float4*)&Vs[r][c] = vv;
        }
        __syncthreads();
        #pragma unroll
        for (int r = 0; r < 32; r++) {
            float4 av = *(const float4*)&Ks[r][ty * 4];
            float4 bv = *(const float4*)&Vs[r][tx * 4];
            float a[4] = {av.x, av.y, av.z, av.w};
            float bb[4] = {bv.x, bv.y, bv.z, bv.w};
            #pragma unroll
            for (int i = 0; i < 4; i++)
                #pragma unroll
                for (int j = 0; j < 4; j++)
                    acc[i][j] += a[i] * bb[j];
        }
        __syncthreads();
    }
    float* cb = ctx + (size_t)bh * (HE * HE);
    #pragma unroll
    for (int i = 0; i < 4; i++)
        #pragma unroll
        for (int j = 0; j < 4; j++)
            cb[(ty * 4 + i) * HE + tx * 4 + j] = acc[i][j];
}

// ---------------- cross-attn output + residual + LN2 (fused, 1 row/block) --
__global__ void cross_out_ln2_kernel(const float* __restrict__ q2, const float* __restrict__ ctx,
                                     const float* __restrict__ res, const float* __restrict__ g,
                                     const float* __restrict__ beta, float* __restrict__ out)
{
    const int row = blockIdx.x;
    const int b = row >> 11;
    const int tid = threadIdx.x;
    const int w = tid >> 5, lane = tid & 31;

    __shared__ float qs_s[DIM];
    __shared__ float red[16];

    const float* qr = q2 + (size_t)row * DIM;
    {
        float a0 = qr[w * HE + lane], a1 = qr[w * HE + 32 + lane];
        float m = fmaxf(a0, a1);
        #pragma unroll
        for (int o = 16; o > 0; o >>= 1) m = fmaxf(m, __shfl_xor_sync(0xffffffffu, m, o));
        float t0 = expf(a0 - m), t1 = expf(a1 - m);
        float s = t0 + t1;
        #pragma unroll
        for (int o = 16; o > 0; o >>= 1) s += __shfl_xor_sync(0xffffffffu, s, o);
        float sc = 0.125f / s;
        qs_s[w * HE + lane] = t0 * sc;
        qs_s[w * HE + 32 + lane] = t1 * sc;
    }
    __syncthreads();

    float pre[2], sum = 0.f, sumsq = 0.f;
    #pragma unroll
    for (int it = 0; it < 2; it++) {
        int o = tid + it * 256;
        int h = o >> 6, e = o & 63;
        const float* cb = ctx + ((size_t)(b * NH + h)) * (HE * HE) + e;
        const float* qh = qs_s + h * HE;
        float acc = 0.f;
        #pragma unroll 8
        for (int d = 0; d < HE; d++) acc += qh[d] * cb[d * HE];
        float p = acc + res[(size_t)row * DIM + o];
        pre[it] = p; sum += p; sumsq += p * p;
    }
    #pragma unroll
    for (int o = 16; o > 0; o >>= 1) {
        sum   += __shfl_xor_sync(0xffffffffu, sum, o);
        sumsq += __shfl_xor_sync(0xffffffffu, sumsq, o);
    }
    if (lane == 0) { red[w] = sum; red[8 + w] = sumsq; }
    __syncthreads();
    if (tid == 0) {
        float s = 0.f, q = 0.f;
        #pragma unroll
        for (int i = 0; i < 8; i++) { s += red[i]; q += red[8 + i]; }
        float mu = s / (float)DIM;
        float var = q / (float)DIM - mu * mu;
        red[0] = mu; red[1] = rsqrtf(var + LN_EPS);
    }
    __syncthreads();
    float mu = red[0], rstd = red[1];
    #pragma unroll
    for (int it = 0; it < 2; it++) {
        int o = tid + it * 256;
        out[(size_t)row * DIM + o] = (pre[it] - mu) * rstd * g[o] + beta[o];
    }
}

// ---------------- host launch ------------------------------------------------
extern "C" void kernel_launch(void* const* d_in, const int* in_sizes, int n_in,
                              void* d_out, int out_size)
{
    const float* x      = (const float*)d_in[0];
    const float* memory = (const float*)d_in[1];
    const float* W_qvk  = (const float*)d_in[2];
    const float* b_qvk  = (const float*)d_in[3];
    const float* W_kv   = (const float*)d_in[4];
    const float* b_kv   = (const float*)d_in[5];
    const float* W_q    = (const float*)d_in[6];
    const float* b_q    = (const float*)d_in[7];
    const float* W_ff1  = (const float*)d_in[8];
    const float* b_ff1  = (const float*)d_in[9];
    const float* W_ff2  = (const float*)d_in[10];
    const float* b_ff2  = (const float*)d_in[11];
    const float* ln1_g  = (const float*)d_in[12];
    const float* ln1_b  = (const float*)d_in[13];
    const float* ln2_g  = (const float*)d_in[14];
    const float* ln2_b  = (const float*)d_in[15];
    const float* ln3_g  = (const float*)d_in[16];
    const float* ln3_b  = (const float*)d_in[17];
    float* outp = (float*)d_out;

    float *qvk, *attn1, *ln1, *kv, *q2, *colmax, *colsum, *ctx, *ln2, *ff1, *pre3;
    float *csumK, *csumKV, *kcp, *Sp;
    cudaGetSymbolAddress((void**)&qvk,   g_qvk);
    cudaGetSymbolAddress((void**)&attn1, g_attn1);
    cudaGetSymbolAddress((void**)&ln1,   g_ln1);
    cudaGetSymbolAddress((void**)&kv,    g_kv);
    cudaGetSymbolAddress((void**)&q2,    g_q2);
    cudaGetSymbolAddress((void**)&colmax,g_colmax);
    cudaGetSymbolAddress((void**)&colsum,g_colsum);
    cudaGetSymbolAddress((void**)&ctx,   g_ctx);
    cudaGetSymbolAddress((void**)&ln2,   g_ln2);
    cudaGetSymbolAddress((void**)&ff1,   g_ff1);
    cudaGetSymbolAddress((void**)&pre3,  g_pre3);
    cudaGetSymbolAddress((void**)&csumK, g_csumK);
    cudaGetSymbolAddress((void**)&csumKV,g_csumKV);
    cudaGetSymbolAddress((void**)&kcp,   g_kcp);
    cudaGetSymbolAddress((void**)&Sp,    g_Sp);

    // opt-in >48KB dynamic smem for the chunk-output kernel
    const int CSMEM = (5 * 64 * 68 + 128) * (int)sizeof(float);
    cudaFuncSetAttribute(causal_chunk_kernel, cudaFuncAttributeMaxDynamicSharedMemorySize, CSMEM);

    // 1) qvk = x @ W_qvk + b
    gemm_kernel<<<dim3((3 * DIM) / BN, ROWS / BM), 256>>>(x, W_qvk, b_qvk, qvk, ROWS, 3 * DIM, DIM, 0);
    // 2) causal linear self-attention, chunk-parallel
    chunk_sum_kernel<<<BH * NC, 256>>>(qvk, csumK, csumKV);
    prefix_kernel<<<BH, 256>>>(csumK, csumKV, kcp, Sp);
    causal_chunk_kernel<<<BH * NC, 256, CSMEM>>>(qvk, kcp, Sp, attn1);
    // 3) LN1(attn + x)
    ln_res_kernel<<<ROWS, 256>>>(attn1, x, ln1_g, ln1_b, ln1);
    // 4) kv = memory @ W_kv + b
    gemm_kernel<<<dim3((2 * DIM) / BN, ROWS / BM), 256>>>(memory, W_kv, b_kv, kv, ROWS, 2 * DIM, DIM, 0);
    // 5) q2 = ln1 @ W_q + b
    gemm_kernel<<<dim3(DIM / BN, ROWS / BM), 256>>>(ln1, W_q, b_q, q2, ROWS, DIM, DIM, 0);
    // 6) column softmax stats of k over memory rows
    col_stats_kernel<<<dim3(DIM / 32, BATCH), 256>>>(kv, colmax, colsum);
    // 7) ctx = softk^T @ v per head
    cross_ctx_kernel<<<BATCH * NH, 256>>>(kv, colmax, colsum, ctx);
    // 8) out2 = softmax(q2) @ ctx, + res, LN2 (fused)
    cross_out_ln2_kernel<<<ROWS, 256>>>(q2, ctx, ln1, ln2_g, ln2_b, ln2);
    // 9) ff1 = relu(ln2 @ W_ff1 + b)
    gemm_kernel<<<dim3(FF / BN, ROWS / BM), 256>>>(ln2, W_ff1, b_ff1, ff1, ROWS, FF, DIM, 1);
    // 10) pre3 = ff1 @ W_ff2 + b
    gemm_kernel<<<dim3(DIM / BN, ROWS / BM), 256>>>(ff1, W_ff2, b_ff2, pre3, ROWS, DIM, FF, 0);
    // 11) LN3(pre3 + ln2) -> output
    ln_res_kernel<<<ROWS, 256>>>(pre3, ln2, ln3_g, ln3_b, outp);
}

// round 5
// speedup vs baseline: 2.8360x; 1.1798x over previous
#include <cuda_runtime.h>
#include <cuda_bf16.h>
#include <math.h>

// Problem dims
#define BATCH 2
#define SEQN 2048
#define SEQM 2048
#define DIM 512
#define NH 8
#define HE 64
#define FF 2048
#define ROWS (BATCH * SEQN)   // 4096
#define LN_EPS 1e-5f
#define ATTN_EPS 1e-6f

// chunked causal linear attention
#define CC 64
#define NC (SEQN / CC)        // 32
#define BH (BATCH * NH)       // 16
// cross-attn ctx n-split
#define NCH 8
#define CHROWS (SEQM / NCH)   // 256

// ---------------- scratch (device globals; no allocations allowed) ----------
__device__ float g_qvk [ROWS * 3 * DIM];
__device__ float g_attn1[ROWS * DIM];
__device__ float g_ln1 [ROWS * DIM];
__device__ float g_kv  [ROWS * 2 * DIM];
__device__ float g_q2  [ROWS * DIM];
__device__ float g_colmax[BATCH * DIM];
__device__ float g_colsum[BATCH * DIM];
__device__ float g_ctxp[BH * NCH * HE * HE];   // partial ctx per n-chunk
__device__ float g_ctx [BH * HE * HE];
__device__ float g_ln2 [ROWS * DIM];
__device__ float g_ff1 [ROWS * FF];
__device__ float g_pre3[ROWS * DIM];
// causal-chunk state
__device__ float g_csumK [BH * NC * HE];
__device__ float g_csumKV[BH * NC * HE * HE];
__device__ float g_kcp   [BH * NC * HE];
__device__ float g_Sp    [BH * NC * HE * HE];

// ---------------- tiled fp32 GEMM, double-buffered ---------------------------
// C = A(MxK) * B(KxN) + bias, opt relu. 128x128 tile, BK=16, 256 thr, 8x8 micro.
#define BM 128
#define BN 128
#define BK 16

__global__ __launch_bounds__(256, 2)
void gemm_kernel(const float* __restrict__ A, const float* __restrict__ B,
                 const float* __restrict__ bias, float* __restrict__ C,
                 int M, int N, int K, int relu)
{
    __shared__ __align__(16) float As[2][BK][BM];
    __shared__ __align__(16) float Bs[2][BK][BN];
    const int tid = threadIdx.x;
    const int tx = tid & 15, ty = tid >> 4;
    const int row0 = blockIdx.y * BM, col0 = blockIdx.x * BN;

    // A tile: 128 rows x 16 k = 512 float4; thread covers rows {ar, 64+ar}
    const int ar = tid >> 2;
    const int ac = (tid & 3) * 4;
    // B tile: 16 k x 128 cols = 512 float4; thread covers k-rows {br, 8+br}
    const int br = tid >> 5;
    const int bc = (tid & 31) * 4;

    const float* Ab = A + (size_t)row0 * K;
    const float* Bb = B + col0;

    // preload tile 0 into buffer 0
    {
        float4 a0 = *(const float4*)(Ab + (size_t)ar * K + ac);
        float4 a1 = *(const float4*)(Ab + (size_t)(64 + ar) * K + ac);
        float4 b0 = *(const float4*)(Bb + (size_t)br * N + bc);
        float4 b1 = *(const float4*)(Bb + (size_t)(8 + br) * N + bc);
        As[0][ac + 0][ar] = a0.x; As[0][ac + 1][ar] = a0.y;
        As[0][ac + 2][ar] = a0.z; As[0][ac + 3][ar] = a0.w;
        As[0][ac + 0][64 + ar] = a1.x; As[0][ac + 1][64 + ar] = a1.y;
        As[0][ac + 2][64 + ar] = a1.z; As[0][ac + 3][64 + ar] = a1.w;
        *(float4*)&Bs[0][br][bc] = b0;
        *(float4*)&Bs[0][8 + br][bc] = b1;
    }
    __syncthreads();

    const int nit = K / BK;
    float acc[8][8] = {};
    int buf = 0;
    for (int it = 0; it < nit; it++) {
        float4 pa0, pa1, pb0, pb1;
        const bool more = (it + 1 < nit);
        if (more) {
            int k0 = (it + 1) * BK;
            pa0 = *(const float4*)(Ab + (size_t)ar * K + k0 + ac);
            pa1 = *(const float4*)(Ab + (size_t)(64 + ar) * K + k0 + ac);
            pb0 = *(const float4*)(Bb + (size_t)(k0 + br) * N + bc);
            pb1 = *(const float4*)(Bb + (size_t)(k0 + 8 + br) * N + bc);
        }
        #pragma unroll
        for (int kk = 0; kk < BK; kk++) {
            float4 a0 = *(const float4*)&As[buf][kk][ty * 4];
            float4 a1 = *(const float4*)&As[buf][kk][64 + ty * 4];
            float4 b0 = *(const float4*)&Bs[buf][kk][tx * 4];
            float4 b1 = *(const float4*)&Bs[buf][kk][64 + tx * 4];
            float av[8] = {a0.x, a0.y, a0.z, a0.w, a1.x, a1.y, a1.z, a1.w};
            float bv[8] = {b0.x, b0.y, b0.z, b0.w, b1.x, b1.y, b1.z, b1.w};
            #pragma unroll
            for (int i = 0; i < 8; i++)
                #pragma unroll
                for (int j = 0; j < 8; j++)
                    acc[i][j] += av[i] * bv[j];
        }
        if (more) {
            int nb = buf ^ 1;
            As[nb][ac + 0][ar] = pa0.x; As[nb][ac + 1][ar] = pa0.y;
            As[nb][ac + 2][ar] = pa0.z; As[nb][ac + 3][ar] = pa0.w;
            As[nb][ac + 0][64 + ar] = pa1.x; As[nb][ac + 1][64 + ar] = pa1.y;
            As[nb][ac + 2][64 + ar] = pa1.z; As[nb][ac + 3][64 + ar] = pa1.w;
            *(float4*)&Bs[nb][br][bc] = pb0;
            *(float4*)&Bs[nb][8 + br][bc] = pb1;
        }
        __syncthreads();
        buf ^= 1;
    }

    #pragma unroll
    for (int i = 0; i < 8; i++) {
        int r = row0 + ((i < 4) ? (ty * 4 + i) : (64 + ty * 4 + i - 4));
        #pragma unroll
        for (int jh = 0; jh < 2; jh++) {
            int c = col0 + jh * 64 + tx * 4;
            float4 o;
            o.x = acc[i][jh * 4 + 0] + bias[c + 0];
            o.y = acc[i][jh * 4 + 1] + bias[c + 1];
            o.z = acc[i][jh * 4 + 2] + bias[c + 2];
            o.w = acc[i][jh * 4 + 3] + bias[c + 3];
            if (relu) {
                o.x = fmaxf(o.x, 0.f); o.y = fmaxf(o.y, 0.f);
                o.z = fmaxf(o.z, 0.f); o.w = fmaxf(o.w, 0.f);
            }
            *(float4*)(C + (size_t)r * N + c) = o;
        }
    }
}

// ---------------- causal chunk phase 1: per-chunk sums ----------------------
__global__ __launch_bounds__(256)
void chunk_sum_kernel(const float* __restrict__ qvk,
                      float* __restrict__ csumK, float* __restrict__ csumKV)
{
    const int blk = blockIdx.x;
    const int bh = blk / NC, c = blk % NC;
    const int b = bh >> 3, h = bh & 7;
    const int tid = threadIdx.x;

    __shared__ __align__(16) float Ks[CC][68];
    __shared__ __align__(16) float Vs[CC][68];

    const float* base = qvk + (size_t)b * SEQN * (3 * DIM) + (size_t)c * CC * (3 * DIM) + h * HE;
    #pragma unroll
    for (int i = tid; i < CC * 16; i += 256) {
        int r = i >> 4;
        int col = (i & 15) * 4;
        const float* rp = base + (size_t)r * (3 * DIM);
        float4 kk = *(const float4*)(rp + 2 * DIM + col);
        float4 vv = *(const float4*)(rp + DIM + col);
        Ks[r][col + 0] = expf(kk.x); Ks[r][col + 1] = expf(kk.y);
        Ks[r][col + 2] = expf(kk.z); Ks[r][col + 3] = expf(kk.w);
        *(float4*)&Vs[r][col] = vv;
    }
    __syncthreads();

    const int ty = tid >> 4, tx = tid & 15;
    const int d0 = ty * 4, e0 = tx * 4;
    float acc[4][4] = {};
    #pragma unroll 8
    for (int n = 0; n < CC; n++) {
        float4 a = *(const float4*)&Ks[n][d0];
        float4 bb = *(const float4*)&Vs[n][e0];
        float av[4] = {a.x, a.y, a.z, a.w};
        float bv[4] = {bb.x, bb.y, bb.z, bb.w};
        #pragma unroll
        for (int i = 0; i < 4; i++)
            #pragma unroll
            for (int j = 0; j < 4; j++)
                acc[i][j] += av[i] * bv[j];
    }
    float* outKV = csumKV + ((size_t)bh * NC + c) * (HE * HE);
    #pragma unroll
    for (int i = 0; i < 4; i++) {
        float4 o = {acc[i][0], acc[i][1], acc[i][2], acc[i][3]};
        *(float4*)(outKV + (d0 + i) * HE + e0) = o;
    }
    if (tid < HE) {
        float s = 0.f;
        #pragma unroll 8
        for (int n = 0; n < CC; n++) s += Ks[n][tid];
        csumK[((size_t)bh * NC + c) * HE + tid] = s;
    }
}

// ---------------- causal chunk phase 2: exclusive prefix over chunks --------
__global__ __launch_bounds__(256)
void prefix_kernel(const float* __restrict__ csumK, const float* __restrict__ csumKV,
                   float* __restrict__ kcp, float* __restrict__ Sp)
{
    const int bh = blockIdx.x;
    const int tid = threadIdx.x;
    float4 run[4];
    #pragma unroll
    for (int i = 0; i < 4; i++) run[i] = make_float4(0.f, 0.f, 0.f, 0.f);
    for (int c = 0; c < NC; c++) {
        size_t base = ((size_t)bh * NC + c) * (HE * HE) + (size_t)tid * 16;
        float4* dst = (float4*)(Sp + base);
        const float4* src = (const float4*)(csumKV + base);
        #pragma unroll
        for (int i = 0; i < 4; i++) {
            dst[i] = run[i];
            float4 s = src[i];
            run[i].x += s.x; run[i].y += s.y; run[i].z += s.z; run[i].w += s.w;
        }
    }
    if (tid < HE) {
        float rk = 0.f;
        for (int c = 0; c < NC; c++) {
            size_t o = ((size_t)bh * NC + c) * HE + tid;
            kcp[o] = rk;
            rk += csumK[o];
        }
    }
}

// ---------------- causal chunk phase 3: per-chunk output --------------------
__global__ __launch_bounds__(256)
void causal_chunk_kernel(const float* __restrict__ qvk,
                         const float* __restrict__ kcp, const float* __restrict__ Sp,
                         float* __restrict__ out)
{
    extern __shared__ __align__(16) float sm[];
    float (*TsT)[68] = (float(*)[68])sm;
    float (*KsT)[68] = TsT + 64;
    float (*AT)[68]  = KsT + 64;
    float (*Vs)[68]  = AT + 64;
    float (*SpS)[68] = Vs + 64;
    float* kcpe = (float*)(SpS + 64);
    float* den  = kcpe + 64;

    const int blk = blockIdx.x;
    const int bh = blk / NC, c = blk % NC;
    const int b = bh >> 3, h = bh & 7;
    const int tid = threadIdx.x;
    const float* base = qvk + (size_t)b * SEQN * (3 * DIM) + (size_t)c * CC * (3 * DIM) + h * HE;

    {
        int r = tid >> 2;
        int g = tid & 3;
        const float* rp = base + (size_t)r * (3 * DIM) + g * 16;
        float qv[16];
        float m = -1e30f;
        #pragma unroll
        for (int j = 0; j < 16; j++) { qv[j] = rp[j]; m = fmaxf(m, qv[j]); }
        m = fmaxf(m, __shfl_xor_sync(0xffffffffu, m, 1));
        m = fmaxf(m, __shfl_xor_sync(0xffffffffu, m, 2));
        #pragma unroll
        for (int j = 0; j < 16; j++) TsT[g * 16 + j][r] = expf(qv[j] - m);
        const float* rpk = rp + 2 * DIM;
        #pragma unroll
        for (int j = 0; j < 16; j++) KsT[g * 16 + j][r] = expf(rpk[j]);
    }
    #pragma unroll
    for (int i = tid; i < CC * 16; i += 256) {
        int r = i >> 4, col = (i & 15) * 4;
        *(float4*)&Vs[r][col] = *(const float4*)(base + (size_t)r * (3 * DIM) + DIM + col);
    }
    const float* spb = Sp + ((size_t)bh * NC + c) * (HE * HE);
    #pragma unroll
    for (int i = tid; i < HE * 16; i += 256) {
        int r = i >> 4, col = (i & 15) * 4;
        *(float4*)&SpS[r][col] = *(const float4*)(spb + r * HE + col);
    }
    if (tid < HE) kcpe[tid] = kcp[((size_t)bh * NC + c) * HE + tid] + ATTN_EPS;
    __syncthreads();

    const int ty = tid >> 4, tx = tid & 15;
    const int t0 = ty * 4, s0 = tx * 4;

    {
        float acc[4][4] = {};
        #pragma unroll 8
        for (int d = 0; d < HE; d++) {
            float4 a = *(const float4*)&TsT[d][t0];
            float4 bb = *(const float4*)&KsT[d][s0];
            float av[4] = {a.x, a.y, a.z, a.w};
            float bv[4] = {bb.x, bb.y, bb.z, bb.w};
            #pragma unroll
            for (int i = 0; i < 4; i++)
                #pragma unroll
                for (int j = 0; j < 4; j++)
                    acc[i][j] += av[i] * bv[j];
        }
        #pragma unroll
        for (int i = 0; i < 4; i++)
            #pragma unroll
            for (int j = 0; j < 4; j++) {
                int t = t0 + i, s = s0 + j;
                AT[s][t] = (s <= t) ? acc[i][j] : 0.f;
            }
    }
    __syncthreads();

    if (tid < 128) {
        int t = tid >> 1, half = tid & 1;
        float sd = 0.f;
        int lo = half * 32;
        #pragma unroll 8
        for (int s = lo; s < lo + 32; s++) sd += AT[s][t];
        #pragma unroll 8
        for (int d = lo; d < lo + 32; d++) sd += TsT[d][t] * kcpe[d];
        sd += __shfl_xor_sync(0xffffffffu, sd, 1);
        if (!half) den[t] = 1.0f / sd;
    }
    __syncthreads();

    {
        const int e0 = tx * 4;
        float o[4][4] = {};
        #pragma unroll 8
        for (int s = 0; s < CC; s++) {
            float4 a = *(const float4*)&AT[s][t0];
            float4 bb = *(const float4*)&Vs[s][e0];
            float av[4] = {a.x, a.y, a.z, a.w};
            float bv[4] = {bb.x, bb.y, bb.z, bb.w};
            #pragma unroll
            for (int i = 0; i < 4; i++)
                #pragma unroll
                for (int j = 0; j < 4; j++)
                    o[i][j] += av[i] * bv[j];
        }
        #pragma unroll 8
        for (int d = 0; d < HE; d++) {
            float4 a = *(const float4*)&TsT[d][t0];
            float4 bb = *(const float4*)&SpS[d][e0];
            float av[4] = {a.x, a.y, a.z, a.w};
            float bv[4] = {bb.x, bb.y, bb.z, bb.w};
            #pragma unroll
            for (int i = 0; i < 4; i++)
                #pragma unroll
                for (int j = 0; j < 4; j++)
                    o[i][j] += av[i] * bv[j];
        }
        float* ob = out + (size_t)b * SEQN * DIM + (size_t)c * CC * DIM + h * HE;
        #pragma unroll
        for (int i = 0; i < 4; i++) {
            float rcp = den[t0 + i];
            float4 ov = {o[i][0] * rcp, o[i][1] * rcp, o[i][2] * rcp, o[i][3] * rcp};
            *(float4*)(ob + (size_t)(t0 + i) * DIM + e0) = ov;
        }
    }
}

// ---------------- residual + layernorm (512 cols, 256 threads, 1 row/block) -
__global__ void ln_res_kernel(const float* __restrict__ a, const float* __restrict__ r,
                              const float* __restrict__ g, const float* __restrict__ beta,
                              float* __restrict__ out)
{
    const int row = blockIdx.x;
    const int tid = threadIdx.x;
    const int w = tid >> 5, lane = tid & 31;
    __shared__ float red[16];

    float pre[2], sum = 0.f, sumsq = 0.f;
    #pragma unroll
    for (int it = 0; it < 2; it++) {
        int o = tid + it * 256;
        float p = a[(size_t)row * DIM + o] + r[(size_t)row * DIM + o];
        pre[it] = p; sum += p; sumsq += p * p;
    }
    #pragma unroll
    for (int o = 16; o > 0; o >>= 1) {
        sum   += __shfl_xor_sync(0xffffffffu, sum, o);
        sumsq += __shfl_xor_sync(0xffffffffu, sumsq, o);
    }
    if (lane == 0) { red[w] = sum; red[8 + w] = sumsq; }
    __syncthreads();
    if (tid == 0) {
        float s = 0.f, q = 0.f;
        #pragma unroll
        for (int i = 0; i < 8; i++) { s += red[i]; q += red[8 + i]; }
        float mu = s / (float)DIM;
        float var = q / (float)DIM - mu * mu;
        red[0] = mu; red[1] = rsqrtf(var + LN_EPS);
    }
    __syncthreads();
    float mu = red[0], rstd = red[1];
    #pragma unroll
    for (int it = 0; it < 2; it++) {
        int o = tid + it * 256;
        out[(size_t)row * DIM + o] = (pre[it] - mu) * rstd * g[o] + beta[o];
    }
}

// ---------------- cross-attn: per-column softmax stats over memory rows -----
__global__ void col_stats_kernel(const float* __restrict__ kv,
                                 float* __restrict__ colmax, float* __restrict__ colsum)
{
    const int b = blockIdx.y;
    const int lane = threadIdx.x & 31;
    const int r = threadIdx.x >> 5;
    const int d = blockIdx.x * 32 + lane;
    const float* base = kv + (size_t)b * SEQM * (2 * DIM) + d;

    __shared__ float sm[8][32];
    __shared__ float cm[32];

    float m = -1e30f;
    for (int n = r; n < SEQM; n += 8) m = fmaxf(m, base[(size_t)n * (2 * DIM)]);
    sm[r][lane] = m;
    __syncthreads();
    if (threadIdx.x < 32) {
        float mm = sm[0][threadIdx.x];
        #pragma unroll
        for (int i = 1; i < 8; i++) mm = fmaxf(mm, sm[i][threadIdx.x]);
        cm[threadIdx.x] = mm;
        colmax[b * DIM + blockIdx.x * 32 + threadIdx.x] = mm;
    }
    __syncthreads();
    float s = 0.f;
    float mref = cm[lane];
    for (int n = r; n < SEQM; n += 8) s += expf(base[(size_t)n * (2 * DIM)] - mref);
    sm[r][lane] = s;
    __syncthreads();
    if (threadIdx.x < 32) {
        float ss = sm[0][threadIdx.x];
        #pragma unroll
        for (int i = 1; i < 8; i++) ss += sm[i][threadIdx.x];
        colsum[b * DIM + blockIdx.x * 32 + threadIdx.x] = ss;
    }
}

// ---------------- cross-attn: partial ctx over n-chunks ---------------------
// grid = BH*NCH, 256 threads (16x16, 4x4 micro-tile)
__global__ void cross_ctx_kernel(const float* __restrict__ kv,
                                 const float* __restrict__ colmax, const float* __restrict__ colsum,
                                 float* __restrict__ ctxp)
{
    const int blk = blockIdx.x;
    const int bh = blk / NCH, ch = blk % NCH;
    const int b = bh >> 3, h = bh & 7;
    const int tid = threadIdx.x;
    const int tx = tid & 15, ty = tid >> 4;

    __shared__ __align__(16) float Ks[32][64];
    __shared__ __align__(16) float Vs[32][64];
    __shared__ float cm[64], ci[64];

    if (tid < 64) {
        cm[tid] = colmax[b * DIM + h * HE + tid];
        ci[tid] = 1.0f / colsum[b * DIM + h * HE + tid];
    }
    __syncthreads();

    float acc[4][4] = {};
    const float* base = kv + (size_t)b * SEQM * (2 * DIM) + h * HE;
    const int n_lo = ch * CHROWS, n_hi = n_lo + CHROWS;
    for (int n0 = n_lo; n0 < n_hi; n0 += 32) {
        #pragma unroll
        for (int it = 0; it < 2; it++) {
            int f4 = tid + it * 256;
            int r = f4 >> 4;
            int c = (f4 & 15) * 4;
            const float* rp = base + (size_t)(n0 + r) * (2 * DIM);
            float4 kk = *(const float4*)(rp + c);
            float4 vv = *(const float4*)(rp + DIM + c);
            Ks[r][c + 0] = expf(kk.x - cm[c + 0]) * ci[c + 0];
            Ks[r][c + 1] = expf(kk.y - cm[c + 1]) * ci[c + 1];
            Ks[r][c + 2] = expf(kk.z - cm[c + 2]) * ci[c + 2];
            Ks[r][c + 3] = expf(kk.w - cm[c + 3]) * ci[c + 3];
            *(float4*)&Vs[r][c] = vv;
        }
        __syncthreads();
        #pragma unroll
        for (int r = 0; r < 32; r++) {
            float4 av = *(const float4*)&Ks[r][ty * 4];
            float4 bv = *(const float4*)&Vs[r][tx * 4];
            float a[4] = {av.x, av.y, av.z, av.w};
            float bb[4] = {bv.x, bv.y, bv.z, bv.w};
            #pragma unroll
            for (int i = 0; i < 4; i++)
                #pragma unroll
                for (int j = 0; j < 4; j++)
                    acc[i][j] += a[i] * bb[j];
        }
        __syncthreads();
    }
    float* cb = ctxp + (size_t)blk * (HE * HE);
    #pragma unroll
    for (int i = 0; i < 4; i++)
        #pragma unroll
        for (int j = 0; j < 4; j++)
            cb[(ty * 4 + i) * HE + tx * 4 + j] = acc[i][j];
}

// reduce partial ctx: grid = BH, 256 threads, 16 floats each
__global__ void ctx_reduce_kernel(const float* __restrict__ ctxp, float* __restrict__ ctx)
{
    const int bh = blockIdx.x;
    const int tid = threadIdx.x;
    size_t o = (size_t)tid * 16;
    float4 s[4];
    #pragma unroll
    for (int i = 0; i < 4; i++) s[i] = make_float4(0.f, 0.f, 0.f, 0.f);
    #pragma unroll
    for (int ch = 0; ch < NCH; ch++) {
        const float4* src = (const float4*)(ctxp + ((size_t)bh * NCH + ch) * (HE * HE) + o);
        #pragma unroll
        for (int i = 0; i < 4; i++) {
            float4 v = src[i];
            s[i].x += v.x; s[i].y += v.y; s[i].z += v.z; s[i].w += v.w;
        }
    }
    float4* dst = (float4*)(ctx + (size_t)bh * (HE * HE) + o);
    #pragma unroll
    for (int i = 0; i < 4; i++) dst[i] = s[i];
}

// ---------------- cross-attn output + residual + LN2 (fused, 1 row/block) --
__global__ void cross_out_ln2_kernel(const float* __restrict__ q2, const float* __restrict__ ctx,
                                     const float* __restrict__ res, const float* __restrict__ g,
                                     const float* __restrict__ beta, float* __restrict__ out)
{
    const int row = blockIdx.x;
    const int b = row >> 11;
    const int tid = threadIdx.x;
    const int w = tid >> 5, lane = tid & 31;

    __shared__ float qs_s[DIM];
    __shared__ float red[16];

    const float* qr = q2 + (size_t)row * DIM;
    {
        float a0 = qr[w * HE + lane], a1 = qr[w * HE + 32 + lane];
        float m = fmaxf(a0, a1);
        #pragma unroll
        for (int o = 16; o > 0; o >>= 1) m = fmaxf(m, __shfl_xor_sync(0xffffffffu, m, o));
        float t0 = expf(a0 - m), t1 = expf(a1 - m);
        float s = t0 + t1;
        #pragma unroll
        for (int o = 16; o > 0; o >>= 1) s += __shfl_xor_sync(0xffffffffu, s, o);
        float sc = 0.125f / s;
        qs_s[w * HE + lane] = t0 * sc;
        qs_s[w * HE + 32 + lane] = t1 * sc;
    }
    __syncthreads();

    float pre[2], sum = 0.f, sumsq = 0.f;
    #pragma unroll
    for (int it = 0; it < 2; it++) {
        int o = tid + it * 256;
        int h = o >> 6, e = o & 63;
        const float* cb = ctx + ((size_t)(b * NH + h)) * (HE * HE) + e;
        const float* qh = qs_s + h * HE;
        float acc = 0.f;
        #pragma unroll 8
        for (int d = 0; d < HE; d++) acc += qh[d] * cb[d * HE];
        float p = acc + res[(size_t)row * DIM + o];
        pre[it] = p; sum += p; sumsq += p * p;
    }
    #pragma unroll
    for (int o = 16; o > 0; o >>= 1) {
        sum   += __shfl_xor_sync(0xffffffffu, sum, o);
        sumsq += __shfl_xor_sync(0xffffffffu, sumsq, o);
    }
    if (lane == 0) { red[w] = sum; red[8 + w] = sumsq; }
    __syncthreads();
    if (tid == 0) {
        float s = 0.f, q = 0.f;
        #pragma unroll
        for (int i = 0; i < 8; i++) { s += red[i]; q += red[8 + i]; }
        float mu = s / (float)DIM;
        float var = q / (float)DIM - mu * mu;
        red[0] = mu; red[1] = rsqrtf(var + LN_EPS);
    }
    __syncthreads();
    float mu = red[0], rstd = red[1];
    #pragma unroll
    for (int it = 0; it < 2; it++) {
        int o = tid + it * 256;
        out[(size_t)row * DIM + o] = (pre[it] - mu) * rstd * g[o] + beta[o];
    }
}

// ---------------- host launch ------------------------------------------------
extern "C" void kernel_launch(void* const* d_in, const int* in_sizes, int n_in,
                              void* d_out, int out_size)
{
    const float* x      = (const float*)d_in[0];
    const float* memory = (const float*)d_in[1];
    const float* W_qvk  = (const float*)d_in[2];
    const float* b_qvk  = (const float*)d_in[3];
    const float* W_kv   = (const float*)d_in[4];
    const float* b_kv   = (const float*)d_in[5];
    const float* W_q    = (const float*)d_in[6];
    const float* b_q    = (const float*)d_in[7];
    const float* W_ff1  = (const float*)d_in[8];
    const float* b_ff1  = (const float*)d_in[9];
    const float* W_ff2  = (const float*)d_in[10];
    const float* b_ff2  = (const float*)d_in[11];
    const float* ln1_g  = (const float*)d_in[12];
    const float* ln1_b  = (const float*)d_in[13];
    const float* ln2_g  = (const float*)d_in[14];
    const float* ln2_b  = (const float*)d_in[15];
    const float* ln3_g  = (const float*)d_in[16];
    const float* ln3_b  = (const float*)d_in[17];
    float* outp = (float*)d_out;

    float *qvk, *attn1, *ln1, *kv, *q2, *colmax, *colsum, *ctxp, *ctx, *ln2, *ff1, *pre3;
    float *csumK, *csumKV, *kcp, *Sp;
    cudaGetSymbolAddress((void**)&qvk,   g_qvk);
    cudaGetSymbolAddress((void**)&attn1, g_attn1);
    cudaGetSymbolAddress((void**)&ln1,   g_ln1);
    cudaGetSymbolAddress((void**)&kv,    g_kv);
    cudaGetSymbolAddress((void**)&q2,    g_q2);
    cudaGetSymbolAddress((void**)&colmax,g_colmax);
    cudaGetSymbolAddress((void**)&colsum,g_colsum);
    cudaGetSymbolAddress((void**)&ctxp,  g_ctxp);
    cudaGetSymbolAddress((void**)&ctx,   g_ctx);
    cudaGetSymbolAddress((void**)&ln2,   g_ln2);
    cudaGetSymbolAddress((void**)&ff1,   g_ff1);
    cudaGetSymbolAddress((void**)&pre3,  g_pre3);
    cudaGetSymbolAddress((void**)&csumK, g_csumK);
    cudaGetSymbolAddress((void**)&csumKV,g_csumKV);
    cudaGetSymbolAddress((void**)&kcp,   g_kcp);
    cudaGetSymbolAddress((void**)&Sp,    g_Sp);

    const int CSMEM = (5 * 64 * 68 + 128) * (int)sizeof(float);
    cudaFuncSetAttribute(causal_chunk_kernel, cudaFuncAttributeMaxDynamicSharedMemorySize, CSMEM);

    // 1) qvk = x @ W_qvk + b
    gemm_kernel<<<dim3((3 * DIM) / BN, ROWS / BM), 256>>>(x, W_qvk, b_qvk, qvk, ROWS, 3 * DIM, DIM, 0);
    // 2) causal linear self-attention, chunk-parallel
    chunk_sum_kernel<<<BH * NC, 256>>>(qvk, csumK, csumKV);
    prefix_kernel<<<BH, 256>>>(csumK, csumKV, kcp, Sp);
    causal_chunk_kernel<<<BH * NC, 256, CSMEM>>>(qvk, kcp, Sp, attn1);
    // 3) LN1(attn + x)
    ln_res_kernel<<<ROWS, 256>>>(attn1, x, ln1_g, ln1_b, ln1);
    // 4) kv = memory @ W_kv + b
    gemm_kernel<<<dim3((2 * DIM) / BN, ROWS / BM), 256>>>(memory, W_kv, b_kv, kv, ROWS, 2 * DIM, DIM, 0);
    // 5) q2 = ln1 @ W_q + b
    gemm_kernel<<<dim3(DIM / BN, ROWS / BM), 256>>>(ln1, W_q, b_q, q2, ROWS, DIM, DIM, 0);
    // 6) column softmax stats of k over memory rows
    col_stats_kernel<<<dim3(DIM / 32, BATCH), 256>>>(kv, colmax, colsum);
    // 7) ctx = softk^T @ v per head (n-chunked + reduce)
    cross_ctx_kernel<<<BH * NCH, 256>>>(kv, colmax, colsum, ctxp);
    ctx_reduce_kernel<<<BH, 256>>>(ctxp, ctx);
    // 8) out2 = softmax(q2) @ ctx, + res, LN2 (fused)
    cross_out_ln2_kernel<<<ROWS, 256>>>(q2, ctx, ln1, ln2_g, ln2_b, ln2);
    // 9) ff1 = relu(ln2 @ W_ff1 + b)
    gemm_kernel<<<dim3(FF / BN, ROWS / BM), 256>>>(ln2, W_ff1, b_ff1, ff1, ROWS, FF, DIM, 1);
    // 10) pre3 = ff1 @ W_ff2 + b
    gemm_kernel<<<dim3(DIM / BN, ROWS / BM), 256>>>(ff1, W_ff2, b_ff2, pre3, ROWS, DIM, FF, 0);
    // 11) LN3(pre3 + ln2) -> output
    ln_res_kernel<<<ROWS, 256>>>(pre3, ln2, ln3_g, ln3_b, outp);
}

// round 7
// speedup vs baseline: 4.9460x; 1.7440x over previous
#include <cuda_runtime.h>
#include <cuda_bf16.h>
#include <math.h>
#include <stdint.h>

// Problem dims
#define BATCH 2
#define SEQN 2048
#define SEQM 2048
#define DIM 512
#define NH 8
#define HE 64
#define FF 2048
#define ROWS (BATCH * SEQN)   // 4096
#define LN_EPS 1e-5f
#define ATTN_EPS 1e-6f

// chunked causal linear attention
#define CC 64
#define NC (SEQN / CC)        // 32
#define BH (BATCH * NH)       // 16
// cross-attn ctx n-split
#define NCH 8
#define CHROWS (SEQM / NCH)   // 256

// ---------------- scratch (device globals; no allocations allowed) ----------
__device__ float g_qvk [ROWS * 3 * DIM];
__device__ float g_attn1[ROWS * DIM];
__device__ float g_ln1 [ROWS * DIM];
__device__ float g_kv  [ROWS * 2 * DIM];
__device__ float g_q2  [ROWS * DIM];
__device__ float g_colmax[BATCH * DIM];
__device__ float g_colsum[BATCH * DIM];
__device__ float g_ctxp[BH * NCH * HE * HE];
__device__ float g_ctx [BH * HE * HE];
__device__ float g_ln2 [ROWS * DIM];
__device__ float g_ff1 [ROWS * FF];
__device__ float g_pre3[ROWS * DIM];
// causal-chunk state
__device__ float g_csumK [BH * NC * HE];
__device__ float g_csumKV[BH * NC * HE * HE];
__device__ float g_kcp   [BH * NC * HE];
__device__ float g_Sp    [BH * NC * HE * HE];

// ---------------- mma.sync helpers ------------------------------------------
__device__ __forceinline__ uint32_t smem_u32(const void* p) {
    uint32_t a;
    asm("{ .reg .u64 t; cvta.to.shared.u64 t, %1; cvt.u32.u64 %0, t; }" : "=r"(a) : "l"(p));
    return a;
}
__device__ __forceinline__ void ldmat_x4(uint32_t& r0, uint32_t& r1, uint32_t& r2, uint32_t& r3,
                                         uint32_t addr) {
    asm volatile("ldmatrix.sync.aligned.m8n8.x4.shared.b16 {%0,%1,%2,%3}, [%4];"
                 : "=r"(r0), "=r"(r1), "=r"(r2), "=r"(r3) : "r"(addr));
}
__device__ __forceinline__ void ldmat_x4t(uint32_t& r0, uint32_t& r1, uint32_t& r2, uint32_t& r3,
                                          uint32_t addr) {
    asm volatile("ldmatrix.sync.aligned.m8n8.x4.trans.shared.b16 {%0,%1,%2,%3}, [%4];"
                 : "=r"(r0), "=r"(r1), "=r"(r2), "=r"(r3) : "r"(addr));
}
__device__ __forceinline__ void mma_bf16(float* c, const uint32_t* a, const uint32_t* b) {
    asm volatile(
        "mma.sync.aligned.m16n8k16.row.col.f32.bf16.bf16.f32 "
        "{%0,%1,%2,%3}, {%4,%5,%6,%7}, {%8,%9}, {%0,%1,%2,%3};"
        : "+f"(c[0]), "+f"(c[1]), "+f"(c[2]), "+f"(c[3])
        : "r"(a[0]), "r"(a[1]), "r"(a[2]), "r"(a[3]), "r"(b[0]), "r"(b[1]));
}

// ================= split-bf16 tensor-core GEMM (mma.sync) ====================
// C(MxN) = A(MxK) @ B(KxN) + bias, opt relu.
// 128x128 CTA tile, BK=32, 8 warps (2x4), warp tile 64x32.
// Split: A=Ah+Al, B=Bh+Bl (bf16); acc += AhBh + AlBh + AhBl (fp32).
#define SA_STR 40    // bf16 units per A row (32 + 8 pad -> 80B, conflict-free ldmatrix)
#define SB_STR 136   // bf16 units per B row (128 + 8 pad -> 272B)

__global__ __launch_bounds__(256, 2)
void gemm_mma(const float* __restrict__ A, const float* __restrict__ B,
              const float* __restrict__ bias, float* __restrict__ C,
              int M, int N, int K, int relu)
{
    __shared__ __align__(16) __nv_bfloat16 sAh[128][SA_STR];
    __shared__ __align__(16) __nv_bfloat16 sAl[128][SA_STR];
    __shared__ __align__(16) __nv_bfloat16 sBh[32][SB_STR];
    __shared__ __align__(16) __nv_bfloat16 sBl[32][SB_STR];

    const int tid = threadIdx.x;
    const int lane = tid & 31, wid = tid >> 5;
    const int wm = (wid >> 2) * 64;      // warp M offset (0 or 64)
    const int wn = (wid & 3) * 32;       // warp N offset (0,32,64,96)
    const int row0 = blockIdx.y * 128, col0 = blockIdx.x * 128;

    float acc[4][4][4] = {};             // [mtile][ntile][frag]

    const uint32_t ah_base = smem_u32(&sAh[0][0]);
    const uint32_t al_base = smem_u32(&sAl[0][0]);
    const uint32_t bh_base = smem_u32(&sBh[0][0]);
    const uint32_t bl_base = smem_u32(&sBl[0][0]);
    // ldmatrix lane addressing
    const int a_row  = wm + (lane & 15);          // + mt*16
    const int a_colb = (lane >> 4) * 8;           // + ks*16
    const int b_row  = (lane & 7) + ((lane >> 3) & 1) * 8;  // + ks*16
    const int b_colb = wn + (lane >> 4) * 8;      // + p*16

    for (int k0 = 0; k0 < K; k0 += 32) {
        // ---- A tile: 128 rows x 32 k, fp32 -> hi/lo bf16 ----
        #pragma unroll
        for (int i = 0; i < 4; i++) {
            int cidx = tid + i * 256;             // 1024 float4 chunks
            int r = cidx >> 3, ch = cidx & 7;
            float4 f = *(const float4*)(A + (size_t)(row0 + r) * K + k0 + ch * 4);
            __nv_bfloat16 h0 = __float2bfloat16_rn(f.x), h1 = __float2bfloat16_rn(f.y);
            __nv_bfloat16 h2 = __float2bfloat16_rn(f.z), h3 = __float2bfloat16_rn(f.w);
            __nv_bfloat16 l0 = __float2bfloat16_rn(f.x - __bfloat162float(h0));
            __nv_bfloat16 l1 = __float2bfloat16_rn(f.y - __bfloat162float(h1));
            __nv_bfloat16 l2 = __float2bfloat16_rn(f.z - __bfloat162float(h2));
            __nv_bfloat16 l3 = __float2bfloat16_rn(f.w - __bfloat162float(h3));
            __nv_bfloat162 hA = {h0, h1}, hB = {h2, h3}, lA = {l0, l1}, lB = {l2, l3};
            *(uint2*)&sAh[r][ch * 4] = make_uint2(*(uint32_t*)&hA, *(uint32_t*)&hB);
            *(uint2*)&sAl[r][ch * 4] = make_uint2(*(uint32_t*)&lA, *(uint32_t*)&lB);
        }
        // ---- B tile: 32 k-rows x 128 n, fp32 -> hi/lo bf16 (k-major, no transpose) ----
        #pragma unroll
        for (int i = 0; i < 4; i++) {
            int cidx = tid + i * 256;
            int kr = cidx >> 5, n4 = (cidx & 31) * 4;
            float4 f = *(const float4*)(B + (size_t)(k0 + kr) * N + col0 + n4);
            __nv_bfloat16 h0 = __float2bfloat16_rn(f.x), h1 = __float2bfloat16_rn(f.y);
            __nv_bfloat16 h2 = __float2bfloat16_rn(f.z), h3 = __float2bfloat16_rn(f.w);
            __nv_bfloat16 l0 = __float2bfloat16_rn(f.x - __bfloat162float(h0));
            __nv_bfloat16 l1 = __float2bfloat16_rn(f.y - __bfloat162float(h1));
            __nv_bfloat16 l2 = __float2bfloat16_rn(f.z - __bfloat162float(h2));
            __nv_bfloat16 l3 = __float2bfloat16_rn(f.w - __bfloat162float(h3));
            __nv_bfloat162 hA = {h0, h1}, hB = {h2, h3}, lA = {l0, l1}, lB = {l2, l3};
            *(uint2*)&sBh[kr][n4] = make_uint2(*(uint32_t*)&hA, *(uint32_t*)&hB);
            *(uint2*)&sBl[kr][n4] = make_uint2(*(uint32_t*)&lA, *(uint32_t*)&lB);
        }
        __syncthreads();

        #pragma unroll
        for (int ks = 0; ks < 2; ks++) {
            uint32_t ah[4][4], al[4][4], bf[4][2];
            #pragma unroll
            for (int mt = 0; mt < 4; mt++) {
                uint32_t off = (uint32_t)((a_row + mt * 16) * SA_STR + ks * 16 + a_colb) * 2;
                ldmat_x4(ah[mt][0], ah[mt][1], ah[mt][2], ah[mt][3], ah_base + off);
                ldmat_x4(al[mt][0], al[mt][1], al[mt][2], al[mt][3], al_base + off);
            }
            #pragma unroll
            for (int p = 0; p < 2; p++) {
                uint32_t off = (uint32_t)((ks * 16 + b_row) * SB_STR + b_colb + p * 16) * 2;
                ldmat_x4t(bf[p * 2][0], bf[p * 2][1], bf[p * 2 + 1][0], bf[p * 2 + 1][1],
                          bh_base + off);
            }
            #pragma unroll
            for (int mt = 0; mt < 4; mt++)
                #pragma unroll
                for (int nt = 0; nt < 4; nt++) {
                    mma_bf16(acc[mt][nt], ah[mt], bf[nt]);   // Ah*Bh
                    mma_bf16(acc[mt][nt], al[mt], bf[nt]);   // Al*Bh
                }
            #pragma unroll
            for (int p = 0; p < 2; p++) {
                uint32_t off = (uint32_t)((ks * 16 + b_row) * SB_STR + b_colb + p * 16) * 2;
                ldmat_x4t(bf[p * 2][0], bf[p * 2][1], bf[p * 2 + 1][0], bf[p * 2 + 1][1],
                          bl_base + off);
            }
            #pragma unroll
            for (int mt = 0; mt < 4; mt++)
                #pragma unroll
                for (int nt = 0; nt < 4; nt++)
                    mma_bf16(acc[mt][nt], ah[mt], bf[nt]);   // Ah*Bl
        }
        __syncthreads();
    }

    // ---- epilogue: fragments -> gmem with bias/relu ----
    const int r_l = lane >> 2, c_l = (lane & 3) * 2;
    #pragma unroll
    for (int mt = 0; mt < 4; mt++) {
        int row = row0 + wm + mt * 16 + r_l;
        #pragma unroll
        for (int nt = 0; nt < 4; nt++) {
            int col = col0 + wn + nt * 8 + c_l;
            float b0 = bias[col], b1 = bias[col + 1];
            float2 o0 = {acc[mt][nt][0] + b0, acc[mt][nt][1] + b1};
            float2 o1 = {acc[mt][nt][2] + b0, acc[mt][nt][3] + b1};
            if (relu) {
                o0.x = fmaxf(o0.x, 0.f); o0.y = fmaxf(o0.y, 0.f);
                o1.x = fmaxf(o1.x, 0.f); o1.y = fmaxf(o1.y, 0.f);
            }
            *(float2*)(C + (size_t)row * N + col) = o0;
            *(float2*)(C + (size_t)(row + 8) * N + col) = o1;
        }
    }
}

// ---------------- causal chunk phase 1: per-chunk sums ----------------------
__global__ __launch_bounds__(256)
void chunk_sum_kernel(const float* __restrict__ qvk,
                      float* __restrict__ csumK, float* __restrict__ csumKV)
{
    const int blk = blockIdx.x;
    const int bh = blk / NC, c = blk % NC;
    const int b = bh >> 3, h = bh & 7;
    const int tid = threadIdx.x;

    __shared__ __align__(16) float Ks[CC][68];
    __shared__ __align__(16) float Vs[CC][68];

    const float* base = qvk + (size_t)b * SEQN * (3 * DIM) + (size_t)c * CC * (3 * DIM) + h * HE;
    #pragma unroll
    for (int i = tid; i < CC * 16; i += 256) {
        int r = i >> 4;
        int col = (i & 15) * 4;
        const float* rp = base + (size_t)r * (3 * DIM);
        float4 kk = *(const float4*)(rp + 2 * DIM + col);
        float4 vv = *(const float4*)(rp + DIM + col);
        Ks[r][col + 0] = expf(kk.x); Ks[r][col + 1] = expf(kk.y);
        Ks[r][col + 2] = expf(kk.z); Ks[r][col + 3] = expf(kk.w);
        *(float4*)&Vs[r][col] = vv;
    }
    __syncthreads();

    const int ty = tid >> 4, tx = tid & 15;
    const int d0 = ty * 4, e0 = tx * 4;
    float acc[4][4] = {};
    #pragma unroll 8
    for (int n = 0; n < CC; n++) {
        float4 a = *(const float4*)&Ks[n][d0];
        float4 bb = *(const float4*)&Vs[n][e0];
        float av[4] = {a.x, a.y, a.z, a.w};
        float bv[4] = {bb.x, bb.y, bb.z, bb.w};
        #pragma unroll
        for (int i = 0; i < 4; i++)
            #pragma unroll
            for (int j = 0; j < 4; j++)
                acc[i][j] += av[i] * bv[j];
    }
    float* outKV = csumKV + ((size_t)bh * NC + c) * (HE * HE);
    #pragma unroll
    for (int i = 0; i < 4; i++) {
        float4 o = {acc[i][0], acc[i][1], acc[i][2], acc[i][3]};
        *(float4*)(outKV + (d0 + i) * HE + e0) = o;
    }
    if (tid < HE) {
        float s = 0.f;
        #pragma unroll 8
        for (int n = 0; n < CC; n++) s += Ks[n][tid];
        csumK[((size_t)bh * NC + c) * HE + tid] = s;
    }
}

// ---------------- causal chunk phase 2: exclusive prefix over chunks --------
__global__ __launch_bounds__(256)
void prefix_kernel(const float* __restrict__ csumK, const float* __restrict__ csumKV,
                   float* __restrict__ kcp, float* __restrict__ Sp)
{
    const int bh = blockIdx.x;
    const int tid = threadIdx.x;
    float4 run[4];
    #pragma unroll
    for (int i = 0; i < 4; i++) run[i] = make_float4(0.f, 0.f, 0.f, 0.f);
    for (int c = 0; c < NC; c++) {
        size_t base = ((size_t)bh * NC + c) * (HE * HE) + (size_t)tid * 16;
        float4* dst = (float4*)(Sp + base);
        const float4* src = (const float4*)(csumKV + base);
        #pragma unroll
        for (int i = 0; i < 4; i++) {
            dst[i] = run[i];
            float4 s = src[i];
            run[i].x += s.x; run[i].y += s.y; run[i].z += s.z; run[i].w += s.w;
        }
    }
    if (tid < HE) {
        float rk = 0.f;
        for (int c = 0; c < NC; c++) {
            size_t o = ((size_t)bh * NC + c) * HE + tid;
            kcp[o] = rk;
            rk += csumK[o];
        }
    }
}

// ---------------- causal chunk phase 3: per-chunk output --------------------
__global__ __launch_bounds__(256)
void causal_chunk_kernel(const float* __restrict__ qvk,
                         const float* __restrict__ kcp, const float* __restrict__ Sp,
                         float* __restrict__ out)
{
    extern __shared__ __align__(16) float sm[];
    float (*TsT)[68] = (float(*)[68])sm;
    float (*KsT)[68] = TsT + 64;
    float (*AT)[68]  = KsT + 64;
    float (*Vs)[68]  = AT + 64;
    float (*SpS)[68] = Vs + 64;
    float* kcpe = (float*)(SpS + 64);
    float* den  = kcpe + 64;

    const int blk = blockIdx.x;
    const int bh = blk / NC, c = blk % NC;
    const int b = bh >> 3, h = bh & 7;
    const int tid = threadIdx.x;
    const float* base = qvk + (size_t)b * SEQN * (3 * DIM) + (size_t)c * CC * (3 * DIM) + h * HE;

    {
        int r = tid >> 2;
        int g = tid & 3;
        const float* rp = base + (size_t)r * (3 * DIM) + g * 16;
        float qv[16];
        float m = -1e30f;
        #pragma unroll
        for (int j = 0; j < 16; j++) { qv[j] = rp[j]; m = fmaxf(m, qv[j]); }
        m = fmaxf(m, __shfl_xor_sync(0xffffffffu, m, 1));
        m = fmaxf(m, __shfl_xor_sync(0xffffffffu, m, 2));
        #pragma unroll
        for (int j = 0; j < 16; j++) TsT[g * 16 + j][r] = expf(qv[j] - m);
        const float* rpk = rp + 2 * DIM;
        #pragma unroll
        for (int j = 0; j < 16; j++) KsT[g * 16 + j][r] = expf(rpk[j]);
    }
    #pragma unroll
    for (int i = tid; i < CC * 16; i += 256) {
        int r = i >> 4, col = (i & 15) * 4;
        *(float4*)&Vs[r][col] = *(const float4*)(base + (size_t)r * (3 * DIM) + DIM + col);
    }
    const float* spb = Sp + ((size_t)bh * NC + c) * (HE * HE);
    #pragma unroll
    for (int i = tid; i < HE * 16; i += 256) {
        int r = i >> 4, col = (i & 15) * 4;
        *(float4*)&SpS[r][col] = *(const float4*)(spb + r * HE + col);
    }
    if (tid < HE) kcpe[tid] = kcp[((size_t)bh * NC + c) * HE + tid] + ATTN_EPS;
    __syncthreads();

    const int ty = tid >> 4, tx = tid & 15;
    const int t0 = ty * 4, s0 = tx * 4;

    {
        float acc[4][4] = {};
        #pragma unroll 8
        for (int d = 0; d < HE; d++) {
            float4 a = *(const float4*)&TsT[d][t0];
            float4 bb = *(const float4*)&KsT[d][s0];
            float av[4] = {a.x, a.y, a.z, a.w};
            float bv[4] = {bb.x, bb.y, bb.z, bb.w};
            #pragma unroll
            for (int i = 0; i < 4; i++)
                #pragma unroll
                for (int j = 0; j < 4; j++)
                    acc[i][j] += av[i] * bv[j];
        }
        #pragma unroll
        for (int i = 0; i < 4; i++)
            #pragma unroll
            for (int j = 0; j < 4; j++) {
                int t = t0 + i, s = s0 + j;
                AT[s][t] = (s <= t) ? acc[i][j] : 0.f;
            }
    }
    __syncthreads();

    if (tid < 128) {
        int t = tid >> 1, half = tid & 1;
        float sd = 0.f;
        int lo = half * 32;
        #pragma unroll 8
        for (int s = lo; s < lo + 32; s++) sd += AT[s][t];
        #pragma unroll 8
        for (int d = lo; d < lo + 32; d++) sd += TsT[d][t] * kcpe[d];
        sd += __shfl_xor_sync(0xffffffffu, sd, 1);
        if (!half) den[t] = 1.0f / sd;
    }
    __syncthreads();

    {
        const int e0 = tx * 4;
        float o[4][4] = {};
        #pragma unroll 8
        for (int s = 0; s < CC; s++) {
            float4 a = *(const float4*)&AT[s][t0];
            float4 bb = *(const float4*)&Vs[s][e0];
            float av[4] = {a.x, a.y, a.z, a.w};
            float bv[4] = {bb.x, bb.y, bb.z, bb.w};
            #pragma unroll
            for (int i = 0; i < 4; i++)
                #pragma unroll
                for (int j = 0; j < 4; j++)
                    o[i][j] += av[i] * bv[j];
        }
        #pragma unroll 8
        for (int d = 0; d < HE; d++) {
            float4 a = *(const float4*)&TsT[d][t0];
            float4 bb = *(const float4*)&SpS[d][e0];
            float av[4] = {a.x, a.y, a.z, a.w};
            float bv[4] = {bb.x, bb.y, bb.z, bb.w};
            #pragma unroll
            for (int i = 0; i < 4; i++)
                #pragma unroll
                for (int j = 0; j < 4; j++)
                    o[i][j] += av[i] * bv[j];
        }
        float* ob = out + (size_t)b * SEQN * DIM + (size_t)c * CC * DIM + h * HE;
        #pragma unroll
        for (int i = 0; i < 4; i++) {
            float rcp = den[t0 + i];
            float4 ov = {o[i][0] * rcp, o[i][1] * rcp, o[i][2] * rcp, o[i][3] * rcp};
            *(float4*)(ob + (size_t)(t0 + i) * DIM + e0) = ov;
        }
    }
}

// ---------------- residual + layernorm ---------------------------------------
__global__ void ln_res_kernel(const float* __restrict__ a, const float* __restrict__ r,
                              const float* __restrict__ g, const float* __restrict__ beta,
                              float* __restrict__ out)
{
    const int row = blockIdx.x;
    const int tid = threadIdx.x;
    const int w = tid >> 5, lane = tid & 31;
    __shared__ float red[16];

    float pre[2], sum = 0.f, sumsq = 0.f;
    #pragma unroll
    for (int it = 0; it < 2; it++) {
        int o = tid + it * 256;
        float p = a[(size_t)row * DIM + o] + r[(size_t)row * DIM + o];
        pre[it] = p; sum += p; sumsq += p * p;
    }
    #pragma unroll
    for (int o = 16; o > 0; o >>= 1) {
        sum   += __shfl_xor_sync(0xffffffffu, sum, o);
        sumsq += __shfl_xor_sync(0xffffffffu, sumsq, o);
    }
    if (lane == 0) { red[w] = sum; red[8 + w] = sumsq; }
    __syncthreads();
    if (tid == 0) {
        float s = 0.f, q = 0.f;
        #pragma unroll
        for (int i = 0; i < 8; i++) { s += red[i]; q += red[8 + i]; }
        float mu = s / (float)DIM;
        float var = q / (float)DIM - mu * mu;
        red[0] = mu; red[1] = rsqrtf(var + LN_EPS);
    }
    __syncthreads();
    float mu = red[0], rstd = red[1];
    #pragma unroll
    for (int it = 0; it < 2; it++) {
        int o = tid + it * 256;
        out[(size_t)row * DIM + o] = (pre[it] - mu) * rstd * g[o] + beta[o];
    }
}

// ---------------- cross-attn: per-column softmax stats -----------------------
__global__ void col_stats_kernel(const float* __restrict__ kv,
                                 float* __restrict__ colmax, float* __restrict__ colsum)
{
    const int b = blockIdx.y;
    const int lane = threadIdx.x & 31;
    const int r = threadIdx.x >> 5;
    const int d = blockIdx.x * 32 + lane;
    const float* base = kv + (size_t)b * SEQM * (2 * DIM) + d;

    __shared__ float sm[8][32];
    __shared__ float cm[32];

    float m = -1e30f;
    for (int n = r; n < SEQM; n += 8) m = fmaxf(m, base[(size_t)n * (2 * DIM)]);
    sm[r][lane] = m;
    __syncthreads();
    if (threadIdx.x < 32) {
        float mm = sm[0][threadIdx.x];
        #pragma unroll
        for (int i = 1; i < 8; i++) mm = fmaxf(mm, sm[i][threadIdx.x]);
        cm[threadIdx.x] = mm;
        colmax[b * DIM + blockIdx.x * 32 + threadIdx.x] = mm;
    }
    __syncthreads();
    float s = 0.f;
    float mref = cm[lane];
    for (int n = r; n < SEQM; n += 8) s += expf(base[(size_t)n * (2 * DIM)] - mref);
    sm[r][lane] = s;
    __syncthreads();
    if (threadIdx.x < 32) {
        float ss = sm[0][threadIdx.x];
        #pragma unroll
        for (int i = 1; i < 8; i++) ss += sm[i][threadIdx.x];
        colsum[b * DIM + blockIdx.x * 32 + threadIdx.x] = ss;
    }
}

// ---------------- cross-attn: partial ctx over n-chunks ----------------------
__global__ void cross_ctx_kernel(const float* __restrict__ kv,
                                 const float* __restrict__ colmax, const float* __restrict__ colsum,
                                 float* __restrict__ ctxp)
{
    const int blk = blockIdx.x;
    const int bh = blk / NCH, ch = blk % NCH;
    const int b = bh >> 3, h = bh & 7;
    const int tid = threadIdx.x;
    const int tx = tid & 15, ty = tid >> 4;

    __shared__ __align__(16) float Ks[32][64];
    __shared__ __align__(16) float Vs[32][64];
    __shared__ float cm[64], ci[64];

    if (tid < 64) {
        cm[tid] = colmax[b * DIM + h * HE + tid];
        ci[tid] = 1.0f / colsum[b * DIM + h * HE + tid];
    }
    __syncthreads();

    float acc[4][4] = {};
    const float* base = kv + (size_t)b * SEQM * (2 * DIM) + h * HE;
    const int n_lo = ch * CHROWS, n_hi = n_lo + CHROWS;
    for (int n0 = n_lo; n0 < n_hi; n0 += 32) {
        #pragma unroll
        for (int it = 0; it < 2; it++) {
            int f4 = tid + it * 256;
            int r = f4 >> 4;
            int c = (f4 & 15) * 4;
            const float* rp = base + (size_t)(n0 + r) * (2 * DIM);
            float4 kk = *(const float4*)(rp + c);
            float4 vv = *(const float4*)(rp + DIM + c);
            Ks[r][c + 0] = expf(kk.x - cm[c + 0]) * ci[c + 0];
            Ks[r][c + 1] = expf(kk.y - cm[c + 1]) * ci[c + 1];
            Ks[r][c + 2] = expf(kk.z - cm[c + 2]) * ci[c + 2];
            Ks[r][c + 3] = expf(kk.w - cm[c + 3]) * ci[c + 3];
            *(float4*)&Vs[r][c] = vv;
        }
        __syncthreads();
        #pragma unroll
        for (int r = 0; r < 32; r++) {
            float4 av = *(const float4*)&Ks[r][ty * 4];
            float4 bv = *(const float4*)&Vs[r][tx * 4];
            float a[4] = {av.x, av.y, av.z, av.w};
            float bb[4] = {bv.x, bv.y, bv.z, bv.w};
            #pragma unroll
            for (int i = 0; i < 4; i++)
                #pragma unroll
                for (int j = 0; j < 4; j++)
                    acc[i][j] += a[i] * bb[j];
        }
        __syncthreads();
    }
    float* cb = ctxp + (size_t)blk * (HE * HE);
    #pragma unroll
    for (int i = 0; i < 4; i++)
        #pragma unroll
        for (int j = 0; j < 4; j++)
            cb[(ty * 4 + i) * HE + tx * 4 + j] = acc[i][j];
}

__global__ void ctx_reduce_kernel(const float* __restrict__ ctxp, float* __restrict__ ctx)
{
    const int bh = blockIdx.x;
    const int tid = threadIdx.x;
    size_t o = (size_t)tid * 16;
    float4 s[4];
    #pragma unroll
    for (int i = 0; i < 4; i++) s[i] = make_float4(0.f, 0.f, 0.f, 0.f);
    #pragma unroll
    for (int ch = 0; ch < NCH; ch++) {
        const float4* src = (const float4*)(ctxp + ((size_t)bh * NCH + ch) * (HE * HE) + o);
        #pragma unroll
        for (int i = 0; i < 4; i++) {
            float4 v = src[i];
            s[i].x += v.x; s[i].y += v.y; s[i].z += v.z; s[i].w += v.w;
        }
    }
    float4* dst = (float4*)(ctx + (size_t)bh * (HE * HE) + o);
    #pragma unroll
    for (int i = 0; i < 4; i++) dst[i] = s[i];
}

// ---------------- cross-attn output + residual + LN2 -------------------------
__global__ void cross_out_ln2_kernel(const float* __restrict__ q2, const float* __restrict__ ctx,
                                     const float* __restrict__ res, const float* __restrict__ g,
                                     const float* __restrict__ beta, float* __restrict__ out)
{
    const int row = blockIdx.x;
    const int b = row >> 11;
    const int tid = threadIdx.x;
    const int w = tid >> 5, lane = tid & 31;

    __shared__ float qs_s[DIM];
    __shared__ float red[16];

    const float* qr = q2 + (size_t)row * DIM;
    {
        float a0 = qr[w * HE + lane], a1 = qr[w * HE + 32 + lane];
        float m = fmaxf(a0, a1);
        #pragma unroll
        for (int o = 16; o > 0; o >>= 1) m = fmaxf(m, __shfl_xor_sync(0xffffffffu, m, o));
        float t0 = expf(a0 - m), t1 = expf(a1 - m);
        float s = t0 + t1;
        #pragma unroll
        for (int o = 16; o > 0; o >>= 1) s += __shfl_xor_sync(0xffffffffu, s, o);
        float sc = 0.125f / s;
        qs_s[w * HE + lane] = t0 * sc;
        qs_s[w * HE + 32 + lane] = t1 * sc;
    }
    __syncthreads();

    float pre[2], sum = 0.f, sumsq = 0.f;
    #pragma unroll
    for (int it = 0; it < 2; it++) {
        int o = tid + it * 256;
        int h = o >> 6, e = o & 63;
        const float* cb = ctx + ((size_t)(b * NH + h)) * (HE * HE) + e;
        const float* qh = qs_s + h * HE;
        float acc = 0.f;
        #pragma unroll 8
        for (int d = 0; d < HE; d++) acc += qh[d] * cb[d * HE];
        float p = acc + res[(size_t)row * DIM + o];
        pre[it] = p; sum += p; sumsq += p * p;
    }
    #pragma unroll
    for (int o = 16; o > 0; o >>= 1) {
        sum   += __shfl_xor_sync(0xffffffffu, sum, o);
        sumsq += __shfl_xor_sync(0xffffffffu, sumsq, o);
    }
    if (lane == 0) { red[w] = sum; red[8 + w] = sumsq; }
    __syncthreads();
    if (tid == 0) {
        float s = 0.f, q = 0.f;
        #pragma unroll
        for (int i = 0; i < 8; i++) { s += red[i]; q += red[8 + i]; }
        float mu = s / (float)DIM;
        float var = q / (float)DIM - mu * mu;
        red[0] = mu; red[1] = rsqrtf(var + LN_EPS);
    }
    __syncthreads();
    float mu = red[0], rstd = red[1];
    #pragma unroll
    for (int it = 0; it < 2; it++) {
        int o = tid + it * 256;
        out[(size_t)row * DIM + o] = (pre[it] - mu) * rstd * g[o] + beta[o];
    }
}

// ---------------- host launch ------------------------------------------------
extern "C" void kernel_launch(void* const* d_in, const int* in_sizes, int n_in,
                              void* d_out, int out_size)
{
    const float* x      = (const float*)d_in[0];
    const float* memory = (const float*)d_in[1];
    const float* W_qvk  = (const float*)d_in[2];
    const float* b_qvk  = (const float*)d_in[3];
    const float* W_kv   = (const float*)d_in[4];
    const float* b_kv   = (const float*)d_in[5];
    const float* W_q    = (const float*)d_in[6];
    const float* b_q    = (const float*)d_in[7];
    const float* W_ff1  = (const float*)d_in[8];
    const float* b_ff1  = (const float*)d_in[9];
    const float* W_ff2  = (const float*)d_in[10];
    const float* b_ff2  = (const float*)d_in[11];
    const float* ln1_g  = (const float*)d_in[12];
    const float* ln1_b  = (const float*)d_in[13];
    const float* ln2_g  = (const float*)d_in[14];
    const float* ln2_b  = (const float*)d_in[15];
    const float* ln3_g  = (const float*)d_in[16];
    const float* ln3_b  = (const float*)d_in[17];
    float* outp = (float*)d_out;

    float *qvk, *attn1, *ln1, *kv, *q2, *colmax, *colsum, *ctxp, *ctx, *ln2, *ff1, *pre3;
    float *csumK, *csumKV, *kcp, *Sp;
    cudaGetSymbolAddress((void**)&qvk,   g_qvk);
    cudaGetSymbolAddress((void**)&attn1, g_attn1);
    cudaGetSymbolAddress((void**)&ln1,   g_ln1);
    cudaGetSymbolAddress((void**)&kv,    g_kv);
    cudaGetSymbolAddress((void**)&q2,    g_q2);
    cudaGetSymbolAddress((void**)&colmax,g_colmax);
    cudaGetSymbolAddress((void**)&colsum,g_colsum);
    cudaGetSymbolAddress((void**)&ctxp,  g_ctxp);
    cudaGetSymbolAddress((void**)&ctx,   g_ctx);
    cudaGetSymbolAddress((void**)&ln2,   g_ln2);
    cudaGetSymbolAddress((void**)&ff1,   g_ff1);
    cudaGetSymbolAddress((void**)&pre3,  g_pre3);
    cudaGetSymbolAddress((void**)&csumK, g_csumK);
    cudaGetSymbolAddress((void**)&csumKV,g_csumKV);
    cudaGetSymbolAddress((void**)&kcp,   g_kcp);
    cudaGetSymbolAddress((void**)&Sp,    g_Sp);

    const int CSMEM = (5 * 64 * 68 + 128) * (int)sizeof(float);
    cudaFuncSetAttribute(causal_chunk_kernel, cudaFuncAttributeMaxDynamicSharedMemorySize, CSMEM);

    // 1) qvk = x @ W_qvk + b
    gemm_mma<<<dim3((3 * DIM) / 128, ROWS / 128), 256>>>(x, W_qvk, b_qvk, qvk, ROWS, 3 * DIM, DIM, 0);
    // 2) causal linear self-attention, chunk-parallel
    chunk_sum_kernel<<<BH * NC, 256>>>(qvk, csumK, csumKV);
    prefix_kernel<<<BH, 256>>>(csumK, csumKV, kcp, Sp);
    causal_chunk_kernel<<<BH * NC, 256, CSMEM>>>(qvk, kcp, Sp, attn1);
    // 3) LN1(attn + x)
    ln_res_kernel<<<ROWS, 256>>>(attn1, x, ln1_g, ln1_b, ln1);
    // 4) kv = memory @ W_kv + b
    gemm_mma<<<dim3((2 * DIM) / 128, ROWS / 128), 256>>>(memory, W_kv, b_kv, kv, ROWS, 2 * DIM, DIM, 0);
    // 5) q2 = ln1 @ W_q + b
    gemm_mma<<<dim3(DIM / 128, ROWS / 128), 256>>>(ln1, W_q, b_q, q2, ROWS, DIM, DIM, 0);
    // 6) column softmax stats of k over memory rows
    col_stats_kernel<<<dim3(DIM / 32, BATCH), 256>>>(kv, colmax, colsum);
    // 7) ctx = softk^T @ v per head (n-chunked + reduce)
    cross_ctx_kernel<<<BH * NCH, 256>>>(kv, colmax, colsum, ctxp);
    ctx_reduce_kernel<<<BH, 256>>>(ctxp, ctx);
    // 8) out2 = softmax(q2) @ ctx, + res, LN2 (fused)
    cross_out_ln2_kernel<<<ROWS, 256>>>(q2, ctx, ln1, ln2_g, ln2_b, ln2);
    // 9) ff1 = relu(ln2 @ W_ff1 + b)
    gemm_mma<<<dim3(FF / 128, ROWS / 128), 256>>>(ln2, W_ff1, b_ff1, ff1, ROWS, FF, DIM, 1);
    // 10) pre3 = ff1 @ W_ff2 + b
    gemm_mma<<<dim3(DIM / 128, ROWS / 128), 256>>>(ff1, W_ff2, b_ff2, pre3, ROWS, DIM, FF, 0);
    // 11) LN3(pre3 + ln2) -> output
    ln_res_kernel<<<ROWS, 256>>>(pre3, ln2, ln3_g, ln3_b, outp);
}

// round 8
// speedup vs baseline: 5.1649x; 1.0443x over previous
#include <cuda_runtime.h>
#include <cuda_bf16.h>
#include <math.h>
#include <stdint.h>

// Problem dims
#define BATCH 2
#define SEQN 2048
#define SEQM 2048
#define DIM 512
#define NH 8
#define HE 64
#define FF 2048
#define ROWS (BATCH * SEQN)   // 4096
#define LN_EPS 1e-5f
#define ATTN_EPS 1e-6f

// chunked causal linear attention
#define CC 64
#define NC (SEQN / CC)        // 32
#define BH (BATCH * NH)       // 16
// cross-attn ctx n-split
#define NCH 8
#define CHROWS (SEQM / NCH)   // 256

// ---------------- scratch (device globals; no allocations allowed) ----------
__device__ float g_qvk [ROWS * 3 * DIM];
__device__ float g_attn1[ROWS * DIM];
__device__ float g_ln1 [ROWS * DIM];
__device__ float g_kv  [ROWS * 2 * DIM];
__device__ float g_q2  [ROWS * DIM];
__device__ float g_colmax[BATCH * DIM];
__device__ float g_colsum[BATCH * DIM];
__device__ float g_ctxp[BH * NCH * HE * HE];
__device__ float g_ctx [BH * HE * HE];
__device__ float g_ln2 [ROWS * DIM];
__device__ float g_pre3[ROWS * DIM];
// causal-chunk state
__device__ float g_csumK [BH * NC * HE];
__device__ float g_csumKV[BH * NC * HE * HE];
__device__ float g_kcp   [BH * NC * HE];
__device__ float g_Sp    [BH * NC * HE * HE];
// bf16 hi/lo split tensors
__device__ __nv_bfloat16 g_xh [ROWS * DIM],      g_xl [ROWS * DIM];
__device__ __nv_bfloat16 g_mh [ROWS * DIM],      g_ml [ROWS * DIM];
__device__ __nv_bfloat16 g_ln1h[ROWS * DIM],     g_ln1l[ROWS * DIM];
__device__ __nv_bfloat16 g_ln2h[ROWS * DIM],     g_ln2l[ROWS * DIM];
__device__ __nv_bfloat16 g_ff1h[ROWS * FF],      g_ff1l[ROWS * FF];
__device__ __nv_bfloat16 g_wqvkh[DIM * 3 * DIM], g_wqvkl[DIM * 3 * DIM];
__device__ __nv_bfloat16 g_wkvh [DIM * 2 * DIM], g_wkvl [DIM * 2 * DIM];
__device__ __nv_bfloat16 g_wqh  [DIM * DIM],     g_wql  [DIM * DIM];
__device__ __nv_bfloat16 g_wf1h [DIM * FF],      g_wf1l [DIM * FF];
__device__ __nv_bfloat16 g_wf2h [FF * DIM],      g_wf2l [FF * DIM];

// ---------------- helpers ----------------------------------------------------
__device__ __forceinline__ uint32_t smem_u32(const void* p) {
    uint32_t a;
    asm("{ .reg .u64 t; cvta.to.shared.u64 t, %1; cvt.u32.u64 %0, t; }" : "=r"(a) : "l"(p));
    return a;
}
__device__ __forceinline__ void ldmat_x4(uint32_t& r0, uint32_t& r1, uint32_t& r2, uint32_t& r3,
                                         uint32_t addr) {
    asm volatile("ldmatrix.sync.aligned.m8n8.x4.shared.b16 {%0,%1,%2,%3}, [%4];"
                 : "=r"(r0), "=r"(r1), "=r"(r2), "=r"(r3) : "r"(addr));
}
__device__ __forceinline__ void ldmat_x4t(uint32_t& r0, uint32_t& r1, uint32_t& r2, uint32_t& r3,
                                          uint32_t addr) {
    asm volatile("ldmatrix.sync.aligned.m8n8.x4.trans.shared.b16 {%0,%1,%2,%3}, [%4];"
                 : "=r"(r0), "=r"(r1), "=r"(r2), "=r"(r3) : "r"(addr));
}
__device__ __forceinline__ void mma_bf16(float* c, const uint32_t* a, const uint32_t* b) {
    asm volatile(
        "mma.sync.aligned.m16n8k16.row.col.f32.bf16.bf16.f32 "
        "{%0,%1,%2,%3}, {%4,%5,%6,%7}, {%8,%9}, {%0,%1,%2,%3};"
        : "+f"(c[0]), "+f"(c[1]), "+f"(c[2]), "+f"(c[3])
        : "r"(a[0]), "r"(a[1]), "r"(a[2]), "r"(a[3]), "r"(b[0]), "r"(b[1]));
}
#define CP_ASYNC16(dst, src) \
    asm volatile("cp.async.cg.shared.global [%0], [%1], 16;" :: "r"(dst), "l"(src) : "memory")
#define CP_COMMIT() asm volatile("cp.async.commit_group;" ::: "memory")

// ---------------- fp32 -> bf16 hi/lo split conversion ------------------------
__global__ void conv_split(const float4* __restrict__ in, uint2* __restrict__ hi,
                           uint2* __restrict__ lo, int n4)
{
    int i = blockIdx.x * blockDim.x + threadIdx.x;
    if (i >= n4) return;
    float4 f = in[i];
    __nv_bfloat16 h0 = __float2bfloat16_rn(f.x), h1 = __float2bfloat16_rn(f.y);
    __nv_bfloat16 h2 = __float2bfloat16_rn(f.z), h3 = __float2bfloat16_rn(f.w);
    __nv_bfloat16 l0 = __float2bfloat16_rn(f.x - __bfloat162float(h0));
    __nv_bfloat16 l1 = __float2bfloat16_rn(f.y - __bfloat162float(h1));
    __nv_bfloat16 l2 = __float2bfloat16_rn(f.z - __bfloat162float(h2));
    __nv_bfloat16 l3 = __float2bfloat16_rn(f.w - __bfloat162float(h3));
    __nv_bfloat162 ha = {h0, h1}, hb = {h2, h3}, la = {l0, l1}, lb = {l2, l3};
    hi[i] = make_uint2(*(uint32_t*)&ha, *(uint32_t*)&hb);
    lo[i] = make_uint2(*(uint32_t*)&la, *(uint32_t*)&lb);
}

// ================= split-bf16 tensor-core GEMM, cp.async pipelined ===========
// 128x128 CTA tile, BK=32, 8 warps (2x4), warp tile 64x32, 2-stage pipeline.
// A/B inputs pre-split into bf16 hi/lo. acc += AhBh + AlBh + AhBl (fp32).
#define OFF_AL 10240      // A: 128 rows * 80B
#define OFF_BH 20480
#define OFF_BL 29184      // B: 32 rows * 272B
#define PIPE_STAGE 37888
#define GB_SMEM (2 * PIPE_STAGE)

__global__ __launch_bounds__(256)
void gemm_bf(const __nv_bfloat16* __restrict__ Ah, const __nv_bfloat16* __restrict__ Al,
             const __nv_bfloat16* __restrict__ Bh, const __nv_bfloat16* __restrict__ Bl,
             const float* __restrict__ bias, float* __restrict__ Cf,
             __nv_bfloat16* __restrict__ Ch, __nv_bfloat16* __restrict__ Cl,
             int M, int N, int K, int relu)
{
    extern __shared__ char smc[];
    const uint32_t sb = smem_u32(smc);
    const int tid = threadIdx.x;
    const int lane = tid & 31, wid = tid >> 5;
    const int wm = (wid >> 2) * 64;
    const int wn = (wid & 3) * 32;
    const int row0 = blockIdx.y * 128, col0 = blockIdx.x * 128;

    // load indices (16B granules)
    const int a_r = tid >> 2, a_c = (tid & 3) * 16;        // granule 0; granule 1 at tid+256
    const int a_r2 = (tid + 256) >> 2, a_c2 = ((tid + 256) & 3) * 16;
    const int b_kr = tid >> 4, b_c = (tid & 15) * 16;
    const int b_kr2 = (tid + 256) >> 4, b_c2 = ((tid + 256) & 15) * 16;

    float acc[4][4][4] = {};

    // ldmatrix lane addressing
    const int la_row  = wm + (lane & 15);
    const int la_colb = (lane >> 4) * 8;
    const int lb_row  = (lane & 7) + ((lane >> 3) & 1) * 8;
    const int lb_colb = wn + (lane >> 4) * 8;

    const int nblk = K / 32;

    // prologue: stage 0
    {
        const int kq = 0;
        uint32_t st = sb;
        CP_ASYNC16(st + a_r * 80 + a_c, Ah + (size_t)(row0 + a_r) * K + kq + a_c / 2);
        CP_ASYNC16(st + a_r2 * 80 + a_c2, Ah + (size_t)(row0 + a_r2) * K + kq + a_c2 / 2);
        CP_ASYNC16(st + OFF_AL + a_r * 80 + a_c, Al + (size_t)(row0 + a_r) * K + kq + a_c / 2);
        CP_ASYNC16(st + OFF_AL + a_r2 * 80 + a_c2, Al + (size_t)(row0 + a_r2) * K + kq + a_c2 / 2);
        CP_ASYNC16(st + OFF_BH + b_kr * 272 + b_c, Bh + (size_t)(kq + b_kr) * N + col0 + b_c / 2);
        CP_ASYNC16(st + OFF_BH + b_kr2 * 272 + b_c2, Bh + (size_t)(kq + b_kr2) * N + col0 + b_c2 / 2);
        CP_ASYNC16(st + OFF_BL + b_kr * 272 + b_c, Bl + (size_t)(kq + b_kr) * N + col0 + b_c / 2);
        CP_ASYNC16(st + OFF_BL + b_kr2 * 272 + b_c2, Bl + (size_t)(kq + b_kr2) * N + col0 + b_c2 / 2);
        CP_COMMIT();
    }

    for (int kb = 0; kb < nblk; kb++) {
        const int more = (kb + 1 < nblk);
        if (more) {
            const int kq = (kb + 1) * 32;
            uint32_t st = sb + ((kb + 1) & 1) * PIPE_STAGE;
            CP_ASYNC16(st + a_r * 80 + a_c, Ah + (size_t)(row0 + a_r) * K + kq + a_c / 2);
            CP_ASYNC16(st + a_r2 * 80 + a_c2, Ah + (size_t)(row0 + a_r2) * K + kq + a_c2 / 2);
            CP_ASYNC16(st + OFF_AL + a_r * 80 + a_c, Al + (size_t)(row0 + a_r) * K + kq + a_c / 2);
            CP_ASYNC16(st + OFF_AL + a_r2 * 80 + a_c2, Al + (size_t)(row0 + a_r2) * K + kq + a_c2 / 2);
            CP_ASYNC16(st + OFF_BH + b_kr * 272 + b_c, Bh + (size_t)(kq + b_kr) * N + col0 + b_c / 2);
            CP_ASYNC16(st + OFF_BH + b_kr2 * 272 + b_c2, Bh + (size_t)(kq + b_kr2) * N + col0 + b_c2 / 2);
            CP_ASYNC16(st + OFF_BL + b_kr * 272 + b_c, Bl + (size_t)(kq + b_kr) * N + col0 + b_c / 2);
            CP_ASYNC16(st + OFF_BL + b_kr2 * 272 + b_c2, Bl + (size_t)(kq + b_kr2) * N + col0 + b_c2 / 2);
            CP_COMMIT();
            asm volatile("cp.async.wait_group 1;" ::: "memory");
        } else {
            asm volatile("cp.async.wait_group 0;" ::: "memory");
        }
        __syncthreads();

        const uint32_t st = sb + (kb & 1) * PIPE_STAGE;
        #pragma unroll
        for (int ks = 0; ks < 2; ks++) {
            uint32_t ah[4][4], al[4][4], bf[4][2];
            #pragma unroll
            for (int mt = 0; mt < 4; mt++) {
                uint32_t off = (uint32_t)((la_row + mt * 16) * 40 + ks * 16 + la_colb) * 2;
                ldmat_x4(ah[mt][0], ah[mt][1], ah[mt][2], ah[mt][3], st + off);
                ldmat_x4(al[mt][0], al[mt][1], al[mt][2], al[mt][3], st + OFF_AL + off);
            }
            #pragma unroll
            for (int p = 0; p < 2; p++) {
                uint32_t off = (uint32_t)((ks * 16 + lb_row) * 136 + lb_colb + p * 16) * 2;
                ldmat_x4t(bf[p * 2][0], bf[p * 2][1], bf[p * 2 + 1][0], bf[p * 2 + 1][1],
                          st + OFF_BH + off);
            }
            #pragma unroll
            for (int mt = 0; mt < 4; mt++)
                #pragma unroll
                for (int nt = 0; nt < 4; nt++) {
                    mma_bf16(acc[mt][nt], ah[mt], bf[nt]);
                    mma_bf16(acc[mt][nt], al[mt], bf[nt]);
                }
            #pragma unroll
            for (int p = 0; p < 2; p++) {
                uint32_t off = (uint32_t)((ks * 16 + lb_row) * 136 + lb_colb + p * 16) * 2;
                ldmat_x4t(bf[p * 2][0], bf[p * 2][1], bf[p * 2 + 1][0], bf[p * 2 + 1][1],
                          st + OFF_BL + off);
            }
            #pragma unroll
            for (int mt = 0; mt < 4; mt++)
                #pragma unroll
                for (int nt = 0; nt < 4; nt++)
                    mma_bf16(acc[mt][nt], ah[mt], bf[nt]);
        }
        __syncthreads();
    }

    // ---- epilogue ----
    const int r_l = lane >> 2, c_l = (lane & 3) * 2;
    #pragma unroll
    for (int mt = 0; mt < 4; mt++) {
        int row = row0 + wm + mt * 16 + r_l;
        #pragma unroll
        for (int nt = 0; nt < 4; nt++) {
            int col = col0 + wn + nt * 8 + c_l;
            float b0 = bias[col], b1 = bias[col + 1];
            float v00 = acc[mt][nt][0] + b0, v01 = acc[mt][nt][1] + b1;
            float v10 = acc[mt][nt][2] + b0, v11 = acc[mt][nt][3] + b1;
            if (relu) {
                v00 = fmaxf(v00, 0.f); v01 = fmaxf(v01, 0.f);
                v10 = fmaxf(v10, 0.f); v11 = fmaxf(v11, 0.f);
            }
            if (Cf) {
                *(float2*)(Cf + (size_t)row * N + col) = make_float2(v00, v01);
                *(float2*)(Cf + (size_t)(row + 8) * N + col) = make_float2(v10, v11);
            }
            if (Ch) {
                __nv_bfloat16 h00 = __float2bfloat16_rn(v00), h01 = __float2bfloat16_rn(v01);
                __nv_bfloat16 h10 = __float2bfloat16_rn(v10), h11 = __float2bfloat16_rn(v11);
                __nv_bfloat162 hp0 = {h00, h01}, hp1 = {h10, h11};
                __nv_bfloat162 lp0 = {__float2bfloat16_rn(v00 - __bfloat162float(h00)),
                                      __float2bfloat16_rn(v01 - __bfloat162float(h01))};
                __nv_bfloat162 lp1 = {__float2bfloat16_rn(v10 - __bfloat162float(h10)),
                                      __float2bfloat16_rn(v11 - __bfloat162float(h11))};
                *(__nv_bfloat162*)(Ch + (size_t)row * N + col) = hp0;
                *(__nv_bfloat162*)(Ch + (size_t)(row + 8) * N + col) = hp1;
                *(__nv_bfloat162*)(Cl + (size_t)row * N + col) = lp0;
                *(__nv_bfloat162*)(Cl + (size_t)(row + 8) * N + col) = lp1;
            }
        }
    }
}

// ---------------- causal chunk phase 1: per-chunk sums ----------------------
__global__ __launch_bounds__(256)
void chunk_sum_kernel(const float* __restrict__ qvk,
                      float* __restrict__ csumK, float* __restrict__ csumKV)
{
    const int blk = blockIdx.x;
    const int bh = blk / NC, c = blk % NC;
    const int b = bh >> 3, h = bh & 7;
    const int tid = threadIdx.x;

    __shared__ __align__(16) float Ks[CC][68];
    __shared__ __align__(16) float Vs[CC][68];

    const float* base = qvk + (size_t)b * SEQN * (3 * DIM) + (size_t)c * CC * (3 * DIM) + h * HE;
    #pragma unroll
    for (int i = tid; i < CC * 16; i += 256) {
        int r = i >> 4;
        int col = (i & 15) * 4;
        const float* rp = base + (size_t)r * (3 * DIM);
        float4 kk = *(const float4*)(rp + 2 * DIM + col);
        float4 vv = *(const float4*)(rp + DIM + col);
        Ks[r][col + 0] = expf(kk.x); Ks[r][col + 1] = expf(kk.y);
        Ks[r][col + 2] = expf(kk.z); Ks[r][col + 3] = expf(kk.w);
        *(float4*)&Vs[r][col] = vv;
    }
    __syncthreads();

    const int ty = tid >> 4, tx = tid & 15;
    const int d0 = ty * 4, e0 = tx * 4;
    float acc[4][4] = {};
    #pragma unroll 8
    for (int n = 0; n < CC; n++) {
        float4 a = *(const float4*)&Ks[n][d0];
        float4 bb = *(const float4*)&Vs[n][e0];
        float av[4] = {a.x, a.y, a.z, a.w};
        float bv[4] = {bb.x, bb.y, bb.z, bb.w};
        #pragma unroll
        for (int i = 0; i < 4; i++)
            #pragma unroll
            for (int j = 0; j < 4; j++)
                acc[i][j] += av[i] * bv[j];
    }
    float* outKV = csumKV + ((size_t)bh * NC + c) * (HE * HE);
    #pragma unroll
    for (int i = 0; i < 4; i++) {
        float4 o = {acc[i][0], acc[i][1], acc[i][2], acc[i][3]};
        *(float4*)(outKV + (d0 + i) * HE + e0) = o;
    }
    if (tid < HE) {
        float s = 0.f;
        #pragma unroll 8
        for (int n = 0; n < CC; n++) s += Ks[n][tid];
        csumK[((size_t)bh * NC + c) * HE + tid] = s;
    }
}

// ---------------- causal chunk phase 2: exclusive prefix over chunks --------
__global__ __launch_bounds__(256)
void prefix_kernel(const float* __restrict__ csumK, const float* __restrict__ csumKV,
                   float* __restrict__ kcp, float* __restrict__ Sp)
{
    const int bh = blockIdx.x;
    const int tid = threadIdx.x;
    float4 run[4];
    #pragma unroll
    for (int i = 0; i < 4; i++) run[i] = make_float4(0.f, 0.f, 0.f, 0.f);
    for (int c = 0; c < NC; c++) {
        size_t base = ((size_t)bh * NC + c) * (HE * HE) + (size_t)tid * 16;
        float4* dst = (float4*)(Sp + base);
        const float4* src = (const float4*)(csumKV + base);
        #pragma unroll
        for (int i = 0; i < 4; i++) {
            dst[i] = run[i];
            float4 s = src[i];
            run[i].x += s.x; run[i].y += s.y; run[i].z += s.z; run[i].w += s.w;
        }
    }
    if (tid < HE) {
        float rk = 0.f;
        for (int c = 0; c < NC; c++) {
            size_t o = ((size_t)bh * NC + c) * HE + tid;
            kcp[o] = rk;
            rk += csumK[o];
        }
    }
}

// ---------------- causal chunk phase 3: per-chunk output --------------------
__global__ __launch_bounds__(256)
void causal_chunk_kernel(const float* __restrict__ qvk,
                         const float* __restrict__ kcp, const float* __restrict__ Sp,
                         float* __restrict__ out)
{
    extern __shared__ __align__(16) float sm[];
    float (*TsT)[68] = (float(*)[68])sm;
    float (*KsT)[68] = TsT + 64;
    float (*AT)[68]  = KsT + 64;
    float (*Vs)[68]  = AT + 64;
    float (*SpS)[68] = Vs + 64;
    float* kcpe = (float*)(SpS + 64);
    float* den  = kcpe + 64;

    const int blk = blockIdx.x;
    const int bh = blk / NC, c = blk % NC;
    const int b = bh >> 3, h = bh & 7;
    const int tid = threadIdx.x;
    const float* base = qvk + (size_t)b * SEQN * (3 * DIM) + (size_t)c * CC * (3 * DIM) + h * HE;

    {
        int r = tid >> 2;
        int g = tid & 3;
        const float* rp = base + (size_t)r * (3 * DIM) + g * 16;
        float qv[16];
        float m = -1e30f;
        #pragma unroll
        for (int j = 0; j < 16; j++) { qv[j] = rp[j]; m = fmaxf(m, qv[j]); }
        m = fmaxf(m, __shfl_xor_sync(0xffffffffu, m, 1));
        m = fmaxf(m, __shfl_xor_sync(0xffffffffu, m, 2));
        #pragma unroll
        for (int j = 0; j < 16; j++) TsT[g * 16 + j][r] = expf(qv[j] - m);
        const float* rpk = rp + 2 * DIM;
        #pragma unroll
        for (int j = 0; j < 16; j++) KsT[g * 16 + j][r] = expf(rpk[j]);
    }
    #pragma unroll
    for (int i = tid; i < CC * 16; i += 256) {
        int r = i >> 4, col = (i & 15) * 4;
        *(float4*)&Vs[r][col] = *(const float4*)(base + (size_t)r * (3 * DIM) + DIM + col);
    }
    const float* spb = Sp + ((size_t)bh * NC + c) * (HE * HE);
    #pragma unroll
    for (int i = tid; i < HE * 16; i += 256) {
        int r = i >> 4, col = (i & 15) * 4;
        *(float4*)&SpS[r][col] = *(const float4*)(spb + r * HE + col);
    }
    if (tid < HE) kcpe[tid] = kcp[((size_t)bh * NC + c) * HE + tid] + ATTN_EPS;
    __syncthreads();

    const int ty = tid >> 4, tx = tid & 15;
    const int t0 = ty * 4, s0 = tx * 4;

    {
        float acc[4][4] = {};
        #pragma unroll 8
        for (int d = 0; d < HE; d++) {
            float4 a = *(const float4*)&TsT[d][t0];
            float4 bb = *(const float4*)&KsT[d][s0];
            float av[4] = {a.x, a.y, a.z, a.w};
            float bv[4] = {bb.x, bb.y, bb.z, bb.w};
            #pragma unroll
            for (int i = 0; i < 4; i++)
                #pragma unroll
                for (int j = 0; j < 4; j++)
                    acc[i][j] += av[i] * bv[j];
        }
        #pragma unroll
        for (int i = 0; i < 4; i++)
            #pragma unroll
            for (int j = 0; j < 4; j++) {
                int t = t0 + i, s = s0 + j;
                AT[s][t] = (s <= t) ? acc[i][j] : 0.f;
            }
    }
    __syncthreads();

    if (tid < 128) {
        int t = tid >> 1, half = tid & 1;
        float sd = 0.f;
        int lo = half * 32;
        #pragma unroll 8
        for (int s = lo; s < lo + 32; s++) sd += AT[s][t];
        #pragma unroll 8
        for (int d = lo; d < lo + 32; d++) sd += TsT[d][t] * kcpe[d];
        sd += __shfl_xor_sync(0xffffffffu, sd, 1);
        if (!half) den[t] = 1.0f / sd;
    }
    __syncthreads();

    {
        const int e0 = tx * 4;
        float o[4][4] = {};
        #pragma unroll 8
        for (int s = 0; s < CC; s++) {
            float4 a = *(const float4*)&AT[s][t0];
            float4 bb = *(const float4*)&Vs[s][e0];
            float av[4] = {a.x, a.y, a.z, a.w};
            float bv[4] = {bb.x, bb.y, bb.z, bb.w};
            #pragma unroll
            for (int i = 0; i < 4; i++)
                #pragma unroll
                for (int j = 0; j < 4; j++)
                    o[i][j] += av[i] * bv[j];
        }
        #pragma unroll 8
        for (int d = 0; d < HE; d++) {
            float4 a = *(const float4*)&TsT[d][t0];
            float4 bb = *(const float4*)&SpS[d][e0];
            float av[4] = {a.x, a.y, a.z, a.w};
            float bv[4] = {bb.x, bb.y, bb.z, bb.w};
            #pragma unroll
            for (int i = 0; i < 4; i++)
                #pragma unroll
                for (int j = 0; j < 4; j++)
                    o[i][j] += av[i] * bv[j];
        }
        float* ob = out + (size_t)b * SEQN * DIM + (size_t)c * CC * DIM + h * HE;
        #pragma unroll
        for (int i = 0; i < 4; i++) {
            float rcp = den[t0 + i];
            float4 ov = {o[i][0] * rcp, o[i][1] * rcp, o[i][2] * rcp, o[i][3] * rcp};
            *(float4*)(ob + (size_t)(t0 + i) * DIM + e0) = ov;
        }
    }
}

// ---------------- residual + layernorm (+ optional bf16 hi/lo out) -----------
__global__ void ln_res_kernel(const float* __restrict__ a, const float* __restrict__ r,
                              const float* __restrict__ g, const float* __restrict__ beta,
                              float* __restrict__ out,
                              __nv_bfloat16* __restrict__ oh, __nv_bfloat16* __restrict__ ol)
{
    const int row = blockIdx.x;
    const int tid = threadIdx.x;
    const int w = tid >> 5, lane = tid & 31;
    __shared__ float red[16];

    float pre[2], sum = 0.f, sumsq = 0.f;
    #pragma unroll
    for (int it = 0; it < 2; it++) {
        int o = tid + it * 256;
        float p = a[(size_t)row * DIM + o] + r[(size_t)row * DIM + o];
        pre[it] = p; sum += p; sumsq += p * p;
    }
    #pragma unroll
    for (int o = 16; o > 0; o >>= 1) {
        sum   += __shfl_xor_sync(0xffffffffu, sum, o);
        sumsq += __shfl_xor_sync(0xffffffffu, sumsq, o);
    }
    if (lane == 0) { red[w] = sum; red[8 + w] = sumsq; }
    __syncthreads();
    if (tid == 0) {
        float s = 0.f, q = 0.f;
        #pragma unroll
        for (int i = 0; i < 8; i++) { s += red[i]; q += red[8 + i]; }
        float mu = s / (float)DIM;
        float var = q / (float)DIM - mu * mu;
        red[0] = mu; red[1] = rsqrtf(var + LN_EPS);
    }
    __syncthreads();
    float mu = red[0], rstd = red[1];
    #pragma unroll
    for (int it = 0; it < 2; it++) {
        int o = tid + it * 256;
        float v = (pre[it] - mu) * rstd * g[o] + beta[o];
        out[(size_t)row * DIM + o] = v;
        if (oh) {
            __nv_bfloat16 h = __float2bfloat16_rn(v);
            oh[(size_t)row * DIM + o] = h;
            ol[(size_t)row * DIM + o] = __float2bfloat16_rn(v - __bfloat162float(h));
        }
    }
}

// ---------------- cross-attn: per-column softmax stats -----------------------
__global__ void col_stats_kernel(const float* __restrict__ kv,
                                 float* __restrict__ colmax, float* __restrict__ colsum)
{
    const int b = blockIdx.y;
    const int lane = threadIdx.x & 31;
    const int r = threadIdx.x >> 5;
    const int d = blockIdx.x * 32 + lane;
    const float* base = kv + (size_t)b * SEQM * (2 * DIM) + d;

    __shared__ float sm[8][32];
    __shared__ float cm[32];

    float m = -1e30f;
    for (int n = r; n < SEQM; n += 8) m = fmaxf(m, base[(size_t)n * (2 * DIM)]);
    sm[r][lane] = m;
    __syncthreads();
    if (threadIdx.x < 32) {
        float mm = sm[0][threadIdx.x];
        #pragma unroll
        for (int i = 1; i < 8; i++) mm = fmaxf(mm, sm[i][threadIdx.x]);
        cm[threadIdx.x] = mm;
        colmax[b * DIM + blockIdx.x * 32 + threadIdx.x] = mm;
    }
    __syncthreads();
    float s = 0.f;
    float mref = cm[lane];
    for (int n = r; n < SEQM; n += 8) s += expf(base[(size_t)n * (2 * DIM)] - mref);
    sm[r][lane] = s;
    __syncthreads();
    if (threadIdx.x < 32) {
        float ss = sm[0][threadIdx.x];
        #pragma unroll
        for (int i = 1; i < 8; i++) ss += sm[i][threadIdx.x];
        colsum[b * DIM + blockIdx.x * 32 + threadIdx.x] = ss;
    }
}

// ---------------- cross-attn: partial ctx over n-chunks ----------------------
__global__ void cross_ctx_kernel(const float* __restrict__ kv,
                                 const float* __restrict__ colmax, const float* __restrict__ colsum,
                                 float* __restrict__ ctxp)
{
    const int blk = blockIdx.x;
    const int bh = blk / NCH, ch = blk % NCH;
    const int b = bh >> 3, h = bh & 7;
    const int tid = threadIdx.x;
    const int tx = tid & 15, ty = tid >> 4;

    __shared__ __align__(16) float Ks[32][64];
    __shared__ __align__(16) float Vs[32][64];
    __shared__ float cm[64], ci[64];

    if (tid < 64) {
        cm[tid] = colmax[b * DIM + h * HE + tid];
        ci[tid] = 1.0f / colsum[b * DIM + h * HE + tid];
    }
    __syncthreads();

    float acc[4][4] = {};
    const float* base = kv + (size_t)b * SEQM * (2 * DIM) + h * HE;
    const int n_lo = ch * CHROWS, n_hi = n_lo + CHROWS;
    for (int n0 = n_lo; n0 < n_hi; n0 += 32) {
        #pragma unroll
        for (int it = 0; it < 2; it++) {
            int f4 = tid + it * 256;
            int r = f4 >> 4;
            int c = (f4 & 15) * 4;
            const float* rp = base + (size_t)(n0 + r) * (2 * DIM);
            float4 kk = *(const float4*)(rp + c);
            float4 vv = *(const float4*)(rp + DIM + c);
            Ks[r][c + 0] = expf(kk.x - cm[c + 0]) * ci[c + 0];
            Ks[r][c + 1] = expf(kk.y - cm[c + 1]) * ci[c + 1];
            Ks[r][c + 2] = expf(kk.z - cm[c + 2]) * ci[c + 2];
            Ks[r][c + 3] = expf(kk.w - cm[c + 3]) * ci[c + 3];
            *(float4*)&Vs[r][c] = vv;
        }
        __syncthreads();
        #pragma unroll
        for (int r = 0; r < 32; r++) {
            float4 av = *(const float4*)&Ks[r][ty * 4];
            float4 bv = *(const float4*)&Vs[r][tx * 4];
            float a[4] = {av.x, av.y, av.z, av.w};
            float bb[4] = {bv.x, bv.y, bv.z, bv.w};
            #pragma unroll
            for (int i = 0; i < 4; i++)
                #pragma unroll
                for (int j = 0; j < 4; j++)
                    acc[i][j] += a[i] * bb[j];
        }
        __syncthreads();
    }
    float* cb = ctxp + (size_t)blk * (HE * HE);
    #pragma unroll
    for (int i = 0; i < 4; i++)
        #pragma unroll
        for (int j = 0; j < 4; j++)
            cb[(ty * 4 + i) * HE + tx * 4 + j] = acc[i][j];
}

__global__ void ctx_reduce_kernel(const float* __restrict__ ctxp, float* __restrict__ ctx)
{
    const int bh = blockIdx.x;
    const int tid = threadIdx.x;
    size_t o = (size_t)tid * 16;
    float4 s[4];
    #pragma unroll
    for (int i = 0; i < 4; i++) s[i] = make_float4(0.f, 0.f, 0.f, 0.f);
    #pragma unroll
    for (int ch = 0; ch < NCH; ch++) {
        const float4* src = (const float4*)(ctxp + ((size_t)bh * NCH + ch) * (HE * HE) + o);
        #pragma unroll
        for (int i = 0; i < 4; i++) {
            float4 v = src[i];
            s[i].x += v.x; s[i].y += v.y; s[i].z += v.z; s[i].w += v.w;
        }
    }
    float4* dst = (float4*)(ctx + (size_t)bh * (HE * HE) + o);
    #pragma unroll
    for (int i = 0; i < 4; i++) dst[i] = s[i];
}

// ---------------- cross-attn output + residual + LN2 (+ bf16 out) -----------
__global__ void cross_out_ln2_kernel(const float* __restrict__ q2, const float* __restrict__ ctx,
                                     const float* __restrict__ res, const float* __restrict__ g,
                                     const float* __restrict__ beta, float* __restrict__ out,
                                     __nv_bfloat16* __restrict__ oh, __nv_bfloat16* __restrict__ ol)
{
    const int row = blockIdx.x;
    const int b = row >> 11;
    const int tid = threadIdx.x;
    const int w = tid >> 5, lane = tid & 31;

    __shared__ float qs_s[DIM];
    __shared__ float red[16];

    const float* qr = q2 + (size_t)row * DIM;
    {
        float a0 = qr[w * HE + lane], a1 = qr[w * HE + 32 + lane];
        float m = fmaxf(a0, a1);
        #pragma unroll
        for (int o = 16; o > 0; o >>= 1) m = fmaxf(m, __shfl_xor_sync(0xffffffffu, m, o));
        float t0 = expf(a0 - m), t1 = expf(a1 - m);
        float s = t0 + t1;
        #pragma unroll
        for (int o = 16; o > 0; o >>= 1) s += __shfl_xor_sync(0xffffffffu, s, o);
        float sc = 0.125f / s;
        qs_s[w * HE + lane] = t0 * sc;
        qs_s[w * HE + 32 + lane] = t1 * sc;
    }
    __syncthreads();

    float pre[2], sum = 0.f, sumsq = 0.f;
    #pragma unroll
    for (int it = 0; it < 2; it++) {
        int o = tid + it * 256;
        int h = o >> 6, e = o & 63;
        const float* cb = ctx + ((size_t)(b * NH + h)) * (HE * HE) + e;
        const float* qh = qs_s + h * HE;
        float acc = 0.f;
        #pragma unroll 8
        for (int d = 0; d < HE; d++) acc += qh[d] * cb[d * HE];
        float p = acc + res[(size_t)row * DIM + o];
        pre[it] = p; sum += p; sumsq += p * p;
    }
    #pragma unroll
    for (int o = 16; o > 0; o >>= 1) {
        sum   += __shfl_xor_sync(0xffffffffu, sum, o);
        sumsq += __shfl_xor_sync(0xffffffffu, sumsq, o);
    }
    if (lane == 0) { red[w] = sum; red[8 + w] = sumsq; }
    __syncthreads();
    if (tid == 0) {
        float s = 0.f, q = 0.f;
        #pragma unroll
        for (int i = 0; i < 8; i++) { s += red[i]; q += red[8 + i]; }
        float mu = s / (float)DIM;
        float var = q / (float)DIM - mu * mu;
        red[0] = mu; red[1] = rsqrtf(var + LN_EPS);
    }
    __syncthreads();
    float mu = red[0], rstd = red[1];
    #pragma unroll
    for (int it = 0; it < 2; it++) {
        int o = tid + it * 256;
        float v = (pre[it] - mu) * rstd * g[o] + beta[o];
        out[(size_t)row * DIM + o] = v;
        __nv_bfloat16 h = __float2bfloat16_rn(v);
        oh[(size_t)row * DIM + o] = h;
        ol[(size_t)row * DIM + o] = __float2bfloat16_rn(v - __bfloat162float(h));
    }
}

// ---------------- host launch ------------------------------------------------
extern "C" void kernel_launch(void* const* d_in, const int* in_sizes, int n_in,
                              void* d_out, int out_size)
{
    const float* x      = (const float*)d_in[0];
    const float* memory = (const float*)d_in[1];
    const float* W_qvk  = (const float*)d_in[2];
    const float* b_qvk  = (const float*)d_in[3];
    const float* W_kv   = (const float*)d_in[4];
    const float* b_kv   = (const float*)d_in[5];
    const float* W_q    = (const float*)d_in[6];
    const float* b_q    = (const float*)d_in[7];
    const float* W_ff1  = (const float*)d_in[8];
    const float* b_ff1  = (const float*)d_in[9];
    const float* W_ff2  = (const float*)d_in[10];
    const float* b_ff2  = (const float*)d_in[11];
    const float* ln1_g  = (const float*)d_in[12];
    const float* ln1_b  = (const float*)d_in[13];
    const float* ln2_g  = (const float*)d_in[14];
    const float* ln2_b  = (const float*)d_in[15];
    const float* ln3_g  = (const float*)d_in[16];
    const float* ln3_b  = (const float*)d_in[17];
    float* outp = (float*)d_out;

    float *qvk, *attn1, *ln1, *kv, *q2, *colmax, *colsum, *ctxp, *ctx, *ln2, *pre3;
    float *csumK, *csumKV, *kcp, *Sp;
    __nv_bfloat16 *xh, *xl, *mh, *ml, *ln1h, *ln1l, *ln2h, *ln2l, *ff1h, *ff1l;
    __nv_bfloat16 *wqvkh, *wqvkl, *wkvh, *wkvl, *wqh, *wql, *wf1h, *wf1l, *wf2h, *wf2l;
    cudaGetSymbolAddress((void**)&qvk,   g_qvk);
    cudaGetSymbolAddress((void**)&attn1, g_attn1);
    cudaGetSymbolAddress((void**)&ln1,   g_ln1);
    cudaGetSymbolAddress((void**)&kv,    g_kv);
    cudaGetSymbolAddress((void**)&q2,    g_q2);
    cudaGetSymbolAddress((void**)&colmax,g_colmax);
    cudaGetSymbolAddress((void**)&colsum,g_colsum);
    cudaGetSymbolAddress((void**)&ctxp,  g_ctxp);
    cudaGetSymbolAddress((void**)&ctx,   g_ctx);
    cudaGetSymbolAddress((void**)&ln2,   g_ln2);
    cudaGetSymbolAddress((void**)&pre3,  g_pre3);
    cudaGetSymbolAddress((void**)&csumK, g_csumK);
    cudaGetSymbolAddress((void**)&csumKV,g_csumKV);
    cudaGetSymbolAddress((void**)&kcp,   g_kcp);
    cudaGetSymbolAddress((void**)&Sp,    g_Sp);
    cudaGetSymbolAddress((void**)&xh,   g_xh);   cudaGetSymbolAddress((void**)&xl,   g_xl);
    cudaGetSymbolAddress((void**)&mh,   g_mh);   cudaGetSymbolAddress((void**)&ml,   g_ml);
    cudaGetSymbolAddress((void**)&ln1h, g_ln1h); cudaGetSymbolAddress((void**)&ln1l, g_ln1l);
    cudaGetSymbolAddress((void**)&ln2h, g_ln2h); cudaGetSymbolAddress((void**)&ln2l, g_ln2l);
    cudaGetSymbolAddress((void**)&ff1h, g_ff1h); cudaGetSymbolAddress((void**)&ff1l, g_ff1l);
    cudaGetSymbolAddress((void**)&wqvkh,g_wqvkh);cudaGetSymbolAddress((void**)&wqvkl,g_wqvkl);
    cudaGetSymbolAddress((void**)&wkvh, g_wkvh); cudaGetSymbolAddress((void**)&wkvl, g_wkvl);
    cudaGetSymbolAddress((void**)&wqh,  g_wqh);  cudaGetSymbolAddress((void**)&wql,  g_wql);
    cudaGetSymbolAddress((void**)&wf1h, g_wf1h); cudaGetSymbolAddress((void**)&wf1l, g_wf1l);
    cudaGetSymbolAddress((void**)&wf2h, g_wf2h); cudaGetSymbolAddress((void**)&wf2l, g_wf2l);

    const int CSMEM = (5 * 64 * 68 + 128) * (int)sizeof(float);
    cudaFuncSetAttribute(causal_chunk_kernel, cudaFuncAttributeMaxDynamicSharedMemorySize, CSMEM);
    cudaFuncSetAttribute(gemm_bf, cudaFuncAttributeMaxDynamicSharedMemorySize, GB_SMEM);

    // 0) precision-split conversions (inputs + weights)
    #define CONV(src, dh, dl, n) \
        conv_split<<<((n) / 4 + 255) / 256, 256>>>((const float4*)(src), (uint2*)(dh), (uint2*)(dl), (n) / 4)
    CONV(x,      xh,    xl,    ROWS * DIM);
    CONV(memory, mh,    ml,    ROWS * DIM);
    CONV(W_qvk,  wqvkh, wqvkl, DIM * 3 * DIM);
    CONV(W_kv,   wkvh,  wkvl,  DIM * 2 * DIM);
    CONV(W_q,    wqh,   wql,   DIM * DIM);
    CONV(W_ff1,  wf1h,  wf1l,  DIM * FF);
    CONV(W_ff2,  wf2h,  wf2l,  FF * DIM);

    // 1) qvk = x @ W_qvk + b
    gemm_bf<<<dim3((3 * DIM) / 128, ROWS / 128), 256, GB_SMEM>>>(
        xh, xl, wqvkh, wqvkl, b_qvk, qvk, nullptr, nullptr, ROWS, 3 * DIM, DIM, 0);
    // 2) causal linear self-attention, chunk-parallel
    chunk_sum_kernel<<<BH * NC, 256>>>(qvk, csumK, csumKV);
    prefix_kernel<<<BH, 256>>>(csumK, csumKV, kcp, Sp);
    causal_chunk_kernel<<<BH * NC, 256, CSMEM>>>(qvk, kcp, Sp, attn1);
    // 3) LN1(attn + x) -> fp32 + bf16 split
    ln_res_kernel<<<ROWS, 256>>>(attn1, x, ln1_g, ln1_b, ln1, ln1h, ln1l);
    // 4) kv = memory @ W_kv + b
    gemm_bf<<<dim3((2 * DIM) / 128, ROWS / 128), 256, GB_SMEM>>>(
        mh, ml, wkvh, wkvl, b_kv, kv, nullptr, nullptr, ROWS, 2 * DIM, DIM, 0);
    // 5) q2 = ln1 @ W_q + b
    gemm_bf<<<dim3(DIM / 128, ROWS / 128), 256, GB_SMEM>>>(
        ln1h, ln1l, wqh, wql, b_q, q2, nullptr, nullptr, ROWS, DIM, DIM, 0);
    // 6) column softmax stats of k over memory rows
    col_stats_kernel<<<dim3(DIM / 32, BATCH), 256>>>(kv, colmax, colsum);
    // 7) ctx = softk^T @ v per head (n-chunked + reduce)
    cross_ctx_kernel<<<BH * NCH, 256>>>(kv, colmax, colsum, ctxp);
    ctx_reduce_kernel<<<BH, 256>>>(ctxp, ctx);
    // 8) out2 = softmax(q2) @ ctx, + res, LN2 (fused) -> fp32 + bf16 split
    cross_out_ln2_kernel<<<ROWS, 256>>>(q2, ctx, ln1, ln2_g, ln2_b, ln2, ln2h, ln2l);
    // 9) ff1 = relu(ln2 @ W_ff1 + b) -> bf16 split only
    gemm_bf<<<dim3(FF / 128, ROWS / 128), 256, GB_SMEM>>>(
        ln2h, ln2l, wf1h, wf1l, b_ff1, nullptr, ff1h, ff1l, ROWS, FF, DIM, 1);
    // 10) pre3 = ff1 @ W_ff2 + b
    gemm_bf<<<dim3(DIM / 128, ROWS / 128), 256, GB_SMEM>>>(
        ff1h, ff1l, wf2h, wf2l, b_ff2, pre3, nullptr, nullptr, ROWS, DIM, FF, 0);
    // 11) LN3(pre3 + ln2) -> output
    ln_res_kernel<<<ROWS, 256>>>(pre3, ln2, ln3_g, ln3_b, outp, nullptr, nullptr);
}

// round 9
// speedup vs baseline: 5.2439x; 1.0153x over previous
#include <cuda_runtime.h>
#include <cuda_bf16.h>
#include <math.h>
#include <stdint.h>

// Problem dims
#define BATCH 2
#define SEQN 2048
#define SEQM 2048
#define DIM 512
#define NH 8
#define HE 64
#define FF 2048
#define ROWS (BATCH * SEQN)   // 4096
#define LN_EPS 1e-5f
#define ATTN_EPS 1e-6f

// chunked causal linear attention
#define CC 64
#define NC (SEQN / CC)        // 32
#define BH (BATCH * NH)       // 16
// cross-attn ctx n-split
#define NCH 8
#define CHROWS (SEQM / NCH)   // 256

// ---------------- scratch (device globals; no allocations allowed) ----------
__device__ float g_qvk [ROWS * 3 * DIM];
__device__ float g_attn1[ROWS * DIM];
__device__ float g_ln1 [ROWS * DIM];
__device__ float g_kv  [ROWS * 2 * DIM];
__device__ float g_q2  [ROWS * DIM];
__device__ float g_colmax[BATCH * DIM];
__device__ float g_colsum[BATCH * DIM];
__device__ float g_ctxp[BH * NCH * HE * HE];
__device__ float g_ctx [BH * HE * HE];
__device__ float g_ln2 [ROWS * DIM];
__device__ float g_pre3[ROWS * DIM];
// causal-chunk state
__device__ float g_csumK [BH * NC * HE];
__device__ float g_csumKV[BH * NC * HE * HE];
__device__ float g_kcp   [BH * NC * HE];
__device__ float g_Sp    [BH * NC * HE * HE];
// bf16 hi/lo split tensors
__device__ __nv_bfloat16 g_xh [ROWS * DIM],      g_xl [ROWS * DIM];
__device__ __nv_bfloat16 g_mh [ROWS * DIM],      g_ml [ROWS * DIM];
__device__ __nv_bfloat16 g_ln1h[ROWS * DIM],     g_ln1l[ROWS * DIM];
__device__ __nv_bfloat16 g_ln2h[ROWS * DIM],     g_ln2l[ROWS * DIM];
__device__ __nv_bfloat16 g_ff1h[ROWS * FF],      g_ff1l[ROWS * FF];
__device__ __nv_bfloat16 g_wqvkh[DIM * 3 * DIM], g_wqvkl[DIM * 3 * DIM];
__device__ __nv_bfloat16 g_wkvh [DIM * 2 * DIM], g_wkvl [DIM * 2 * DIM];
__device__ __nv_bfloat16 g_wqh  [DIM * DIM],     g_wql  [DIM * DIM];
__device__ __nv_bfloat16 g_wf1h [DIM * FF],      g_wf1l [DIM * FF];
__device__ __nv_bfloat16 g_wf2h [FF * DIM],      g_wf2l [FF * DIM];

// ---------------- helpers ----------------------------------------------------
__device__ __forceinline__ uint32_t smem_u32(const void* p) {
    uint32_t a;
    asm("{ .reg .u64 t; cvta.to.shared.u64 t, %1; cvt.u32.u64 %0, t; }" : "=r"(a) : "l"(p));
    return a;
}
__device__ __forceinline__ void ldmat_x4(uint32_t& r0, uint32_t& r1, uint32_t& r2, uint32_t& r3,
                                         uint32_t addr) {
    asm volatile("ldmatrix.sync.aligned.m8n8.x4.shared.b16 {%0,%1,%2,%3}, [%4];"
                 : "=r"(r0), "=r"(r1), "=r"(r2), "=r"(r3) : "r"(addr));
}
__device__ __forceinline__ void ldmat_x4t(uint32_t& r0, uint32_t& r1, uint32_t& r2, uint32_t& r3,
                                          uint32_t addr) {
    asm volatile("ldmatrix.sync.aligned.m8n8.x4.trans.shared.b16 {%0,%1,%2,%3}, [%4];"
                 : "=r"(r0), "=r"(r1), "=r"(r2), "=r"(r3) : "r"(addr));
}
__device__ __forceinline__ void mma_bf16(float* c, const uint32_t* a, const uint32_t* b) {
    asm volatile(
        "mma.sync.aligned.m16n8k16.row.col.f32.bf16.bf16.f32 "
        "{%0,%1,%2,%3}, {%4,%5,%6,%7}, {%8,%9}, {%0,%1,%2,%3};"
        : "+f"(c[0]), "+f"(c[1]), "+f"(c[2]), "+f"(c[3])
        : "r"(a[0]), "r"(a[1]), "r"(a[2]), "r"(a[3]), "r"(b[0]), "r"(b[1]));
}
#define CP_ASYNC16(dst, src) \
    asm volatile("cp.async.cg.shared.global [%0], [%1], 16;" :: "r"(dst), "l"(src) : "memory")
#define CP_COMMIT() asm volatile("cp.async.commit_group;" ::: "memory")

// ---------------- fp32 -> bf16 hi/lo split, batched over 7 tensors ----------
#define NSEG 7
struct ConvBatch {
    const float4* src[NSEG];
    uint2* hi[NSEG];
    uint2* lo[NSEG];
    int end[NSEG];   // exclusive prefix ends (in float4 units)
};
__global__ void conv_split_multi(ConvBatch cb)
{
    int i = blockIdx.x * blockDim.x + threadIdx.x;
    if (i >= cb.end[NSEG - 1]) return;
    int s = 0;
    #pragma unroll
    for (int k = 0; k < NSEG - 1; k++) s += (i >= cb.end[k]);
    int j = i - (s ? cb.end[s - 1] : 0);
    float4 f = cb.src[s][j];
    __nv_bfloat16 h0 = __float2bfloat16_rn(f.x), h1 = __float2bfloat16_rn(f.y);
    __nv_bfloat16 h2 = __float2bfloat16_rn(f.z), h3 = __float2bfloat16_rn(f.w);
    __nv_bfloat16 l0 = __float2bfloat16_rn(f.x - __bfloat162float(h0));
    __nv_bfloat16 l1 = __float2bfloat16_rn(f.y - __bfloat162float(h1));
    __nv_bfloat16 l2 = __float2bfloat16_rn(f.z - __bfloat162float(h2));
    __nv_bfloat16 l3 = __float2bfloat16_rn(f.w - __bfloat162float(h3));
    __nv_bfloat162 ha = {h0, h1}, hb = {h2, h3}, la = {l0, l1}, lb = {l2, l3};
    cb.hi[s][j] = make_uint2(*(uint32_t*)&ha, *(uint32_t*)&hb);
    cb.lo[s][j] = make_uint2(*(uint32_t*)&la, *(uint32_t*)&lb);
}

// ================= split-bf16 tensor-core GEMM, 3-stage cp.async =============
// 128x128 CTA tile, BK=32, 8 warps (2x4), warp tile 64x32.
// A/B pre-split bf16 hi/lo. acc += AhBh + AlBh + AhBl (fp32).
#define OFF_AL 10240      // A: 128 rows * 80B
#define OFF_BH 20480
#define OFF_BL 29184      // B: 32 rows * 272B
#define PIPE_STAGE 37888
#define GB_SMEM (3 * PIPE_STAGE)   // 113,664 B

__global__ __launch_bounds__(256)
void gemm_bf(const __nv_bfloat16* __restrict__ Ah, const __nv_bfloat16* __restrict__ Al,
             const __nv_bfloat16* __restrict__ Bh, const __nv_bfloat16* __restrict__ Bl,
             const float* __restrict__ bias, float* __restrict__ Cf,
             __nv_bfloat16* __restrict__ Ch, __nv_bfloat16* __restrict__ Cl,
             int M, int N, int K, int relu)
{
    extern __shared__ char smc[];
    const uint32_t sb = smem_u32(smc);
    const int tid = threadIdx.x;
    const int lane = tid & 31, wid = tid >> 5;
    const int wm = (wid >> 2) * 64;
    const int wn = (wid & 3) * 32;
    const int row0 = blockIdx.y * 128, col0 = blockIdx.x * 128;

    const int a_r = tid >> 2, a_c = (tid & 3) * 16;
    const int a_r2 = (tid + 256) >> 2, a_c2 = ((tid + 256) & 3) * 16;
    const int b_kr = tid >> 4, b_c = (tid & 15) * 16;
    const int b_kr2 = (tid + 256) >> 4, b_c2 = ((tid + 256) & 15) * 16;

    float acc[4][4][4] = {};

    const int la_row  = wm + (lane & 15);
    const int la_colb = (lane >> 4) * 8;
    const int lb_row  = (lane & 7) + ((lane >> 3) & 1) * 8;
    const int lb_colb = wn + (lane >> 4) * 8;

    const int nblk = K / 32;

    #define PREFETCH(kb_, st_) do {                                                              \
        const int kq = (kb_) * 32;                                                               \
        uint32_t st = sb + (st_) * PIPE_STAGE;                                                   \
        CP_ASYNC16(st + a_r * 80 + a_c, Ah + (size_t)(row0 + a_r) * K + kq + a_c / 2);           \
        CP_ASYNC16(st + a_r2 * 80 + a_c2, Ah + (size_t)(row0 + a_r2) * K + kq + a_c2 / 2);       \
        CP_ASYNC16(st + OFF_AL + a_r * 80 + a_c, Al + (size_t)(row0 + a_r) * K + kq + a_c / 2);  \
        CP_ASYNC16(st + OFF_AL + a_r2 * 80 + a_c2, Al + (size_t)(row0 + a_r2) * K + kq + a_c2 / 2);\
        CP_ASYNC16(st + OFF_BH + b_kr * 272 + b_c, Bh + (size_t)(kq + b_kr) * N + col0 + b_c / 2);\
        CP_ASYNC16(st + OFF_BH + b_kr2 * 272 + b_c2, Bh + (size_t)(kq + b_kr2) * N + col0 + b_c2 / 2);\
        CP_ASYNC16(st + OFF_BL + b_kr * 272 + b_c, Bl + (size_t)(kq + b_kr) * N + col0 + b_c / 2);\
        CP_ASYNC16(st + OFF_BL + b_kr2 * 272 + b_c2, Bl + (size_t)(kq + b_kr2) * N + col0 + b_c2 / 2);\
        CP_COMMIT();                                                                             \
    } while (0)

    // prologue: stages 0 and 1
    PREFETCH(0, 0);
    if (nblk > 1) PREFETCH(1, 1);

    for (int kb = 0; kb < nblk; kb++) {
        // wait for stage kb (allow the younger in-flight groups to stay pending)
        if (kb + 2 < nblk)      asm volatile("cp.async.wait_group 1;" ::: "memory");
        else if (kb + 1 < nblk) asm volatile("cp.async.wait_group 1;" ::: "memory");
        else                    asm volatile("cp.async.wait_group 0;" ::: "memory");
        __syncthreads();
        // prefetch kb+2 into stage (kb+2)%3 — safe: all warps finished kb-1 (the
        // last reader of that stage) at the barrier above.
        if (kb + 2 < nblk) PREFETCH(kb + 2, (kb + 2) % 3);

        const uint32_t st = sb + (kb % 3) * PIPE_STAGE;
        #pragma unroll
        for (int ks = 0; ks < 2; ks++) {
            uint32_t ah[4][4], al[4][4], bf[4][2];
            #pragma unroll
            for (int mt = 0; mt < 4; mt++) {
                uint32_t off = (uint32_t)((la_row + mt * 16) * 40 + ks * 16 + la_colb) * 2;
                ldmat_x4(ah[mt][0], ah[mt][1], ah[mt][2], ah[mt][3], st + off);
                ldmat_x4(al[mt][0], al[mt][1], al[mt][2], al[mt][3], st + OFF_AL + off);
            }
            #pragma unroll
            for (int p = 0; p < 2; p++) {
                uint32_t off = (uint32_t)((ks * 16 + lb_row) * 136 + lb_colb + p * 16) * 2;
                ldmat_x4t(bf[p * 2][0], bf[p * 2][1], bf[p * 2 + 1][0], bf[p * 2 + 1][1],
                          st + OFF_BH + off);
            }
            #pragma unroll
            for (int mt = 0; mt < 4; mt++)
                #pragma unroll
                for (int nt = 0; nt < 4; nt++) {
                    mma_bf16(acc[mt][nt], ah[mt], bf[nt]);
                    mma_bf16(acc[mt][nt], al[mt], bf[nt]);
                }
            #pragma unroll
            for (int p = 0; p < 2; p++) {
                uint32_t off = (uint32_t)((ks * 16 + lb_row) * 136 + lb_colb + p * 16) * 2;
                ldmat_x4t(bf[p * 2][0], bf[p * 2][1], bf[p * 2 + 1][0], bf[p * 2 + 1][1],
                          st + OFF_BL + off);
            }
            #pragma unroll
            for (int mt = 0; mt < 4; mt++)
                #pragma unroll
                for (int nt = 0; nt < 4; nt++)
                    mma_bf16(acc[mt][nt], ah[mt], bf[nt]);
        }
    }

    // ---- epilogue ----
    const int r_l = lane >> 2, c_l = (lane & 3) * 2;
    #pragma unroll
    for (int mt = 0; mt < 4; mt++) {
        int row = row0 + wm + mt * 16 + r_l;
        #pragma unroll
        for (int nt = 0; nt < 4; nt++) {
            int col = col0 + wn + nt * 8 + c_l;
            float b0 = bias[col], b1 = bias[col + 1];
            float v00 = acc[mt][nt][0] + b0, v01 = acc[mt][nt][1] + b1;
            float v10 = acc[mt][nt][2] + b0, v11 = acc[mt][nt][3] + b1;
            if (relu) {
                v00 = fmaxf(v00, 0.f); v01 = fmaxf(v01, 0.f);
                v10 = fmaxf(v10, 0.f); v11 = fmaxf(v11, 0.f);
            }
            if (Cf) {
                *(float2*)(Cf + (size_t)row * N + col) = make_float2(v00, v01);
                *(float2*)(Cf + (size_t)(row + 8) * N + col) = make_float2(v10, v11);
            }
            if (Ch) {
                __nv_bfloat16 h00 = __float2bfloat16_rn(v00), h01 = __float2bfloat16_rn(v01);
                __nv_bfloat16 h10 = __float2bfloat16_rn(v10), h11 = __float2bfloat16_rn(v11);
                __nv_bfloat162 hp0 = {h00, h01}, hp1 = {h10, h11};
                __nv_bfloat162 lp0 = {__float2bfloat16_rn(v00 - __bfloat162float(h00)),
                                      __float2bfloat16_rn(v01 - __bfloat162float(h01))};
                __nv_bfloat162 lp1 = {__float2bfloat16_rn(v10 - __bfloat162float(h10)),
                                      __float2bfloat16_rn(v11 - __bfloat162float(h11))};
                *(__nv_bfloat162*)(Ch + (size_t)row * N + col) = hp0;
                *(__nv_bfloat162*)(Ch + (size_t)(row + 8) * N + col) = hp1;
                *(__nv_bfloat162*)(Cl + (size_t)row * N + col) = lp0;
                *(__nv_bfloat162*)(Cl + (size_t)(row + 8) * N + col) = lp1;
            }
        }
    }
}

// ---------------- causal chunk phase 1: per-chunk sums ----------------------
__global__ __launch_bounds__(256)
void chunk_sum_kernel(const float* __restrict__ qvk,
                      float* __restrict__ csumK, float* __restrict__ csumKV)
{
    const int blk = blockIdx.x;
    const int bh = blk / NC, c = blk % NC;
    const int b = bh >> 3, h = bh & 7;
    const int tid = threadIdx.x;

    __shared__ __align__(16) float Ks[CC][68];
    __shared__ __align__(16) float Vs[CC][68];

    const float* base = qvk + (size_t)b * SEQN * (3 * DIM) + (size_t)c * CC * (3 * DIM) + h * HE;
    #pragma unroll
    for (int i = tid; i < CC * 16; i += 256) {
        int r = i >> 4;
        int col = (i & 15) * 4;
        const float* rp = base + (size_t)r * (3 * DIM);
        float4 kk = *(const float4*)(rp + 2 * DIM + col);
        float4 vv = *(const float4*)(rp + DIM + col);
        Ks[r][col + 0] = expf(kk.x); Ks[r][col + 1] = expf(kk.y);
        Ks[r][col + 2] = expf(kk.z); Ks[r][col + 3] = expf(kk.w);
        *(float4*)&Vs[r][col] = vv;
    }
    __syncthreads();

    const int ty = tid >> 4, tx = tid & 15;
    const int d0 = ty * 4, e0 = tx * 4;
    float acc[4][4] = {};
    #pragma unroll 8
    for (int n = 0; n < CC; n++) {
        float4 a = *(const float4*)&Ks[n][d0];
        float4 bb = *(const float4*)&Vs[n][e0];
        float av[4] = {a.x, a.y, a.z, a.w};
        float bv[4] = {bb.x, bb.y, bb.z, bb.w};
        #pragma unroll
        for (int i = 0; i < 4; i++)
            #pragma unroll
            for (int j = 0; j < 4; j++)
                acc[i][j] += av[i] * bv[j];
    }
    float* outKV = csumKV + ((size_t)bh * NC + c) * (HE * HE);
    #pragma unroll
    for (int i = 0; i < 4; i++) {
        float4 o = {acc[i][0], acc[i][1], acc[i][2], acc[i][3]};
        *(float4*)(outKV + (d0 + i) * HE + e0) = o;
    }
    if (tid < HE) {
        float s = 0.f;
        #pragma unroll 8
        for (int n = 0; n < CC; n++) s += Ks[n][tid];
        csumK[((size_t)bh * NC + c) * HE + tid] = s;
    }
}

// ---------------- causal chunk phase 2: exclusive prefix over chunks --------
__global__ __launch_bounds__(256)
void prefix_kernel(const float* __restrict__ csumK, const float* __restrict__ csumKV,
                   float* __restrict__ kcp, float* __restrict__ Sp)
{
    const int bh = blockIdx.x;
    const int tid = threadIdx.x;
    float4 run[4];
    #pragma unroll
    for (int i = 0; i < 4; i++) run[i] = make_float4(0.f, 0.f, 0.f, 0.f);
    for (int c = 0; c < NC; c++) {
        size_t base = ((size_t)bh * NC + c) * (HE * HE) + (size_t)tid * 16;
        float4* dst = (float4*)(Sp + base);
        const float4* src = (const float4*)(csumKV + base);
        #pragma unroll
        for (int i = 0; i < 4; i++) {
            dst[i] = run[i];
            float4 s = src[i];
            run[i].x += s.x; run[i].y += s.y; run[i].z += s.z; run[i].w += s.w;
        }
    }
    if (tid < HE) {
        float rk = 0.f;
        for (int c = 0; c < NC; c++) {
            size_t o = ((size_t)bh * NC + c) * HE + tid;
            kcp[o] = rk;
            rk += csumK[o];
        }
    }
}

// ---------------- causal chunk phase 3: per-chunk output --------------------
__global__ __launch_bounds__(256)
void causal_chunk_kernel(const float* __restrict__ qvk,
                         const float* __restrict__ kcp, const float* __restrict__ Sp,
                         float* __restrict__ out)
{
    extern __shared__ __align__(16) float sm[];
    float (*TsT)[68] = (float(*)[68])sm;
    float (*KsT)[68] = TsT + 64;
    float (*AT)[68]  = KsT + 64;
    float (*Vs)[68]  = AT + 64;
    float (*SpS)[68] = Vs + 64;
    float* kcpe = (float*)(SpS + 64);
    float* den  = kcpe + 64;

    const int blk = blockIdx.x;
    const int bh = blk / NC, c = blk % NC;
    const int b = bh >> 3, h = bh & 7;
    const int tid = threadIdx.x;
    const float* base = qvk + (size_t)b * SEQN * (3 * DIM) + (size_t)c * CC * (3 * DIM) + h * HE;

    {
        int r = tid >> 2;
        int g = tid & 3;
        const float* rp = base + (size_t)r * (3 * DIM) + g * 16;
        float qv[16];
        float m = -1e30f;
        #pragma unroll
        for (int j = 0; j < 16; j++) { qv[j] = rp[j]; m = fmaxf(m, qv[j]); }
        m = fmaxf(m, __shfl_xor_sync(0xffffffffu, m, 1));
        m = fmaxf(m, __shfl_xor_sync(0xffffffffu, m, 2));
        #pragma unroll
        for (int j = 0; j < 16; j++) TsT[g * 16 + j][r] = expf(qv[j] - m);
        const float* rpk = rp + 2 * DIM;
        #pragma unroll
        for (int j = 0; j < 16; j++) KsT[g * 16 + j][r] = expf(rpk[j]);
    }
    #pragma unroll
    for (int i = tid; i < CC * 16; i += 256) {
        int r = i >> 4, col = (i & 15) * 4;
        *(float4*)&Vs[r][col] = *(const float4*)(base + (size_t)r * (3 * DIM) + DIM + col);
    }
    const float* spb = Sp + ((size_t)bh * NC + c) * (HE * HE);
    #pragma unroll
    for (int i = tid; i < HE * 16; i += 256) {
        int r = i >> 4, col = (i & 15) * 4;
        *(float4*)&SpS[r][col] = *(const float4*)(spb + r * HE + col);
    }
    if (tid < HE) kcpe[tid] = kcp[((size_t)bh * NC + c) * HE + tid] + ATTN_EPS;
    __syncthreads();

    const int ty = tid >> 4, tx = tid & 15;
    const int t0 = ty * 4, s0 = tx * 4;

    {
        float acc[4][4] = {};
        #pragma unroll 8
        for (int d = 0; d < HE; d++) {
            float4 a = *(const float4*)&TsT[d][t0];
            float4 bb = *(const float4*)&KsT[d][s0];
            float av[4] = {a.x, a.y, a.z, a.w};
            float bv[4] = {bb.x, bb.y, bb.z, bb.w};
            #pragma unroll
            for (int i = 0; i < 4; i++)
                #pragma unroll
                for (int j = 0; j < 4; j++)
                    acc[i][j] += av[i] * bv[j];
        }
        #pragma unroll
        for (int i = 0; i < 4; i++)
            #pragma unroll
            for (int j = 0; j < 4; j++) {
                int t = t0 + i, s = s0 + j;
                AT[s][t] = (s <= t) ? acc[i][j] : 0.f;
            }
    }
    __syncthreads();

    if (tid < 128) {
        int t = tid >> 1, half = tid & 1;
        float sd = 0.f;
        int lo = half * 32;
        #pragma unroll 8
        for (int s = lo; s < lo + 32; s++) sd += AT[s][t];
        #pragma unroll 8
        for (int d = lo; d < lo + 32; d++) sd += TsT[d][t] * kcpe[d];
        sd += __shfl_xor_sync(0xffffffffu, sd, 1);
        if (!half) den[t] = 1.0f / sd;
    }
    __syncthreads();

    {
        const int e0 = tx * 4;
        float o[4][4] = {};
        #pragma unroll 8
        for (int s = 0; s < CC; s++) {
            float4 a = *(const float4*)&AT[s][t0];
            float4 bb = *(const float4*)&Vs[s][e0];
            float av[4] = {a.x, a.y, a.z, a.w};
            float bv[4] = {bb.x, bb.y, bb.z, bb.w};
            #pragma unroll
            for (int i = 0; i < 4; i++)
                #pragma unroll
                for (int j = 0; j < 4; j++)
                    o[i][j] += av[i] * bv[j];
        }
        #pragma unroll 8
        for (int d = 0; d < HE; d++) {
            float4 a = *(const float4*)&TsT[d][t0];
            float4 bb = *(const float4*)&SpS[d][e0];
            float av[4] = {a.x, a.y, a.z, a.w};
            float bv[4] = {bb.x, bb.y, bb.z, bb.w};
            #pragma unroll
            for (int i = 0; i < 4; i++)
                #pragma unroll
                for (int j = 0; j < 4; j++)
                    o[i][j] += av[i] * bv[j];
        }
        float* ob = out + (size_t)b * SEQN * DIM + (size_t)c * CC * DIM + h * HE;
        #pragma unroll
        for (int i = 0; i < 4; i++) {
            float rcp = den[t0 + i];
            float4 ov = {o[i][0] * rcp, o[i][1] * rcp, o[i][2] * rcp, o[i][3] * rcp};
            *(float4*)(ob + (size_t)(t0 + i) * DIM + e0) = ov;
        }
    }
}

// ---------------- residual + layernorm (+ optional bf16 hi/lo out) -----------
__global__ void ln_res_kernel(const float* __restrict__ a, const float* __restrict__ r,
                              const float* __restrict__ g, const float* __restrict__ beta,
                              float* __restrict__ out,
                              __nv_bfloat16* __restrict__ oh, __nv_bfloat16* __restrict__ ol)
{
    const int row = blockIdx.x;
    const int tid = threadIdx.x;
    const int w = tid >> 5, lane = tid & 31;
    __shared__ float red[16];

    float pre[2], sum = 0.f, sumsq = 0.f;
    #pragma unroll
    for (int it = 0; it < 2; it++) {
        int o = tid + it * 256;
        float p = a[(size_t)row * DIM + o] + r[(size_t)row * DIM + o];
        pre[it] = p; sum += p; sumsq += p * p;
    }
    #pragma unroll
    for (int o = 16; o > 0; o >>= 1) {
        sum   += __shfl_xor_sync(0xffffffffu, sum, o);
        sumsq += __shfl_xor_sync(0xffffffffu, sumsq, o);
    }
    if (lane == 0) { red[w] = sum; red[8 + w] = sumsq; }
    __syncthreads();
    if (tid == 0) {
        float s = 0.f, q = 0.f;
        #pragma unroll
        for (int i = 0; i < 8; i++) { s += red[i]; q += red[8 + i]; }
        float mu = s / (float)DIM;
        float var = q / (float)DIM - mu * mu;
        red[0] = mu; red[1] = rsqrtf(var + LN_EPS);
    }
    __syncthreads();
    float mu = red[0], rstd = red[1];
    #pragma unroll
    for (int it = 0; it < 2; it++) {
        int o = tid + it * 256;
        float v = (pre[it] - mu) * rstd * g[o] + beta[o];
        out[(size_t)row * DIM + o] = v;
        if (oh) {
            __nv_bfloat16 h = __float2bfloat16_rn(v);
            oh[(size_t)row * DIM + o] = h;
            ol[(size_t)row * DIM + o] = __float2bfloat16_rn(v - __bfloat162float(h));
        }
    }
}

// ---------------- cross-attn: per-column softmax stats -----------------------
__global__ void col_stats_kernel(const float* __restrict__ kv,
                                 float* __restrict__ colmax, float* __restrict__ colsum)
{
    const int b = blockIdx.y;
    const int lane = threadIdx.x & 31;
    const int r = threadIdx.x >> 5;
    const int d = blockIdx.x * 32 + lane;
    const float* base = kv + (size_t)b * SEQM * (2 * DIM) + d;

    __shared__ float sm[8][32];
    __shared__ float cm[32];

    float m = -1e30f;
    for (int n = r; n < SEQM; n += 8) m = fmaxf(m, base[(size_t)n * (2 * DIM)]);
    sm[r][lane] = m;
    __syncthreads();
    if (threadIdx.x < 32) {
        float mm = sm[0][threadIdx.x];
        #pragma unroll
        for (int i = 1; i < 8; i++) mm = fmaxf(mm, sm[i][threadIdx.x]);
        cm[threadIdx.x] = mm;
        colmax[b * DIM + blockIdx.x * 32 + threadIdx.x] = mm;
    }
    __syncthreads();
    float s = 0.f;
    float mref = cm[lane];
    for (int n = r; n < SEQM; n += 8) s += expf(base[(size_t)n * (2 * DIM)] - mref);
    sm[r][lane] = s;
    __syncthreads();
    if (threadIdx.x < 32) {
        float ss = sm[0][threadIdx.x];
        #pragma unroll
        for (int i = 1; i < 8; i++) ss += sm[i][threadIdx.x];
        colsum[b * DIM + blockIdx.x * 32 + threadIdx.x] = ss;
    }
}

// ---------------- cross-attn: partial ctx over n-chunks ----------------------
__global__ void cross_ctx_kernel(const float* __restrict__ kv,
                                 const float* __restrict__ colmax, const float* __restrict__ colsum,
                                 float* __restrict__ ctxp)
{
    const int blk = blockIdx.x;
    const int bh = blk / NCH, ch = blk % NCH;
    const int b = bh >> 3, h = bh & 7;
    const int tid = threadIdx.x;
    const int tx = tid & 15, ty = tid >> 4;

    __shared__ __align__(16) float Ks[32][64];
    __shared__ __align__(16) float Vs[32][64];
    __shared__ float cm[64], ci[64];

    if (tid < 64) {
        cm[tid] = colmax[b * DIM + h * HE + tid];
        ci[tid] = 1.0f / colsum[b * DIM + h * HE + tid];
    }
    __syncthreads();

    float acc[4][4] = {};
    const float* base = kv + (size_t)b * SEQM * (2 * DIM) + h * HE;
    const int n_lo = ch * CHROWS, n_hi = n_lo + CHROWS;
    for (int n0 = n_lo; n0 < n_hi; n0 += 32) {
        #pragma unroll
        for (int it = 0; it < 2; it++) {
            int f4 = tid + it * 256;
            int r = f4 >> 4;
            int c = (f4 & 15) * 4;
            const float* rp = base + (size_t)(n0 + r) * (2 * DIM);
            float4 kk = *(const float4*)(rp + c);
            float4 vv = *(const float4*)(rp + DIM + c);
            Ks[r][c + 0] = expf(kk.x - cm[c + 0]) * ci[c + 0];
            Ks[r][c + 1] = expf(kk.y - cm[c + 1]) * ci[c + 1];
            Ks[r][c + 2] = expf(kk.z - cm[c + 2]) * ci[c + 2];
            Ks[r][c + 3] = expf(kk.w - cm[c + 3]) * ci[c + 3];
            *(float4*)&Vs[r][c] = vv;
        }
        __syncthreads();
        #pragma unroll
        for (int r = 0; r < 32; r++) {
            float4 av = *(const float4*)&Ks[r][ty * 4];
            float4 bv = *(const float4*)&Vs[r][tx * 4];
            float a[4] = {av.x, av.y, av.z, av.w};
            float bb[4] = {bv.x, bv.y, bv.z, bv.w};
            #pragma unroll
            for (int i = 0; i < 4; i++)
                #pragma unroll
                for (int j = 0; j < 4; j++)
                    acc[i][j] += a[i] * bb[j];
        }
        __syncthreads();
    }
    float* cb = ctxp + (size_t)blk * (HE * HE);
    #pragma unroll
    for (int i = 0; i < 4; i++)
        #pragma unroll
        for (int j = 0; j < 4; j++)
            cb[(ty * 4 + i) * HE + tx * 4 + j] = acc[i][j];
}

__global__ void ctx_reduce_kernel(const float* __restrict__ ctxp, float* __restrict__ ctx)
{
    const int bh = blockIdx.x;
    const int tid = threadIdx.x;
    size_t o = (size_t)tid * 16;
    float4 s[4];
    #pragma unroll
    for (int i = 0; i < 4; i++) s[i] = make_float4(0.f, 0.f, 0.f, 0.f);
    #pragma unroll
    for (int ch = 0; ch < NCH; ch++) {
        const float4* src = (const float4*)(ctxp + ((size_t)bh * NCH + ch) * (HE * HE) + o);
        #pragma unroll
        for (int i = 0; i < 4; i++) {
            float4 v = src[i];
            s[i].x += v.x; s[i].y += v.y; s[i].z += v.z; s[i].w += v.w;
        }
    }
    float4* dst = (float4*)(ctx + (size_t)bh * (HE * HE) + o);
    #pragma unroll
    for (int i = 0; i < 4; i++) dst[i] = s[i];
}

// ---------------- cross-attn output + residual + LN2 (+ bf16 out) -----------
__global__ void cross_out_ln2_kernel(const float* __restrict__ q2, const float* __restrict__ ctx,
                                     const float* __restrict__ res, const float* __restrict__ g,
                                     const float* __restrict__ beta, float* __restrict__ out,
                                     __nv_bfloat16* __restrict__ oh, __nv_bfloat16* __restrict__ ol)
{
    const int row = blockIdx.x;
    const int b = row >> 11;
    const int tid = threadIdx.x;
    const int w = tid >> 5, lane = tid & 31;

    __shared__ float qs_s[DIM];
    __shared__ float red[16];

    const float* qr = q2 + (size_t)row * DIM;
    {
        float a0 = qr[w * HE + lane], a1 = qr[w * HE + 32 + lane];
        float m = fmaxf(a0, a1);
        #pragma unroll
        for (int o = 16; o > 0; o >>= 1) m = fmaxf(m, __shfl_xor_sync(0xffffffffu, m, o));
        float t0 = expf(a0 - m), t1 = expf(a1 - m);
        float s = t0 + t1;
        #pragma unroll
        for (int o = 16; o > 0; o >>= 1) s += __shfl_xor_sync(0xffffffffu, s, o);
        float sc = 0.125f / s;
        qs_s[w * HE + lane] = t0 * sc;
        qs_s[w * HE + 32 + lane] = t1 * sc;
    }
    __syncthreads();

    float pre[2], sum = 0.f, sumsq = 0.f;
    #pragma unroll
    for (int it = 0; it < 2; it++) {
        int o = tid + it * 256;
        int h = o >> 6, e = o & 63;
        const float* cb = ctx + ((size_t)(b * NH + h)) * (HE * HE) + e;
        const float* qh = qs_s + h * HE;
        float acc = 0.f;
        #pragma unroll 8
        for (int d = 0; d < HE; d++) acc += qh[d] * cb[d * HE];
        float p = acc + res[(size_t)row * DIM + o];
        pre[it] = p; sum += p; sumsq += p * p;
    }
    #pragma unroll
    for (int o = 16; o > 0; o >>= 1) {
        sum   += __shfl_xor_sync(0xffffffffu, sum, o);
        sumsq += __shfl_xor_sync(0xffffffffu, sumsq, o);
    }
    if (lane == 0) { red[w] = sum; red[8 + w] = sumsq; }
    __syncthreads();
    if (tid == 0) {
        float s = 0.f, q = 0.f;
        #pragma unroll
        for (int i = 0; i < 8; i++) { s += red[i]; q += red[8 + i]; }
        float mu = s / (float)DIM;
        float var = q / (float)DIM - mu * mu;
        red[0] = mu; red[1] = rsqrtf(var + LN_EPS);
    }
    __syncthreads();
    float mu = red[0], rstd = red[1];
    #pragma unroll
    for (int it = 0; it < 2; it++) {
        int o = tid + it * 256;
        float v = (pre[it] - mu) * rstd * g[o] + beta[o];
        out[(size_t)row * DIM + o] = v;
        __nv_bfloat16 h = __float2bfloat16_rn(v);
        oh[(size_t)row * DIM + o] = h;
        ol[(size_t)row * DIM + o] = __float2bfloat16_rn(v - __bfloat162float(h));
    }
}

// ---------------- host launch ------------------------------------------------
extern "C" void kernel_launch(void* const* d_in, const int* in_sizes, int n_in,
                              void* d_out, int out_size)
{
    const float* x      = (const float*)d_in[0];
    const float* memory = (const float*)d_in[1];
    const float* W_qvk  = (const float*)d_in[2];
    const float* b_qvk  = (const float*)d_in[3];
    const float* W_kv   = (const float*)d_in[4];
    const float* b_kv   = (const float*)d_in[5];
    const float* W_q    = (const float*)d_in[6];
    const float* b_q    = (const float*)d_in[7];
    const float* W_ff1  = (const float*)d_in[8];
    const float* b_ff1  = (const float*)d_in[9];
    const float* W_ff2  = (const float*)d_in[10];
    const float* b_ff2  = (const float*)d_in[11];
    const float* ln1_g  = (const float*)d_in[12];
    const float* ln1_b  = (const float*)d_in[13];
    const float* ln2_g  = (const float*)d_in[14];
    const float* ln2_b  = (const float*)d_in[15];
    const float* ln3_g  = (const float*)d_in[16];
    const float* ln3_b  = (const float*)d_in[17];
    float* outp = (float*)d_out;

    float *qvk, *attn1, *ln1, *kv, *q2, *colmax, *colsum, *ctxp, *ctx, *ln2, *pre3;
    float *csumK, *csumKV, *kcp, *Sp;
    __nv_bfloat16 *xh, *xl, *mh, *ml, *ln1h, *ln1l, *ln2h, *ln2l, *ff1h, *ff1l;
    __nv_bfloat16 *wqvkh, *wqvkl, *wkvh, *wkvl, *wqh, *wql, *wf1h, *wf1l, *wf2h, *wf2l;
    cudaGetSymbolAddress((void**)&qvk,   g_qvk);
    cudaGetSymbolAddress((void**)&attn1, g_attn1);
    cudaGetSymbolAddress((void**)&ln1,   g_ln1);
    cudaGetSymbolAddress((void**)&kv,    g_kv);
    cudaGetSymbolAddress((void**)&q2,    g_q2);
    cudaGetSymbolAddress((void**)&colmax,g_colmax);
    cudaGetSymbolAddress((void**)&colsum,g_colsum);
    cudaGetSymbolAddress((void**)&ctxp,  g_ctxp);
    cudaGetSymbolAddress((void**)&ctx,   g_ctx);
    cudaGetSymbolAddress((void**)&ln2,   g_ln2);
    cudaGetSymbolAddress((void**)&pre3,  g_pre3);
    cudaGetSymbolAddress((void**)&csumK, g_csumK);
    cudaGetSymbolAddress((void**)&csumKV,g_csumKV);
    cudaGetSymbolAddress((void**)&kcp,   g_kcp);
    cudaGetSymbolAddress((void**)&Sp,    g_Sp);
    cudaGetSymbolAddress((void**)&xh,   g_xh);   cudaGetSymbolAddress((void**)&xl,   g_xl);
    cudaGetSymbolAddress((void**)&mh,   g_mh);   cudaGetSymbolAddress((void**)&ml,   g_ml);
    cudaGetSymbolAddress((void**)&ln1h, g_ln1h); cudaGetSymbolAddress((void**)&ln1l, g_ln1l);
    cudaGetSymbolAddress((void**)&ln2h, g_ln2h); cudaGetSymbolAddress((void**)&ln2l, g_ln2l);
    cudaGetSymbolAddress((void**)&ff1h, g_ff1h); cudaGetSymbolAddress((void**)&ff1l, g_ff1l);
    cudaGetSymbolAddress((void**)&wqvkh,g_wqvkh);cudaGetSymbolAddress((void**)&wqvkl,g_wqvkl);
    cudaGetSymbolAddress((void**)&wkvh, g_wkvh); cudaGetSymbolAddress((void**)&wkvl, g_wkvl);
    cudaGetSymbolAddress((void**)&wqh,  g_wqh);  cudaGetSymbolAddress((void**)&wql,  g_wql);
    cudaGetSymbolAddress((void**)&wf1h, g_wf1h); cudaGetSymbolAddress((void**)&wf1l, g_wf1l);
    cudaGetSymbolAddress((void**)&wf2h, g_wf2h); cudaGetSymbolAddress((void**)&wf2l, g_wf2l);

    const int CSMEM = (5 * 64 * 68 + 128) * (int)sizeof(float);
    cudaFuncSetAttribute(causal_chunk_kernel, cudaFuncAttributeMaxDynamicSharedMemorySize, CSMEM);
    cudaFuncSetAttribute(gemm_bf, cudaFuncAttributeMaxDynamicSharedMemorySize, GB_SMEM);

    // 0) one batched precision-split conversion for all inputs + weights
    {
        ConvBatch cb;
        const float* srcs[NSEG] = {x, memory, W_qvk, W_kv, W_q, W_ff1, W_ff2};
        __nv_bfloat16* his[NSEG] = {xh, mh, wqvkh, wkvh, wqh, wf1h, wf2h};
        __nv_bfloat16* los[NSEG] = {xl, ml, wqvkl, wkvl, wql, wf1l, wf2l};
        int ns[NSEG] = {ROWS * DIM / 4, ROWS * DIM / 4, DIM * 3 * DIM / 4,
                        DIM * 2 * DIM / 4, DIM * DIM / 4, DIM * FF / 4, FF * DIM / 4};
        int acc_n = 0;
        for (int s = 0; s < NSEG; s++) {
            cb.src[s] = (const float4*)srcs[s];
            cb.hi[s] = (uint2*)his[s];
            cb.lo[s] = (uint2*)los[s];
            acc_n += ns[s];
            cb.end[s] = acc_n;
        }
        conv_split_multi<<<(acc_n + 255) / 256, 256>>>(cb);
    }

    // 1) qvk = x @ W_qvk + b
    gemm_bf<<<dim3((3 * DIM) / 128, ROWS / 128), 256, GB_SMEM>>>(
        xh, xl, wqvkh, wqvkl, b_qvk, qvk, nullptr, nullptr, ROWS, 3 * DIM, DIM, 0);
    // 2) causal linear self-attention, chunk-parallel
    chunk_sum_kernel<<<BH * NC, 256>>>(qvk, csumK, csumKV);
    prefix_kernel<<<BH, 256>>>(csumK, csumKV, kcp, Sp);
    causal_chunk_kernel<<<BH * NC, 256, CSMEM>>>(qvk, kcp, Sp, attn1);
    // 3) LN1(attn + x) -> fp32 + bf16 split
    ln_res_kernel<<<ROWS, 256>>>(attn1, x, ln1_g, ln1_b, ln1, ln1h, ln1l);
    // 4) kv = memory @ W_kv + b
    gemm_bf<<<dim3((2 * DIM) / 128, ROWS / 128), 256, GB_SMEM>>>(
        mh, ml, wkvh, wkvl, b_kv, kv, nullptr, nullptr, ROWS, 2 * DIM, DIM, 0);
    // 5) q2 = ln1 @ W_q + b
    gemm_bf<<<dim3(DIM / 128, ROWS / 128), 256, GB_SMEM>>>(
        ln1h, ln1l, wqh, wql, b_q, q2, nullptr, nullptr, ROWS, DIM, DIM, 0);
    // 6) column softmax stats of k over memory rows
    col_stats_kernel<<<dim3(DIM / 32, BATCH), 256>>>(kv, colmax, colsum);
    // 7) ctx = softk^T @ v per head (n-chunked + reduce)
    cross_ctx_kernel<<<BH * NCH, 256>>>(kv, colmax, colsum, ctxp);
    ctx_reduce_kernel<<<BH, 256>>>(ctxp, ctx);
    // 8) out2 = softmax(q2) @ ctx, + res, LN2 (fused) -> fp32 + bf16 split
    cross_out_ln2_kernel<<<ROWS, 256>>>(q2, ctx, ln1, ln2_g, ln2_b, ln2, ln2h, ln2l);
    // 9) ff1 = relu(ln2 @ W_ff1 + b) -> bf16 split only
    gemm_bf<<<dim3(FF / 128, ROWS / 128), 256, GB_SMEM>>>(
        ln2h, ln2l, wf1h, wf1l, b_ff1, nullptr, ff1h, ff1l, ROWS, FF, DIM, 1);
    // 10) pre3 = ff1 @ W_ff2 + b
    gemm_bf<<<dim3(DIM / 128, ROWS / 128), 256, GB_SMEM>>>(
        ff1h, ff1l, wf2h, wf2l, b_ff2, pre3, nullptr, nullptr, ROWS, DIM, FF, 0);
    // 11) LN3(pre3 + ln2) -> output
    ln_res_kernel<<<ROWS, 256>>>(pre3, ln2, ln3_g, ln3_b, outp, nullptr, nullptr);
}

// round 11
// speedup vs baseline: 7.0842x; 1.3509x over previous
#include <cuda_runtime.h>
#include <cuda_bf16.h>
#include <cuda_fp16.h>
#include <math.h>
#include <stdint.h>

// Problem dims
#define BATCH 2
#define SEQN 2048
#define SEQM 2048
#define DIM 512
#define NH 8
#define HE 64
#define FF 2048
#define ROWS (BATCH * SEQN)   // 4096
#define LN_EPS 1e-5f
#define ATTN_EPS 1e-6f

// chunked causal linear attention
#define CC 64
#define NC (SEQN / CC)        // 32
#define BH (BATCH * NH)       // 16
// cross-attn ctx n-split
#define NCH 8
#define CHROWS (SEQM / NCH)   // 256

// ---------------- scratch (device globals; no allocations allowed) ----------
__device__ float g_qvk [ROWS * 3 * DIM];
__device__ float g_attn1[ROWS * DIM];
__device__ float g_ln1 [ROWS * DIM];
__device__ float g_kv  [ROWS * 2 * DIM];
__device__ float g_q2  [ROWS * DIM];
__device__ float g_colmax[BATCH * DIM];
__device__ float g_colsum[BATCH * DIM];
__device__ float g_ctxp[BH * NCH * HE * HE];
__device__ float g_ctx [BH * HE * HE];
__device__ float g_ln2 [ROWS * DIM];
__device__ float g_pre3[ROWS * DIM];
// causal-chunk state
__device__ float g_csumK [BH * NC * HE];
__device__ float g_csumKV[BH * NC * HE * HE];
__device__ float g_kcp   [BH * NC * HE];
__device__ float g_Sp    [BH * NC * HE * HE];
// fp16 hi/lo split tensors (A operands: hi+lo; B/weights: hi only)
__device__ __half g_xh [ROWS * DIM],      g_xl [ROWS * DIM];
__device__ __half g_mh [ROWS * DIM],      g_ml [ROWS * DIM];
__device__ __half g_ln1h[ROWS * DIM],     g_ln1l[ROWS * DIM];
__device__ __half g_ln2h[ROWS * DIM],     g_ln2l[ROWS * DIM];
__device__ __half g_ff1h[ROWS * FF],      g_ff1l[ROWS * FF];
__device__ __half g_wqvkh[DIM * 3 * DIM];
__device__ __half g_wkvh [DIM * 2 * DIM];
__device__ __half g_wqh  [DIM * DIM];
__device__ __half g_wf1h [DIM * FF];
__device__ __half g_wf2h [FF * DIM];

// ---------------- helpers ----------------------------------------------------
__device__ __forceinline__ uint32_t smem_u32(const void* p) {
    uint32_t a;
    asm("{ .reg .u64 t; cvta.to.shared.u64 t, %1; cvt.u32.u64 %0, t; }" : "=r"(a) : "l"(p));
    return a;
}
__device__ __forceinline__ void ldmat_x4(uint32_t& r0, uint32_t& r1, uint32_t& r2, uint32_t& r3,
                                         uint32_t addr) {
    asm volatile("ldmatrix.sync.aligned.m8n8.x4.shared.b16 {%0,%1,%2,%3}, [%4];"
                 : "=r"(r0), "=r"(r1), "=r"(r2), "=r"(r3) : "r"(addr));
}
__device__ __forceinline__ void ldmat_x4t(uint32_t& r0, uint32_t& r1, uint32_t& r2, uint32_t& r3,
                                          uint32_t addr) {
    asm volatile("ldmatrix.sync.aligned.m8n8.x4.trans.shared.b16 {%0,%1,%2,%3}, [%4];"
                 : "=r"(r0), "=r"(r1), "=r"(r2), "=r"(r3) : "r"(addr));
}
__device__ __forceinline__ void mma_f16(float* c, const uint32_t* a, const uint32_t* b) {
    asm volatile(
        "mma.sync.aligned.m16n8k16.row.col.f32.f16.f16.f32 "
        "{%0,%1,%2,%3}, {%4,%5,%6,%7}, {%8,%9}, {%0,%1,%2,%3};"
        : "+f"(c[0]), "+f"(c[1]), "+f"(c[2]), "+f"(c[3])
        : "r"(a[0]), "r"(a[1]), "r"(a[2]), "r"(a[3]), "r"(b[0]), "r"(b[1]));
}
#define CP_ASYNC16(dst, src) \
    asm volatile("cp.async.cg.shared.global [%0], [%1], 16;" :: "r"(dst), "l"(src) : "memory")
#define CP_COMMIT() asm volatile("cp.async.commit_group;" ::: "memory")

// ---------------- fp32 -> fp16 hi/lo split, batched over 7 tensors ----------
#define NSEG 7
struct ConvBatch {
    const float4* src[NSEG];
    uint2* hi[NSEG];
    uint2* lo[NSEG];      // null -> hi-only (weights)
    int end[NSEG];        // exclusive prefix ends (float4 units)
};
__global__ void conv_split_multi(ConvBatch cb)
{
    int i = blockIdx.x * blockDim.x + threadIdx.x;
    if (i >= cb.end[NSEG - 1]) return;
    int s = 0;
    #pragma unroll
    for (int k = 0; k < NSEG - 1; k++) s += (i >= cb.end[k]);
    int j = i - (s ? cb.end[s - 1] : 0);
    float4 f = cb.src[s][j];
    __half h0 = __float2half_rn(f.x), h1 = __float2half_rn(f.y);
    __half h2 = __float2half_rn(f.z), h3 = __float2half_rn(f.w);
    __half2 ha = {h0, h1}, hb = {h2, h3};
    cb.hi[s][j] = make_uint2(*(uint32_t*)&ha, *(uint32_t*)&hb);
    if (cb.lo[s]) {
        __half2 la = {__float2half_rn(f.x - __half2float(h0)),
                      __float2half_rn(f.y - __half2float(h1))};
        __half2 lb = {__float2half_rn(f.z - __half2float(h2)),
                      __float2half_rn(f.w - __half2float(h3))};
        cb.lo[s][j] = make_uint2(*(uint32_t*)&la, *(uint32_t*)&lb);
    }
}

// ================= split-fp16 tensor-core GEMM, 3-stage cp.async =============
// 128x128 CTA tile, BK=32, 8 warps (2x4), warp tile 64x32.
// A = Ah + Al (fp16 pair), B = Bh (single fp16). acc += AhBh + AlBh (fp32).
#define OFF_AL 10240      // A: 128 rows * 80B
#define OFF_BH 20480      // B: 32 rows * 272B
#define PIPE_STAGE 29184
#define GB_SMEM (3 * PIPE_STAGE)   // 87,552 B

__global__ __launch_bounds__(256)
void gemm_hf(const __half* __restrict__ Ah, const __half* __restrict__ Al,
             const __half* __restrict__ Bh,
             const float* __restrict__ bias, float* __restrict__ Cf,
             __half* __restrict__ Ch, __half* __restrict__ Cl,
             int M, int N, int K, int relu)
{
    extern __shared__ char smc[];
    const uint32_t sb = smem_u32(smc);
    const int tid = threadIdx.x;
    const int lane = tid & 31, wid = tid >> 5;
    const int wm = (wid >> 2) * 64;
    const int wn = (wid & 3) * 32;
    const int row0 = blockIdx.y * 128, col0 = blockIdx.x * 128;

    const int a_r = tid >> 2, a_c = (tid & 3) * 16;
    const int a_r2 = (tid + 256) >> 2, a_c2 = ((tid + 256) & 3) * 16;
    const int b_kr = tid >> 4, b_c = (tid & 15) * 16;
    const int b_kr2 = (tid + 256) >> 4, b_c2 = ((tid + 256) & 15) * 16;

    float acc[4][4][4] = {};

    const int la_row  = wm + (lane & 15);
    const int la_colb = (lane >> 4) * 8;
    const int lb_row  = (lane & 7) + ((lane >> 3) & 1) * 8;
    const int lb_colb = wn + (lane >> 4) * 8;

    const int nblk = K / 32;

    #define PREFETCH(kb_, st_) do {                                                              \
        const int kq = (kb_) * 32;                                                               \
        uint32_t st = sb + (st_) * PIPE_STAGE;                                                   \
        CP_ASYNC16(st + a_r * 80 + a_c, Ah + (size_t)(row0 + a_r) * K + kq + a_c / 2);           \
        CP_ASYNC16(st + a_r2 * 80 + a_c2, Ah + (size_t)(row0 + a_r2) * K + kq + a_c2 / 2);       \
        CP_ASYNC16(st + OFF_AL + a_r * 80 + a_c, Al + (size_t)(row0 + a_r) * K + kq + a_c / 2);  \
        CP_ASYNC16(st + OFF_AL + a_r2 * 80 + a_c2, Al + (size_t)(row0 + a_r2) * K + kq + a_c2 / 2);\
        CP_ASYNC16(st + OFF_BH + b_kr * 272 + b_c, Bh + (size_t)(kq + b_kr) * N + col0 + b_c / 2);\
        CP_ASYNC16(st + OFF_BH + b_kr2 * 272 + b_c2, Bh + (size_t)(kq + b_kr2) * N + col0 + b_c2 / 2);\
        CP_COMMIT();                                                                             \
    } while (0)

    PREFETCH(0, 0);
    if (nblk > 1) PREFETCH(1, 1);

    for (int kb = 0; kb < nblk; kb++) {
        if (kb + 1 < nblk) asm volatile("cp.async.wait_group 1;" ::: "memory");
        else               asm volatile("cp.async.wait_group 0;" ::: "memory");
        __syncthreads();
        if (kb + 2 < nblk) PREFETCH(kb + 2, (kb + 2) % 3);

        const uint32_t st = sb + (kb % 3) * PIPE_STAGE;
        #pragma unroll
        for (int ks = 0; ks < 2; ks++) {
            uint32_t ah[4][4], al[4][4], bf[4][2];
            #pragma unroll
            for (int mt = 0; mt < 4; mt++) {
                uint32_t off = (uint32_t)((la_row + mt * 16) * 40 + ks * 16 + la_colb) * 2;
                ldmat_x4(ah[mt][0], ah[mt][1], ah[mt][2], ah[mt][3], st + off);
                ldmat_x4(al[mt][0], al[mt][1], al[mt][2], al[mt][3], st + OFF_AL + off);
            }
            #pragma unroll
            for (int p = 0; p < 2; p++) {
                uint32_t off = (uint32_t)((ks * 16 + lb_row) * 136 + lb_colb + p * 16) * 2;
                ldmat_x4t(bf[p * 2][0], bf[p * 2][1], bf[p * 2 + 1][0], bf[p * 2 + 1][1],
                          st + OFF_BH + off);
            }
            #pragma unroll
            for (int mt = 0; mt < 4; mt++)
                #pragma unroll
                for (int nt = 0; nt < 4; nt++) {
                    mma_f16(acc[mt][nt], ah[mt], bf[nt]);   // Ah*Bh
                    mma_f16(acc[mt][nt], al[mt], bf[nt]);   // Al*Bh
                }
        }
    }

    // ---- epilogue ----
    const int r_l = lane >> 2, c_l = (lane & 3) * 2;
    #pragma unroll
    for (int mt = 0; mt < 4; mt++) {
        int row = row0 + wm + mt * 16 + r_l;
        #pragma unroll
        for (int nt = 0; nt < 4; nt++) {
            int col = col0 + wn + nt * 8 + c_l;
            float b0 = bias[col], b1 = bias[col + 1];
            float v00 = acc[mt][nt][0] + b0, v01 = acc[mt][nt][1] + b1;
            float v10 = acc[mt][nt][2] + b0, v11 = acc[mt][nt][3] + b1;
            if (relu) {
                v00 = fmaxf(v00, 0.f); v01 = fmaxf(v01, 0.f);
                v10 = fmaxf(v10, 0.f); v11 = fmaxf(v11, 0.f);
            }
            if (Cf) {
                *(float2*)(Cf + (size_t)row * N + col) = make_float2(v00, v01);
                *(float2*)(Cf + (size_t)(row + 8) * N + col) = make_float2(v10, v11);
            }
            if (Ch) {
                __half h00 = __float2half_rn(v00), h01 = __float2half_rn(v01);
                __half h10 = __float2half_rn(v10), h11 = __float2half_rn(v11);
                __half2 hp0 = {h00, h01}, hp1 = {h10, h11};
                __half2 lp0 = {__float2half_rn(v00 - __half2float(h00)),
                               __float2half_rn(v01 - __half2float(h01))};
                __half2 lp1 = {__float2half_rn(v10 - __half2float(h10)),
                               __float2half_rn(v11 - __half2float(h11))};
                *(__half2*)(Ch + (size_t)row * N + col) = hp0;
                *(__half2*)(Ch + (size_t)(row + 8) * N + col) = hp1;
                *(__half2*)(Cl + (size_t)row * N + col) = lp0;
                *(__half2*)(Cl + (size_t)(row + 8) * N + col) = lp1;
            }
        }
    }
}

// ---------------- causal chunk phase 1: per-chunk sums ----------------------
__global__ __launch_bounds__(256)
void chunk_sum_kernel(const float* __restrict__ qvk,
                      float* __restrict__ csumK, float* __restrict__ csumKV)
{
    const int blk = blockIdx.x;
    const int bh = blk / NC, c = blk % NC;
    const int b = bh >> 3, h = bh & 7;
    const int tid = threadIdx.x;

    __shared__ __align__(16) float Ks[CC][68];
    __shared__ __align__(16) float Vs[CC][68];

    const float* base = qvk + (size_t)b * SEQN * (3 * DIM) + (size_t)c * CC * (3 * DIM) + h * HE;
    #pragma unroll
    for (int i = tid; i < CC * 16; i += 256) {
        int r = i >> 4;
        int col = (i & 15) * 4;
        const float* rp = base + (size_t)r * (3 * DIM);
        float4 kk = *(const float4*)(rp + 2 * DIM + col);
        float4 vv = *(const float4*)(rp + DIM + col);
        Ks[r][col + 0] = expf(kk.x); Ks[r][col + 1] = expf(kk.y);
        Ks[r][col + 2] = expf(kk.z); Ks[r][col + 3] = expf(kk.w);
        *(float4*)&Vs[r][col] = vv;
    }
    __syncthreads();

    const int ty = tid >> 4, tx = tid & 15;
    const int d0 = ty * 4, e0 = tx * 4;
    float acc[4][4] = {};
    #pragma unroll 8
    for (int n = 0; n < CC; n++) {
        float4 a = *(const float4*)&Ks[n][d0];
        float4 bb = *(const float4*)&Vs[n][e0];
        float av[4] = {a.x, a.y, a.z, a.w};
        float bv[4] = {bb.x, bb.y, bb.z, bb.w};
        #pragma unroll
        for (int i = 0; i < 4; i++)
            #pragma unroll
            for (int j = 0; j < 4; j++)
                acc[i][j] += av[i] * bv[j];
    }
    float* outKV = csumKV + ((size_t)bh * NC + c) * (HE * HE);
    #pragma unroll
    for (int i = 0; i < 4; i++) {
        float4 o = {acc[i][0], acc[i][1], acc[i][2], acc[i][3]};
        *(float4*)(outKV + (d0 + i) * HE + e0) = o;
    }
    if (tid < HE) {
        float s = 0.f;
        #pragma unroll 8
        for (int n = 0; n < CC; n++) s += Ks[n][tid];
        csumK[((size_t)bh * NC + c) * HE + tid] = s;
    }
}

// ---------------- causal chunk phase 2: exclusive prefix (parallel) ---------
// grid = BH*16; block handles 256 elements of one bh; thread owns 1 element.
__global__ __launch_bounds__(256)
void prefix_kernel(const float* __restrict__ csumK, const float* __restrict__ csumKV,
                   float* __restrict__ kcp, float* __restrict__ Sp)
{
    const int blk = blockIdx.x;
    const int bh = blk >> 4, seg = blk & 15;
    const int e = seg * 256 + threadIdx.x;
    const size_t stride = (size_t)(HE * HE);
    const float* src = csumKV + (size_t)bh * NC * stride + e;
    float v[NC];
    #pragma unroll
    for (int c = 0; c < NC; c++) v[c] = src[(size_t)c * stride];
    float* dst = Sp + (size_t)bh * NC * stride + e;
    float run = 0.f;
    #pragma unroll
    for (int c = 0; c < NC; c++) { dst[(size_t)c * stride] = run; run += v[c]; }

    if (seg == 0 && threadIdx.x < HE) {
        const int d = threadIdx.x;
        float vk[NC];
        #pragma unroll
        for (int c = 0; c < NC; c++) vk[c] = csumK[((size_t)bh * NC + c) * HE + d];
        float rk = 0.f;
        #pragma unroll
        for (int c = 0; c < NC; c++) { kcp[((size_t)bh * NC + c) * HE + d] = rk; rk += vk[c]; }
    }
}

// ---------------- causal chunk phase 3: per-chunk output --------------------
__global__ __launch_bounds__(256)
void causal_chunk_kernel(const float* __restrict__ qvk,
                         const float* __restrict__ kcp, const float* __restrict__ Sp,
                         float* __restrict__ out)
{
    extern __shared__ __align__(16) float sm[];
    float (*TsT)[68] = (float(*)[68])sm;
    float (*KsT)[68] = TsT + 64;
    float (*AT)[68]  = KsT + 64;
    float (*Vs)[68]  = AT + 64;
    float (*SpS)[68] = Vs + 64;
    float* kcpe = (float*)(SpS + 64);
    float* den  = kcpe + 64;

    const int blk = blockIdx.x;
    const int bh = blk / NC, c = blk % NC;
    const int b = bh >> 3, h = bh & 7;
    const int tid = threadIdx.x;
    const float* base = qvk + (size_t)b * SEQN * (3 * DIM) + (size_t)c * CC * (3 * DIM) + h * HE;

    {
        int r = tid >> 2;
        int g = tid & 3;
        const float* rp = base + (size_t)r * (3 * DIM) + g * 16;
        float qv[16];
        float m = -1e30f;
        #pragma unroll
        for (int j = 0; j < 16; j++) { qv[j] = rp[j]; m = fmaxf(m, qv[j]); }
        m = fmaxf(m, __shfl_xor_sync(0xffffffffu, m, 1));
        m = fmaxf(m, __shfl_xor_sync(0xffffffffu, m, 2));
        #pragma unroll
        for (int j = 0; j < 16; j++) TsT[g * 16 + j][r] = expf(qv[j] - m);
        const float* rpk = rp + 2 * DIM;
        #pragma unroll
        for (int j = 0; j < 16; j++) KsT[g * 16 + j][r] = expf(rpk[j]);
    }
    #pragma unroll
    for (int i = tid; i < CC * 16; i += 256) {
        int r = i >> 4, col = (i & 15) * 4;
        *(float4*)&Vs[r][col] = *(const float4*)(base + (size_t)r * (3 * DIM) + DIM + col);
    }
    const float* spb = Sp + ((size_t)bh * NC + c) * (HE * HE);
    #pragma unroll
    for (int i = tid; i < HE * 16; i += 256) {
        int r = i >> 4, col = (i & 15) * 4;
        *(float4*)&SpS[r][col] = *(const float4*)(spb + r * HE + col);
    }
    if (tid < HE) kcpe[tid] = kcp[((size_t)bh * NC + c) * HE + tid] + ATTN_EPS;
    __syncthreads();

    const int ty = tid >> 4, tx = tid & 15;
    const int t0 = ty * 4, s0 = tx * 4;

    {
        float acc[4][4] = {};
        #pragma unroll 8
        for (int d = 0; d < HE; d++) {
            float4 a = *(const float4*)&TsT[d][t0];
            float4 bb = *(const float4*)&KsT[d][s0];
            float av[4] = {a.x, a.y, a.z, a.w};
            float bv[4] = {bb.x, bb.y, bb.z, bb.w};
            #pragma unroll
            for (int i = 0; i < 4; i++)
                #pragma unroll
                for (int j = 0; j < 4; j++)
                    acc[i][j] += av[i] * bv[j];
        }
        #pragma unroll
        for (int i = 0; i < 4; i++)
            #pragma unroll
            for (int j = 0; j < 4; j++) {
                int t = t0 + i, s = s0 + j;
                AT[s][t] = (s <= t) ? acc[i][j] : 0.f;
            }
    }
    __syncthreads();

    if (tid < 128) {
        int t = tid >> 1, half = tid & 1;
        float sd = 0.f;
        int lo = half * 32;
        #pragma unroll 8
        for (int s = lo; s < lo + 32; s++) sd += AT[s][t];
        #pragma unroll 8
        for (int d = lo; d < lo + 32; d++) sd += TsT[d][t] * kcpe[d];
        sd += __shfl_xor_sync(0xffffffffu, sd, 1);
        if (!half) den[t] = 1.0f / sd;
    }
    __syncthreads();

    {
        const int e0 = tx * 4;
        float o[4][4] = {};
        #pragma unroll 8
        for (int s = 0; s < CC; s++) {
            float4 a = *(const float4*)&AT[s][t0];
            float4 bb = *(const float4*)&Vs[s][e0];
            float av[4] = {a.x, a.y, a.z, a.w};
            float bv[4] = {bb.x, bb.y, bb.z, bb.w};
            #pragma unroll
            for (int i = 0; i < 4; i++)
                #pragma unroll
                for (int j = 0; j < 4; j++)
                    o[i][j] += av[i] * bv[j];
        }
        #pragma unroll 8
        for (int d = 0; d < HE; d++) {
            float4 a = *(const float4*)&TsT[d][t0];
            float4 bb = *(const float4*)&SpS[d][e0];
            float av[4] = {a.x, a.y, a.z, a.w};
            float bv[4] = {bb.x, bb.y, bb.z, bb.w};
            #pragma unroll
            for (int i = 0; i < 4; i++)
                #pragma unroll
                for (int j = 0; j < 4; j++)
                    o[i][j] += av[i] * bv[j];
        }
        float* ob = out + (size_t)b * SEQN * DIM + (size_t)c * CC * DIM + h * HE;
        #pragma unroll
        for (int i = 0; i < 4; i++) {
            float rcp = den[t0 + i];
            float4 ov = {o[i][0] * rcp, o[i][1] * rcp, o[i][2] * rcp, o[i][3] * rcp};
            *(float4*)(ob + (size_t)(t0 + i) * DIM + e0) = ov;
        }
    }
}

// ---------------- residual + layernorm (+ optional fp16 hi/lo out) -----------
__global__ void ln_res_kernel(const float* __restrict__ a, const float* __restrict__ r,
                              const float* __restrict__ g, const float* __restrict__ beta,
                              float* __restrict__ out,
                              __half* __restrict__ oh, __half* __restrict__ ol)
{
    const int row = blockIdx.x;
    const int tid = threadIdx.x;
    const int w = tid >> 5, lane = tid & 31;
    __shared__ float red[16];

    float pre[2], sum = 0.f, sumsq = 0.f;
    #pragma unroll
    for (int it = 0; it < 2; it++) {
        int o = tid + it * 256;
        float p = a[(size_t)row * DIM + o] + r[(size_t)row * DIM + o];
        pre[it] = p; sum += p; sumsq += p * p;
    }
    #pragma unroll
    for (int o = 16; o > 0; o >>= 1) {
        sum   += __shfl_xor_sync(0xffffffffu, sum, o);
        sumsq += __shfl_xor_sync(0xffffffffu, sumsq, o);
    }
    if (lane == 0) { red[w] = sum; red[8 + w] = sumsq; }
    __syncthreads();
    if (tid == 0) {
        float s = 0.f, q = 0.f;
        #pragma unroll
        for (int i = 0; i < 8; i++) { s += red[i]; q += red[8 + i]; }
        float mu = s / (float)DIM;
        float var = q / (float)DIM - mu * mu;
        red[0] = mu; red[1] = rsqrtf(var + LN_EPS);
    }
    __syncthreads();
    float mu = red[0], rstd = red[1];
    #pragma unroll
    for (int it = 0; it < 2; it++) {
        int o = tid + it * 256;
        float v = (pre[it] - mu) * rstd * g[o] + beta[o];
        out[(size_t)row * DIM + o] = v;
        if (oh) {
            __half h = __float2half_rn(v);
            oh[(size_t)row * DIM + o] = h;
            ol[(size_t)row * DIM + o] = __float2half_rn(v - __half2float(h));
        }
    }
}

// ---------------- cross-attn: per-column softmax stats -----------------------
__global__ void col_stats_kernel(const float* __restrict__ kv,
                                 float* __restrict__ colmax, float* __restrict__ colsum)
{
    const int b = blockIdx.y;
    const int lane = threadIdx.x & 31;
    const int r = threadIdx.x >> 5;
    const int d = blockIdx.x * 32 + lane;
    const float* base = kv + (size_t)b * SEQM * (2 * DIM) + d;

    __shared__ float sm[8][32];
    __shared__ float cm[32];

    float m = -1e30f;
    for (int n = r; n < SEQM; n += 8) m = fmaxf(m, base[(size_t)n * (2 * DIM)]);
    sm[r][lane] = m;
    __syncthreads();
    if (threadIdx.x < 32) {
        float mm = sm[0][threadIdx.x];
        #pragma unroll
        for (int i = 1; i < 8; i++) mm = fmaxf(mm, sm[i][threadIdx.x]);
        cm[threadIdx.x] = mm;
        colmax[b * DIM + blockIdx.x * 32 + threadIdx.x] = mm;
    }
    __syncthreads();
    float s = 0.f;
    float mref = cm[lane];
    for (int n = r; n < SEQM; n += 8) s += expf(base[(size_t)n * (2 * DIM)] - mref);
    sm[r][lane] = s;
    __syncthreads();
    if (threadIdx.x < 32) {
        float ss = sm[0][threadIdx.x];
        #pragma unroll
        for (int i = 1; i < 8; i++) ss += sm[i][threadIdx.x];
        colsum[b * DIM + blockIdx.x * 32 + threadIdx.x] = ss;
    }
}

// ---------------- cross-attn: partial ctx over n-chunks ----------------------
__global__ void cross_ctx_kernel(const float* __restrict__ kv,
                                 const float* __restrict__ colmax, const float* __restrict__ colsum,
                                 float* __restrict__ ctxp)
{
    const int blk = blockIdx.x;
    const int bh = blk / NCH, ch = blk % NCH;
    const int b = bh >> 3, h = bh & 7;
    const int tid = threadIdx.x;
    const int tx = tid & 15, ty = tid >> 4;

    __shared__ __align__(16) float Ks[32][64];
    __shared__ __align__(16) float Vs[32][64];
    __shared__ float cm[64], ci[64];

    if (tid < 64) {
        cm[tid] = colmax[b * DIM + h * HE + tid];
        ci[tid] = 1.0f / colsum[b * DIM + h * HE + tid];
    }
    __syncthreads();

    float acc[4][4] = {};
    const float* base = kv + (size_t)b * SEQM * (2 * DIM) + h * HE;
    const int n_lo = ch * CHROWS, n_hi = n_lo + CHROWS;
    for (int n0 = n_lo; n0 < n_hi; n0 += 32) {
        #pragma unroll
        for (int it = 0; it < 2; it++) {
            int f4 = tid + it * 256;
            int r = f4 >> 4;
            int c = (f4 & 15) * 4;
            const float* rp = base + (size_t)(n0 + r) * (2 * DIM);
            float4 kk = *(const float4*)(rp + c);
            float4 vv = *(const float4*)(rp + DIM + c);
            Ks[r][c + 0] = expf(kk.x - cm[c + 0]) * ci[c + 0];
            Ks[r][c + 1] = expf(kk.y - cm[c + 1]) * ci[c + 1];
            Ks[r][c + 2] = expf(kk.z - cm[c + 2]) * ci[c + 2];
            Ks[r][c + 3] = expf(kk.w - cm[c + 3]) * ci[c + 3];
            *(float4*)&Vs[r][c] = vv;
        }
        __syncthreads();
        #pragma unroll
        for (int r = 0; r < 32; r++) {
            float4 av = *(const float4*)&Ks[r][ty * 4];
            float4 bv = *(const float4*)&Vs[r][tx * 4];
            float a[4] = {av.x, av.y, av.z, av.w};
            float bb[4] = {bv.x, bv.y, bv.z, bv.w};
            #pragma unroll
            for (int i = 0; i < 4; i++)
                #pragma unroll
                for (int j = 0; j < 4; j++)
                    acc[i][j] += a[i] * bb[j];
        }
        __syncthreads();
    }
    float* cb = ctxp + (size_t)blk * (HE * HE);
    #pragma unroll
    for (int i = 0; i < 4; i++)
        #pragma unroll
        for (int j = 0; j < 4; j++)
            cb[(ty * 4 + i) * HE + tx * 4 + j] = acc[i][j];
}

__global__ void ctx_reduce_kernel(const float* __restrict__ ctxp, float* __restrict__ ctx)
{
    const int bh = blockIdx.x;
    const int tid = threadIdx.x;
    size_t o = (size_t)tid * 16;
    float4 s[4];
    #pragma unroll
    for (int i = 0; i < 4; i++) s[i] = make_float4(0.f, 0.f, 0.f, 0.f);
    #pragma unroll
    for (int ch = 0; ch < NCH; ch++) {
        const float4* src = (const float4*)(ctxp + ((size_t)bh * NCH + ch) * (HE * HE) + o);
        #pragma unroll
        for (int i = 0; i < 4; i++) {
            float4 v = src[i];
            s[i].x += v.x; s[i].y += v.y; s[i].z += v.z; s[i].w += v.w;
        }
    }
    float4* dst = (float4*)(ctx + (size_t)bh * (HE * HE) + o);
    #pragma unroll
    for (int i = 0; i < 4; i++) dst[i] = s[i];
}

// ---------------- cross-attn output + residual + LN2 (+ fp16 out) -----------
__global__ void cross_out_ln2_kernel(const float* __restrict__ q2, const float* __restrict__ ctx,
                                     const float* __restrict__ res, const float* __restrict__ g,
                                     const float* __restrict__ beta, float* __restrict__ out,
                                     __half* __restrict__ oh, __half* __restrict__ ol)
{
    const int row = blockIdx.x;
    const int b = row >> 11;
    const int tid = threadIdx.x;
    const int w = tid >> 5, lane = tid & 31;

    __shared__ float qs_s[DIM];
    __shared__ float red[16];

    const float* qr = q2 + (size_t)row * DIM;
    {
        float a0 = qr[w * HE + lane], a1 = qr[w * HE + 32 + lane];
        float m = fmaxf(a0, a1);
        #pragma unroll
        for (int o = 16; o > 0; o >>= 1) m = fmaxf(m, __shfl_xor_sync(0xffffffffu, m, o));
        float t0 = expf(a0 - m), t1 = expf(a1 - m);
        float s = t0 + t1;
        #pragma unroll
        for (int o = 16; o > 0; o >>= 1) s += __shfl_xor_sync(0xffffffffu, s, o);
        float sc = 0.125f / s;
        qs_s[w * HE + lane] = t0 * sc;
        qs_s[w * HE + 32 + lane] = t1 * sc;
    }
    __syncthreads();

    float pre[2], sum = 0.f, sumsq = 0.f;
    #pragma unroll
    for (int it = 0; it < 2; it++) {
        int o = tid + it * 256;
        int h = o >> 6, e = o & 63;
        const float* cb = ctx + ((size_t)(b * NH + h)) * (HE * HE) + e;
        const float* qh = qs_s + h * HE;
        float acc = 0.f;
        #pragma unroll 8
        for (int d = 0; d < HE; d++) acc += qh[d] * cb[d * HE];
        float p = acc + res[(size_t)row * DIM + o];
        pre[it] = p; sum += p; sumsq += p * p;
    }
    #pragma unroll
    for (int o = 16; o > 0; o >>= 1) {
        sum   += __shfl_xor_sync(0xffffffffu, sum, o);
        sumsq += __shfl_xor_sync(0xffffffffu, sumsq, o);
    }
    if (lane == 0) { red[w] = sum; red[8 + w] = sumsq; }
    __syncthreads();
    if (tid == 0) {
        float s = 0.f, q = 0.f;
        #pragma unroll
        for (int i = 0; i < 8; i++) { s += red[i]; q += red[8 + i]; }
        float mu = s / (float)DIM;
        float var = q / (float)DIM - mu * mu;
        red[0] = mu; red[1] = rsqrtf(var + LN_EPS);
    }
    __syncthreads();
    float mu = red[0], rstd = red[1];
    #pragma unroll
    for (int it = 0; it < 2; it++) {
        int o = tid + it * 256;
        float v = (pre[it] - mu) * rstd * g[o] + beta[o];
        out[(size_t)row * DIM + o] = v;
        __half h = __float2half_rn(v);
        oh[(size_t)row * DIM + o] = h;
        ol[(size_t)row * DIM + o] = __float2half_rn(v - __half2float(h));
    }
}

// ---------------- host launch ------------------------------------------------
extern "C" void kernel_launch(void* const* d_in, const int* in_sizes, int n_in,
                              void* d_out, int out_size)
{
    const float* x      = (const float*)d_in[0];
    const float* memory = (const float*)d_in[1];
    const float* W_qvk  = (const float*)d_in[2];
    const float* b_qvk  = (const float*)d_in[3];
    const float* W_kv   = (const float*)d_in[4];
    const float* b_kv   = (const float*)d_in[5];
    const float* W_q    = (const float*)d_in[6];
    const float* b_q    = (const float*)d_in[7];
    const float* W_ff1  = (const float*)d_in[8];
    const float* b_ff1  = (const float*)d_in[9];
    const float* W_ff2  = (const float*)d_in[10];
    const float* b_ff2  = (const float*)d_in[11];
    const float* ln1_g  = (const float*)d_in[12];
    const float* ln1_b  = (const float*)d_in[13];
    const float* ln2_g  = (const float*)d_in[14];
    const float* ln2_b  = (const float*)d_in[15];
    const float* ln3_g  = (const float*)d_in[16];
    const float* ln3_b  = (const float*)d_in[17];
    float* outp = (float*)d_out;

    float *qvk, *attn1, *ln1, *kv, *q2, *colmax, *colsum, *ctxp, *ctx, *ln2, *pre3;
    float *csumK, *csumKV, *kcp, *Sp;
    __half *xh, *xl, *mh, *ml, *ln1h, *ln1l, *ln2h, *ln2l, *ff1h, *ff1l;
    __half *wqvkh, *wkvh, *wqh, *wf1h, *wf2h;
    cudaGetSymbolAddress((void**)&qvk,   g_qvk);
    cudaGetSymbolAddress((void**)&attn1, g_attn1);
    cudaGetSymbolAddress((void**)&ln1,   g_ln1);
    cudaGetSymbolAddress((void**)&kv,    g_kv);
    cudaGetSymbolAddress((void**)&q2,    g_q2);
    cudaGetSymbolAddress((void**)&colmax,g_colmax);
    cudaGetSymbolAddress((void**)&colsum,g_colsum);
    cudaGetSymbolAddress((void**)&ctxp,  g_ctxp);
    cudaGetSymbolAddress((void**)&ctx,   g_ctx);
    cudaGetSymbolAddress((void**)&ln2,   g_ln2);
    cudaGetSymbolAddress((void**)&pre3,  g_pre3);
    cudaGetSymbolAddress((void**)&csumK, g_csumK);
    cudaGetSymbolAddress((void**)&csumKV,g_csumKV);
    cudaGetSymbolAddress((void**)&kcp,   g_kcp);
    cudaGetSymbolAddress((void**)&Sp,    g_Sp);
    cudaGetSymbolAddress((void**)&xh,   g_xh);   cudaGetSymbolAddress((void**)&xl,   g_xl);
    cudaGetSymbolAddress((void**)&mh,   g_mh);   cudaGetSymbolAddress((void**)&ml,   g_ml);
    cudaGetSymbolAddress((void**)&ln1h, g_ln1h); cudaGetSymbolAddress((void**)&ln1l, g_ln1l);
    cudaGetSymbolAddress((void**)&ln2h, g_ln2h); cudaGetSymbolAddress((void**)&ln2l, g_ln2l);
    cudaGetSymbolAddress((void**)&ff1h, g_ff1h); cudaGetSymbolAddress((void**)&ff1l, g_ff1l);
    cudaGetSymbolAddress((void**)&wqvkh,g_wqvkh);
    cudaGetSymbolAddress((void**)&wkvh, g_wkvh);
    cudaGetSymbolAddress((void**)&wqh,  g_wqh);
    cudaGetSymbolAddress((void**)&wf1h, g_wf1h);
    cudaGetSymbolAddress((void**)&wf2h, g_wf2h);

    const int CSMEM = (5 * 64 * 68 + 128) * (int)sizeof(float);
    cudaFuncSetAttribute(causal_chunk_kernel, cudaFuncAttributeMaxDynamicSharedMemorySize, CSMEM);
    cudaFuncSetAttribute(gemm_hf, cudaFuncAttributeMaxDynamicSharedMemorySize, GB_SMEM);

    // 0) batched precision-split conversion (x/memory: hi+lo; weights: hi only)
    {
        ConvBatch cb;
        const float* srcs[NSEG] = {x, memory, W_qvk, W_kv, W_q, W_ff1, W_ff2};
        __half* his[NSEG] = {xh, mh, wqvkh, wkvh, wqh, wf1h, wf2h};
        __half* los[NSEG] = {xl, ml, nullptr, nullptr, nullptr, nullptr, nullptr};
        int ns[NSEG] = {ROWS * DIM / 4, ROWS * DIM / 4, DIM * 3 * DIM / 4,
                        DIM * 2 * DIM / 4, DIM * DIM / 4, DIM * FF / 4, FF * DIM / 4};
        int acc_n = 0;
        for (int s = 0; s < NSEG; s++) {
            cb.src[s] = (const float4*)srcs[s];
            cb.hi[s] = (uint2*)his[s];
            cb.lo[s] = (uint2*)los[s];
            acc_n += ns[s];
            cb.end[s] = acc_n;
        }
        conv_split_multi<<<(acc_n + 255) / 256, 256>>>(cb);
    }

    // 1) qvk = x @ W_qvk + b
    gemm_hf<<<dim3((3 * DIM) / 128, ROWS / 128), 256, GB_SMEM>>>(
        xh, xl, wqvkh, b_qvk, qvk, nullptr, nullptr, ROWS, 3 * DIM, DIM, 0);
    // 2) causal linear self-attention, chunk-parallel
    chunk_sum_kernel<<<BH * NC, 256>>>(qvk, csumK, csumKV);
    prefix_kernel<<<BH * 16, 256>>>(csumK, csumKV, kcp, Sp);
    causal_chunk_kernel<<<BH * NC, 256, CSMEM>>>(qvk, kcp, Sp, attn1);
    // 3) LN1(attn + x) -> fp32 + fp16 split
    ln_res_kernel<<<ROWS, 256>>>(attn1, x, ln1_g, ln1_b, ln1, ln1h, ln1l);
    // 4) kv = memory @ W_kv + b
    gemm_hf<<<dim3((2 * DIM) / 128, ROWS / 128), 256, GB_SMEM>>>(
        mh, ml, wkvh, b_kv, kv, nullptr, nullptr, ROWS, 2 * DIM, DIM, 0);
    // 5) q2 = ln1 @ W_q + b
    gemm_hf<<<dim3(DIM / 128, ROWS / 128), 256, GB_SMEM>>>(
        ln1h, ln1l, wqh, b_q, q2, nullptr, nullptr, ROWS, DIM, DIM, 0);
    // 6) column softmax stats of k over memory rows
    col_stats_kernel<<<dim3(DIM / 32, BATCH), 256>>>(kv, colmax, colsum);
    // 7) ctx = softk^T @ v per head (n-chunked + reduce)
    cross_ctx_kernel<<<BH * NCH, 256>>>(kv, colmax, colsum, ctxp);
    ctx_reduce_kernel<<<BH, 256>>>(ctxp, ctx);
    // 8) out2 = softmax(q2) @ ctx, + res, LN2 (fused) -> fp32 + fp16 split
    cross_out_ln2_kernel<<<ROWS, 256>>>(q2, ctx, ln1, ln2_g, ln2_b, ln2, ln2h, ln2l);
    // 9) ff1 = relu(ln2 @ W_ff1 + b) -> fp16 split only
    gemm_hf<<<dim3(FF / 128, ROWS / 128), 256, GB_SMEM>>>(
        ln2h, ln2l, wf1h, b_ff1, nullptr, ff1h, ff1l, ROWS, FF, DIM, 1);
    // 10) pre3 = ff1 @ W_ff2 + b
    gemm_hf<<<dim3(DIM / 128, ROWS / 128), 256, GB_SMEM>>>(
        ff1h, ff1l, wf2h, b_ff2, pre3, nullptr, nullptr, ROWS, DIM, FF, 0);
    // 11) LN3(pre3 + ln2) -> output
    ln_res_kernel<<<ROWS, 256>>>(pre3, ln2, ln3_g, ln3_b, outp, nullptr, nullptr);
}

// round 12
// speedup vs baseline: 9.1001x; 1.2846x over previous
#include <cuda_runtime.h>
#include <cuda_bf16.h>
#include <cuda_fp16.h>
#include <math.h>
#include <stdint.h>

// Problem dims
#define BATCH 2
#define SEQN 2048
#define SEQM 2048
#define DIM 512
#define NH 8
#define HE 64
#define FF 2048
#define ROWS (BATCH * SEQN)   // 4096
#define LN_EPS 1e-5f
#define ATTN_EPS 1e-6f

// chunked causal linear attention
#define CC 64
#define NC (SEQN / CC)        // 32
#define BH (BATCH * NH)       // 16
// cross-attn ctx n-split
#define NCH 8
#define CHROWS (SEQM / NCH)   // 256

// ---------------- scratch (device globals; no allocations allowed) ----------
__device__ float g_qvk [ROWS * 3 * DIM];
__device__ float g_attn1[ROWS * DIM];
__device__ float g_ln1 [ROWS * DIM];
__device__ float g_kv  [ROWS * 2 * DIM];
__device__ float g_q2  [ROWS * DIM];
__device__ float g_colmax[BATCH * DIM];
__device__ float g_colsum[BATCH * DIM];
__device__ float g_ctxp[BH * NCH * HE * HE];
__device__ float g_ctx [BH * HE * HE];
__device__ float g_ln2 [ROWS * DIM];
__device__ float g_pre3[ROWS * DIM];
// causal-chunk state
__device__ float g_csumK [BH * NC * HE];
__device__ float g_csumKV[BH * NC * HE * HE];
__device__ float g_kcp   [BH * NC * HE];
__device__ float g_Sp    [BH * NC * HE * HE];
// fp16 tensors
__device__ __half g_xh [ROWS * DIM];
__device__ __half g_mh [ROWS * DIM];
__device__ __half g_ln1h[ROWS * DIM];
__device__ __half g_ln2h[ROWS * DIM];
__device__ __half g_ff1h[ROWS * FF];
__device__ __half g_wqvkh[DIM * 3 * DIM];
__device__ __half g_wkvh [DIM * 2 * DIM];
__device__ __half g_wqh  [DIM * DIM];
__device__ __half g_wf1h [DIM * FF];
__device__ __half g_wf2h [FF * DIM];

// ---------------- helpers ----------------------------------------------------
__device__ __forceinline__ uint32_t smem_u32(const void* p) {
    uint32_t a;
    asm("{ .reg .u64 t; cvta.to.shared.u64 t, %1; cvt.u32.u64 %0, t; }" : "=r"(a) : "l"(p));
    return a;
}
__device__ __forceinline__ void ldmat_x4(uint32_t& r0, uint32_t& r1, uint32_t& r2, uint32_t& r3,
                                         uint32_t addr) {
    asm volatile("ldmatrix.sync.aligned.m8n8.x4.shared.b16 {%0,%1,%2,%3}, [%4];"
                 : "=r"(r0), "=r"(r1), "=r"(r2), "=r"(r3) : "r"(addr));
}
__device__ __forceinline__ void ldmat_x4t(uint32_t& r0, uint32_t& r1, uint32_t& r2, uint32_t& r3,
                                          uint32_t addr) {
    asm volatile("ldmatrix.sync.aligned.m8n8.x4.trans.shared.b16 {%0,%1,%2,%3}, [%4];"
                 : "=r"(r0), "=r"(r1), "=r"(r2), "=r"(r3) : "r"(addr));
}
__device__ __forceinline__ void mma_f16(float* c, const uint32_t* a, const uint32_t* b) {
    asm volatile(
        "mma.sync.aligned.m16n8k16.row.col.f32.f16.f16.f32 "
        "{%0,%1,%2,%3}, {%4,%5,%6,%7}, {%8,%9}, {%0,%1,%2,%3};"
        : "+f"(c[0]), "+f"(c[1]), "+f"(c[2]), "+f"(c[3])
        : "r"(a[0]), "r"(a[1]), "r"(a[2]), "r"(a[3]), "r"(b[0]), "r"(b[1]));
}
#define CP_ASYNC16(dst, src) \
    asm volatile("cp.async.cg.shared.global [%0], [%1], 16;" :: "r"(dst), "l"(src) : "memory")
#define CP_COMMIT() asm volatile("cp.async.commit_group;" ::: "memory")

// ---------------- fp32 -> fp16 conversion, batched over 7 tensors -----------
#define NSEG 7
struct ConvBatch {
    const float4* src[NSEG];
    uint2* hi[NSEG];
    int end[NSEG];        // exclusive prefix ends (float4 units)
};
__global__ void conv_multi(ConvBatch cb)
{
    int i = blockIdx.x * blockDim.x + threadIdx.x;
    if (i >= cb.end[NSEG - 1]) return;
    int s = 0;
    #pragma unroll
    for (int k = 0; k < NSEG - 1; k++) s += (i >= cb.end[k]);
    int j = i - (s ? cb.end[s - 1] : 0);
    float4 f = cb.src[s][j];
    __half2 ha = {__float2half_rn(f.x), __float2half_rn(f.y)};
    __half2 hb = {__float2half_rn(f.z), __float2half_rn(f.w)};
    cb.hi[s][j] = make_uint2(*(uint32_t*)&ha, *(uint32_t*)&hb);
}

// ================= fp16 tensor-core GEMM, 3-stage cp.async ===================
// 128x128 CTA tile, BK=32, 8 warps (2x4), warp tile 64x32. acc fp32.
#define OFF_BH 10240      // A: 128 rows * 80B; B: 32 rows * 272B
#define PIPE_STAGE 18944
#define GB_SMEM (3 * PIPE_STAGE)   // 56,832 B

__global__ __launch_bounds__(256)
void gemm_hf(const __half* __restrict__ Ah, const __half* __restrict__ Bh,
             const float* __restrict__ bias, float* __restrict__ Cf,
             __half* __restrict__ Ch,
             int M, int N, int K, int relu)
{
    extern __shared__ char smc[];
    const uint32_t sb = smem_u32(smc);
    const int tid = threadIdx.x;
    const int lane = tid & 31, wid = tid >> 5;
    const int wm = (wid >> 2) * 64;
    const int wn = (wid & 3) * 32;
    const int row0 = blockIdx.y * 128, col0 = blockIdx.x * 128;

    const int a_r = tid >> 2, a_c = (tid & 3) * 16;
    const int a_r2 = (tid + 256) >> 2, a_c2 = ((tid + 256) & 3) * 16;
    const int b_kr = tid >> 4, b_c = (tid & 15) * 16;
    const int b_kr2 = (tid + 256) >> 4, b_c2 = ((tid + 256) & 15) * 16;

    float acc[4][4][4] = {};

    const int la_row  = wm + (lane & 15);
    const int la_colb = (lane >> 4) * 8;
    const int lb_row  = (lane & 7) + ((lane >> 3) & 1) * 8;
    const int lb_colb = wn + (lane >> 4) * 8;

    const int nblk = K / 32;

    #define PREFETCH(kb_, st_) do {                                                              \
        const int kq = (kb_) * 32;                                                               \
        uint32_t st = sb + (st_) * PIPE_STAGE;                                                   \
        CP_ASYNC16(st + a_r * 80 + a_c, Ah + (size_t)(row0 + a_r) * K + kq + a_c / 2);           \
        CP_ASYNC16(st + a_r2 * 80 + a_c2, Ah + (size_t)(row0 + a_r2) * K + kq + a_c2 / 2);       \
        CP_ASYNC16(st + OFF_BH + b_kr * 272 + b_c, Bh + (size_t)(kq + b_kr) * N + col0 + b_c / 2);\
        CP_ASYNC16(st + OFF_BH + b_kr2 * 272 + b_c2, Bh + (size_t)(kq + b_kr2) * N + col0 + b_c2 / 2);\
        CP_COMMIT();                                                                             \
    } while (0)

    PREFETCH(0, 0);
    if (nblk > 1) PREFETCH(1, 1);

    for (int kb = 0; kb < nblk; kb++) {
        if (kb + 1 < nblk) asm volatile("cp.async.wait_group 1;" ::: "memory");
        else               asm volatile("cp.async.wait_group 0;" ::: "memory");
        __syncthreads();
        if (kb + 2 < nblk) PREFETCH(kb + 2, (kb + 2) % 3);

        const uint32_t st = sb + (kb % 3) * PIPE_STAGE;
        #pragma unroll
        for (int ks = 0; ks < 2; ks++) {
            uint32_t ah[4][4], bf[4][2];
            #pragma unroll
            for (int mt = 0; mt < 4; mt++) {
                uint32_t off = (uint32_t)((la_row + mt * 16) * 40 + ks * 16 + la_colb) * 2;
                ldmat_x4(ah[mt][0], ah[mt][1], ah[mt][2], ah[mt][3], st + off);
            }
            #pragma unroll
            for (int p = 0; p < 2; p++) {
                uint32_t off = (uint32_t)((ks * 16 + lb_row) * 136 + lb_colb + p * 16) * 2;
                ldmat_x4t(bf[p * 2][0], bf[p * 2][1], bf[p * 2 + 1][0], bf[p * 2 + 1][1],
                          st + OFF_BH + off);
            }
            #pragma unroll
            for (int mt = 0; mt < 4; mt++)
                #pragma unroll
                for (int nt = 0; nt < 4; nt++)
                    mma_f16(acc[mt][nt], ah[mt], bf[nt]);
        }
    }

    // ---- epilogue ----
    const int r_l = lane >> 2, c_l = (lane & 3) * 2;
    #pragma unroll
    for (int mt = 0; mt < 4; mt++) {
        int row = row0 + wm + mt * 16 + r_l;
        #pragma unroll
        for (int nt = 0; nt < 4; nt++) {
            int col = col0 + wn + nt * 8 + c_l;
            float b0 = bias[col], b1 = bias[col + 1];
            float v00 = acc[mt][nt][0] + b0, v01 = acc[mt][nt][1] + b1;
            float v10 = acc[mt][nt][2] + b0, v11 = acc[mt][nt][3] + b1;
            if (relu) {
                v00 = fmaxf(v00, 0.f); v01 = fmaxf(v01, 0.f);
                v10 = fmaxf(v10, 0.f); v11 = fmaxf(v11, 0.f);
            }
            if (Cf) {
                *(float2*)(Cf + (size_t)row * N + col) = make_float2(v00, v01);
                *(float2*)(Cf + (size_t)(row + 8) * N + col) = make_float2(v10, v11);
            }
            if (Ch) {
                __half2 hp0 = {__float2half_rn(v00), __float2half_rn(v01)};
                __half2 hp1 = {__float2half_rn(v10), __float2half_rn(v11)};
                *(__half2*)(Ch + (size_t)row * N + col) = hp0;
                *(__half2*)(Ch + (size_t)(row + 8) * N + col) = hp1;
            }
        }
    }
}

// ---------------- causal chunk phase 1: per-chunk sums ----------------------
__global__ __launch_bounds__(256)
void chunk_sum_kernel(const float* __restrict__ qvk,
                      float* __restrict__ csumK, float* __restrict__ csumKV)
{
    const int blk = blockIdx.x;
    const int bh = blk / NC, c = blk % NC;
    const int b = bh >> 3, h = bh & 7;
    const int tid = threadIdx.x;

    __shared__ __align__(16) float Ks[CC][68];
    __shared__ __align__(16) float Vs[CC][68];

    const float* base = qvk + (size_t)b * SEQN * (3 * DIM) + (size_t)c * CC * (3 * DIM) + h * HE;
    #pragma unroll
    for (int i = tid; i < CC * 16; i += 256) {
        int r = i >> 4;
        int col = (i & 15) * 4;
        const float* rp = base + (size_t)r * (3 * DIM);
        float4 kk = *(const float4*)(rp + 2 * DIM + col);
        float4 vv = *(const float4*)(rp + DIM + col);
        Ks[r][col + 0] = expf(kk.x); Ks[r][col + 1] = expf(kk.y);
        Ks[r][col + 2] = expf(kk.z); Ks[r][col + 3] = expf(kk.w);
        *(float4*)&Vs[r][col] = vv;
    }
    __syncthreads();

    const int ty = tid >> 4, tx = tid & 15;
    const int d0 = ty * 4, e0 = tx * 4;
    float acc[4][4] = {};
    #pragma unroll 8
    for (int n = 0; n < CC; n++) {
        float4 a = *(const float4*)&Ks[n][d0];
        float4 bb = *(const float4*)&Vs[n][e0];
        float av[4] = {a.x, a.y, a.z, a.w};
        float bv[4] = {bb.x, bb.y, bb.z, bb.w};
        #pragma unroll
        for (int i = 0; i < 4; i++)
            #pragma unroll
            for (int j = 0; j < 4; j++)
                acc[i][j] += av[i] * bv[j];
    }
    float* outKV = csumKV + ((size_t)bh * NC + c) * (HE * HE);
    #pragma unroll
    for (int i = 0; i < 4; i++) {
        float4 o = {acc[i][0], acc[i][1], acc[i][2], acc[i][3]};
        *(float4*)(outKV + (d0 + i) * HE + e0) = o;
    }
    if (tid < HE) {
        float s = 0.f;
        #pragma unroll 8
        for (int n = 0; n < CC; n++) s += Ks[n][tid];
        csumK[((size_t)bh * NC + c) * HE + tid] = s;
    }
}

// ---------------- causal chunk phase 2: exclusive prefix (parallel) ---------
__global__ __launch_bounds__(256)
void prefix_kernel(const float* __restrict__ csumK, const float* __restrict__ csumKV,
                   float* __restrict__ kcp, float* __restrict__ Sp)
{
    const int blk = blockIdx.x;
    const int bh = blk >> 4, seg = blk & 15;
    const int e = seg * 256 + threadIdx.x;
    const size_t stride = (size_t)(HE * HE);
    const float* src = csumKV + (size_t)bh * NC * stride + e;
    float v[NC];
    #pragma unroll
    for (int c = 0; c < NC; c++) v[c] = src[(size_t)c * stride];
    float* dst = Sp + (size_t)bh * NC * stride + e;
    float run = 0.f;
    #pragma unroll
    for (int c = 0; c < NC; c++) { dst[(size_t)c * stride] = run; run += v[c]; }

    if (seg == 0 && threadIdx.x < HE) {
        const int d = threadIdx.x;
        float vk[NC];
        #pragma unroll
        for (int c = 0; c < NC; c++) vk[c] = csumK[((size_t)bh * NC + c) * HE + d];
        float rk = 0.f;
        #pragma unroll
        for (int c = 0; c < NC; c++) { kcp[((size_t)bh * NC + c) * HE + d] = rk; rk += vk[c]; }
    }
}

// ---------------- causal chunk phase 3: per-chunk output --------------------
__global__ __launch_bounds__(256)
void causal_chunk_kernel(const float* __restrict__ qvk,
                         const float* __restrict__ kcp, const float* __restrict__ Sp,
                         float* __restrict__ out)
{
    extern __shared__ __align__(16) float sm[];
    float (*TsT)[68] = (float(*)[68])sm;
    float (*KsT)[68] = TsT + 64;
    float (*AT)[68]  = KsT + 64;
    float (*Vs)[68]  = AT + 64;
    float (*SpS)[68] = Vs + 64;
    float* kcpe = (float*)(SpS + 64);
    float* den  = kcpe + 64;

    const int blk = blockIdx.x;
    const int bh = blk / NC, c = blk % NC;
    const int b = bh >> 3, h = bh & 7;
    const int tid = threadIdx.x;
    const float* base = qvk + (size_t)b * SEQN * (3 * DIM) + (size_t)c * CC * (3 * DIM) + h * HE;

    {
        int r = tid >> 2;
        int g = tid & 3;
        const float* rp = base + (size_t)r * (3 * DIM) + g * 16;
        float qv[16];
        float m = -1e30f;
        #pragma unroll
        for (int j = 0; j < 16; j++) { qv[j] = rp[j]; m = fmaxf(m, qv[j]); }
        m = fmaxf(m, __shfl_xor_sync(0xffffffffu, m, 1));
        m = fmaxf(m, __shfl_xor_sync(0xffffffffu, m, 2));
        #pragma unroll
        for (int j = 0; j < 16; j++) TsT[g * 16 + j][r] = expf(qv[j] - m);
        const float* rpk = rp + 2 * DIM;
        #pragma unroll
        for (int j = 0; j < 16; j++) KsT[g * 16 + j][r] = expf(rpk[j]);
    }
    #pragma unroll
    for (int i = tid; i < CC * 16; i += 256) {
        int r = i >> 4, col = (i & 15) * 4;
        *(float4*)&Vs[r][col] = *(const float4*)(base + (size_t)r * (3 * DIM) + DIM + col);
    }
    const float* spb = Sp + ((size_t)bh * NC + c) * (HE * HE);
    #pragma unroll
    for (int i = tid; i < HE * 16; i += 256) {
        int r = i >> 4, col = (i & 15) * 4;
        *(float4*)&SpS[r][col] = *(const float4*)(spb + r * HE + col);
    }
    if (tid < HE) kcpe[tid] = kcp[((size_t)bh * NC + c) * HE + tid] + ATTN_EPS;
    __syncthreads();

    const int ty = tid >> 4, tx = tid & 15;
    const int t0 = ty * 4, s0 = tx * 4;

    {
        float acc[4][4] = {};
        #pragma unroll 8
        for (int d = 0; d < HE; d++) {
            float4 a = *(const float4*)&TsT[d][t0];
            float4 bb = *(const float4*)&KsT[d][s0];
            float av[4] = {a.x, a.y, a.z, a.w};
            float bv[4] = {bb.x, bb.y, bb.z, bb.w};
            #pragma unroll
            for (int i = 0; i < 4; i++)
                #pragma unroll
                for (int j = 0; j < 4; j++)
                    acc[i][j] += av[i] * bv[j];
        }
        #pragma unroll
        for (int i = 0; i < 4; i++)
            #pragma unroll
            for (int j = 0; j < 4; j++) {
                int t = t0 + i, s = s0 + j;
                AT[s][t] = (s <= t) ? acc[i][j] : 0.f;
            }
    }
    __syncthreads();

    if (tid < 128) {
        int t = tid >> 1, half = tid & 1;
        float sd = 0.f;
        int lo = half * 32;
        #pragma unroll 8
        for (int s = lo; s < lo + 32; s++) sd += AT[s][t];
        #pragma unroll 8
        for (int d = lo; d < lo + 32; d++) sd += TsT[d][t] * kcpe[d];
        sd += __shfl_xor_sync(0xffffffffu, sd, 1);
        if (!half) den[t] = 1.0f / sd;
    }
    __syncthreads();

    {
        const int e0 = tx * 4;
        float o[4][4] = {};
        #pragma unroll 8
        for (int s = 0; s < CC; s++) {
            float4 a = *(const float4*)&AT[s][t0];
            float4 bb = *(const float4*)&Vs[s][e0];
            float av[4] = {a.x, a.y, a.z, a.w};
            float bv[4] = {bb.x, bb.y, bb.z, bb.w};
            #pragma unroll
            for (int i = 0; i < 4; i++)
                #pragma unroll
                for (int j = 0; j < 4; j++)
                    o[i][j] += av[i] * bv[j];
        }
        #pragma unroll 8
        for (int d = 0; d < HE; d++) {
            float4 a = *(const float4*)&TsT[d][t0];
            float4 bb = *(const float4*)&SpS[d][e0];
            float av[4] = {a.x, a.y, a.z, a.w};
            float bv[4] = {bb.x, bb.y, bb.z, bb.w};
            #pragma unroll
            for (int i = 0; i < 4; i++)
                #pragma unroll
                for (int j = 0; j < 4; j++)
                    o[i][j] += av[i] * bv[j];
        }
        float* ob = out + (size_t)b * SEQN * DIM + (size_t)c * CC * DIM + h * HE;
        #pragma unroll
        for (int i = 0; i < 4; i++) {
            float rcp = den[t0 + i];
            float4 ov = {o[i][0] * rcp, o[i][1] * rcp, o[i][2] * rcp, o[i][3] * rcp};
            *(float4*)(ob + (size_t)(t0 + i) * DIM + e0) = ov;
        }
    }
}

// ---------------- residual + layernorm (+ optional fp16 out) -----------------
__global__ void ln_res_kernel(const float* __restrict__ a, const float* __restrict__ r,
                              const float* __restrict__ g, const float* __restrict__ beta,
                              float* __restrict__ out, __half* __restrict__ oh)
{
    const int row = blockIdx.x;
    const int tid = threadIdx.x;
    const int w = tid >> 5, lane = tid & 31;
    __shared__ float red[16];

    float pre[2], sum = 0.f, sumsq = 0.f;
    #pragma unroll
    for (int it = 0; it < 2; it++) {
        int o = tid + it * 256;
        float p = a[(size_t)row * DIM + o] + r[(size_t)row * DIM + o];
        pre[it] = p; sum += p; sumsq += p * p;
    }
    #pragma unroll
    for (int o = 16; o > 0; o >>= 1) {
        sum   += __shfl_xor_sync(0xffffffffu, sum, o);
        sumsq += __shfl_xor_sync(0xffffffffu, sumsq, o);
    }
    if (lane == 0) { red[w] = sum; red[8 + w] = sumsq; }
    __syncthreads();
    if (tid == 0) {
        float s = 0.f, q = 0.f;
        #pragma unroll
        for (int i = 0; i < 8; i++) { s += red[i]; q += red[8 + i]; }
        float mu = s / (float)DIM;
        float var = q / (float)DIM - mu * mu;
        red[0] = mu; red[1] = rsqrtf(var + LN_EPS);
    }
    __syncthreads();
    float mu = red[0], rstd = red[1];
    #pragma unroll
    for (int it = 0; it < 2; it++) {
        int o = tid + it * 256;
        float v = (pre[it] - mu) * rstd * g[o] + beta[o];
        out[(size_t)row * DIM + o] = v;
        if (oh) oh[(size_t)row * DIM + o] = __float2half_rn(v);
    }
}

// ---------------- cross-attn: per-column softmax stats -----------------------
__global__ void col_stats_kernel(const float* __restrict__ kv,
                                 float* __restrict__ colmax, float* __restrict__ colsum)
{
    const int b = blockIdx.y;
    const int lane = threadIdx.x & 31;
    const int r = threadIdx.x >> 5;
    const int d = blockIdx.x * 32 + lane;
    const float* base = kv + (size_t)b * SEQM * (2 * DIM) + d;

    __shared__ float sm[8][32];
    __shared__ float cm[32];

    float m = -1e30f;
    for (int n = r; n < SEQM; n += 8) m = fmaxf(m, base[(size_t)n * (2 * DIM)]);
    sm[r][lane] = m;
    __syncthreads();
    if (threadIdx.x < 32) {
        float mm = sm[0][threadIdx.x];
        #pragma unroll
        for (int i = 1; i < 8; i++) mm = fmaxf(mm, sm[i][threadIdx.x]);
        cm[threadIdx.x] = mm;
        colmax[b * DIM + blockIdx.x * 32 + threadIdx.x] = mm;
    }
    __syncthreads();
    float s = 0.f;
    float mref = cm[lane];
    for (int n = r; n < SEQM; n += 8) s += expf(base[(size_t)n * (2 * DIM)] - mref);
    sm[r][lane] = s;
    __syncthreads();
    if (threadIdx.x < 32) {
        float ss = sm[0][threadIdx.x];
        #pragma unroll
        for (int i = 1; i < 8; i++) ss += sm[i][threadIdx.x];
        colsum[b * DIM + blockIdx.x * 32 + threadIdx.x] = ss;
    }
}

// ---------------- cross-attn: partial ctx over n-chunks ----------------------
__global__ void cross_ctx_kernel(const float* __restrict__ kv,
                                 const float* __restrict__ colmax, const float* __restrict__ colsum,
                                 float* __restrict__ ctxp)
{
    const int blk = blockIdx.x;
    const int bh = blk / NCH, ch = blk % NCH;
    const int b = bh >> 3, h = bh & 7;
    const int tid = threadIdx.x;
    const int tx = tid & 15, ty = tid >> 4;

    __shared__ __align__(16) float Ks[32][64];
    __shared__ __align__(16) float Vs[32][64];
    __shared__ float cm[64], ci[64];

    if (tid < 64) {
        cm[tid] = colmax[b * DIM + h * HE + tid];
        ci[tid] = 1.0f / colsum[b * DIM + h * HE + tid];
    }
    __syncthreads();

    float acc[4][4] = {};
    const float* base = kv + (size_t)b * SEQM * (2 * DIM) + h * HE;
    const int n_lo = ch * CHROWS, n_hi = n_lo + CHROWS;
    for (int n0 = n_lo; n0 < n_hi; n0 += 32) {
        #pragma unroll
        for (int it = 0; it < 2; it++) {
            int f4 = tid + it * 256;
            int r = f4 >> 4;
            int c = (f4 & 15) * 4;
            const float* rp = base + (size_t)(n0 + r) * (2 * DIM);
            float4 kk = *(const float4*)(rp + c);
            float4 vv = *(const float4*)(rp + DIM + c);
            Ks[r][c + 0] = expf(kk.x - cm[c + 0]) * ci[c + 0];
            Ks[r][c + 1] = expf(kk.y - cm[c + 1]) * ci[c + 1];
            Ks[r][c + 2] = expf(kk.z - cm[c + 2]) * ci[c + 2];
            Ks[r][c + 3] = expf(kk.w - cm[c + 3]) * ci[c + 3];
            *(float4*)&Vs[r][c] = vv;
        }
        __syncthreads();
        #pragma unroll
        for (int r = 0; r < 32; r++) {
            float4 av = *(const float4*)&Ks[r][ty * 4];
            float4 bv = *(const float4*)&Vs[r][tx * 4];
            float a[4] = {av.x, av.y, av.z, av.w};
            float bb[4] = {bv.x, bv.y, bv.z, bv.w};
            #pragma unroll
            for (int i = 0; i < 4; i++)
                #pragma unroll
                for (int j = 0; j < 4; j++)
                    acc[i][j] += a[i] * bb[j];
        }
        __syncthreads();
    }
    float* cb = ctxp + (size_t)blk * (HE * HE);
    #pragma unroll
    for (int i = 0; i < 4; i++)
        #pragma unroll
        for (int j = 0; j < 4; j++)
            cb[(ty * 4 + i) * HE + tx * 4 + j] = acc[i][j];
}

__global__ void ctx_reduce_kernel(const float* __restrict__ ctxp, float* __restrict__ ctx)
{
    const int bh = blockIdx.x;
    const int tid = threadIdx.x;
    size_t o = (size_t)tid * 16;
    float4 s[4];
    #pragma unroll
    for (int i = 0; i < 4; i++) s[i] = make_float4(0.f, 0.f, 0.f, 0.f);
    #pragma unroll
    for (int ch = 0; ch < NCH; ch++) {
        const float4* src = (const float4*)(ctxp + ((size_t)bh * NCH + ch) * (HE * HE) + o);
        #pragma unroll
        for (int i = 0; i < 4; i++) {
            float4 v = src[i];
            s[i].x += v.x; s[i].y += v.y; s[i].z += v.z; s[i].w += v.w;
        }
    }
    float4* dst = (float4*)(ctx + (size_t)bh * (HE * HE) + o);
    #pragma unroll
    for (int i = 0; i < 4; i++) dst[i] = s[i];
}

// ---------------- cross-attn output + residual + LN2 (+ fp16 out) -----------
__global__ void cross_out_ln2_kernel(const float* __restrict__ q2, const float* __restrict__ ctx,
                                     const float* __restrict__ res, const float* __restrict__ g,
                                     const float* __restrict__ beta, float* __restrict__ out,
                                     __half* __restrict__ oh)
{
    const int row = blockIdx.x;
    const int b = row >> 11;
    const int tid = threadIdx.x;
    const int w = tid >> 5, lane = tid & 31;

    __shared__ float qs_s[DIM];
    __shared__ float red[16];

    const float* qr = q2 + (size_t)row * DIM;
    {
        float a0 = qr[w * HE + lane], a1 = qr[w * HE + 32 + lane];
        float m = fmaxf(a0, a1);
        #pragma unroll
        for (int o = 16; o > 0; o >>= 1) m = fmaxf(m, __shfl_xor_sync(0xffffffffu, m, o));
        float t0 = expf(a0 - m), t1 = expf(a1 - m);
        float s = t0 + t1;
        #pragma unroll
        for (int o = 16; o > 0; o >>= 1) s += __shfl_xor_sync(0xffffffffu, s, o);
        float sc = 0.125f / s;
        qs_s[w * HE + lane] = t0 * sc;
        qs_s[w * HE + 32 + lane] = t1 * sc;
    }
    __syncthreads();

    float pre[2], sum = 0.f, sumsq = 0.f;
    #pragma unroll
    for (int it = 0; it < 2; it++) {
        int o = tid + it * 256;
        int h = o >> 6, e = o & 63;
        const float* cb = ctx + ((size_t)(b * NH + h)) * (HE * HE) + e;
        const float* qh = qs_s + h * HE;
        float acc = 0.f;
        #pragma unroll 8
        for (int d = 0; d < HE; d++) acc += qh[d] * cb[d * HE];
        float p = acc + res[(size_t)row * DIM + o];
        pre[it] = p; sum += p; sumsq += p * p;
    }
    #pragma unroll
    for (int o = 16; o > 0; o >>= 1) {
        sum   += __shfl_xor_sync(0xffffffffu, sum, o);
        sumsq += __shfl_xor_sync(0xffffffffu, sumsq, o);
    }
    if (lane == 0) { red[w] = sum; red[8 + w] = sumsq; }
    __syncthreads();
    if (tid == 0) {
        float s = 0.f, q = 0.f;
        #pragma unroll
        for (int i = 0; i < 8; i++) { s += red[i]; q += red[8 + i]; }
        float mu = s / (float)DIM;
        float var = q / (float)DIM - mu * mu;
        red[0] = mu; red[1] = rsqrtf(var + LN_EPS);
    }
    __syncthreads();
    float mu = red[0], rstd = red[1];
    #pragma unroll
    for (int it = 0; it < 2; it++) {
        int o = tid + it * 256;
        float v = (pre[it] - mu) * rstd * g[o] + beta[o];
        out[(size_t)row * DIM + o] = v;
        oh[(size_t)row * DIM + o] = __float2half_rn(v);
    }
}

// ---------------- host launch ------------------------------------------------
extern "C" void kernel_launch(void* const* d_in, const int* in_sizes, int n_in,
                              void* d_out, int out_size)
{
    const float* x      = (const float*)d_in[0];
    const float* memory = (const float*)d_in[1];
    const float* W_qvk  = (const float*)d_in[2];
    const float* b_qvk  = (const float*)d_in[3];
    const float* W_kv   = (const float*)d_in[4];
    const float* b_kv   = (const float*)d_in[5];
    const float* W_q    = (const float*)d_in[6];
    const float* b_q    = (const float*)d_in[7];
    const float* W_ff1  = (const float*)d_in[8];
    const float* b_ff1  = (const float*)d_in[9];
    const float* W_ff2  = (const float*)d_in[10];
    const float* b_ff2  = (const float*)d_in[11];
    const float* ln1_g  = (const float*)d_in[12];
    const float* ln1_b  = (const float*)d_in[13];
    const float* ln2_g  = (const float*)d_in[14];
    const float* ln2_b  = (const float*)d_in[15];
    const float* ln3_g  = (const float*)d_in[16];
    const float* ln3_b  = (const float*)d_in[17];
    float* outp = (float*)d_out;

    float *qvk, *attn1, *ln1, *kv, *q2, *colmax, *colsum, *ctxp, *ctx, *ln2, *pre3;
    float *csumK, *csumKV, *kcp, *Sp;
    __half *xh, *mh, *ln1h, *ln2h, *ff1h;
    __half *wqvkh, *wkvh, *wqh, *wf1h, *wf2h;
    cudaGetSymbolAddress((void**)&qvk,   g_qvk);
    cudaGetSymbolAddress((void**)&attn1, g_attn1);
    cudaGetSymbolAddress((void**)&ln1,   g_ln1);
    cudaGetSymbolAddress((void**)&kv,    g_kv);
    cudaGetSymbolAddress((void**)&q2,    g_q2);
    cudaGetSymbolAddress((void**)&colmax,g_colmax);
    cudaGetSymbolAddress((void**)&colsum,g_colsum);
    cudaGetSymbolAddress((void**)&ctxp,  g_ctxp);
    cudaGetSymbolAddress((void**)&ctx,   g_ctx);
    cudaGetSymbolAddress((void**)&ln2,   g_ln2);
    cudaGetSymbolAddress((void**)&pre3,  g_pre3);
    cudaGetSymbolAddress((void**)&csumK, g_csumK);
    cudaGetSymbolAddress((void**)&csumKV,g_csumKV);
    cudaGetSymbolAddress((void**)&kcp,   g_kcp);
    cudaGetSymbolAddress((void**)&Sp,    g_Sp);
    cudaGetSymbolAddress((void**)&xh,   g_xh);
    cudaGetSymbolAddress((void**)&mh,   g_mh);
    cudaGetSymbolAddress((void**)&ln1h, g_ln1h);
    cudaGetSymbolAddress((void**)&ln2h, g_ln2h);
    cudaGetSymbolAddress((void**)&ff1h, g_ff1h);
    cudaGetSymbolAddress((void**)&wqvkh,g_wqvkh);
    cudaGetSymbolAddress((void**)&wkvh, g_wkvh);
    cudaGetSymbolAddress((void**)&wqh,  g_wqh);
    cudaGetSymbolAddress((void**)&wf1h, g_wf1h);
    cudaGetSymbolAddress((void**)&wf2h, g_wf2h);

    const int CSMEM = (5 * 64 * 68 + 128) * (int)sizeof(float);
    cudaFuncSetAttribute(causal_chunk_kernel, cudaFuncAttributeMaxDynamicSharedMemorySize, CSMEM);
    cudaFuncSetAttribute(gemm_hf, cudaFuncAttributeMaxDynamicSharedMemorySize, GB_SMEM);

    // 0) batched fp32->fp16 conversion
    {
        ConvBatch cb;
        const float* srcs[NSEG] = {x, memory, W_qvk, W_kv, W_q, W_ff1, W_ff2};
        __half* his[NSEG] = {xh, mh, wqvkh, wkvh, wqh, wf1h, wf2h};
        int ns[NSEG] = {ROWS * DIM / 4, ROWS * DIM / 4, DIM * 3 * DIM / 4,
                        DIM * 2 * DIM / 4, DIM * DIM / 4, DIM * FF / 4, FF * DIM / 4};
        int acc_n = 0;
        for (int s = 0; s < NSEG; s++) {
            cb.src[s] = (const float4*)srcs[s];
            cb.hi[s] = (uint2*)his[s];
            acc_n += ns[s];
            cb.end[s] = acc_n;
        }
        conv_multi<<<(acc_n + 255) / 256, 256>>>(cb);
    }

    // 1) qvk = x @ W_qvk + b
    gemm_hf<<<dim3((3 * DIM) / 128, ROWS / 128), 256, GB_SMEM>>>(
        xh, wqvkh, b_qvk, qvk, nullptr, ROWS, 3 * DIM, DIM, 0);
    // 2) causal linear self-attention, chunk-parallel
    chunk_sum_kernel<<<BH * NC, 256>>>(qvk, csumK, csumKV);
    prefix_kernel<<<BH * 16, 256>>>(csumK, csumKV, kcp, Sp);
    causal_chunk_kernel<<<BH * NC, 256, CSMEM>>>(qvk, kcp, Sp, attn1);
    // 3) LN1(attn + x) -> fp32 + fp16
    ln_res_kernel<<<ROWS, 256>>>(attn1, x, ln1_g, ln1_b, ln1, ln1h);
    // 4) kv = memory @ W_kv + b
    gemm_hf<<<dim3((2 * DIM) / 128, ROWS / 128), 256, GB_SMEM>>>(
        mh, wkvh, b_kv, kv, nullptr, ROWS, 2 * DIM, DIM, 0);
    // 5) q2 = ln1 @ W_q + b
    gemm_hf<<<dim3(DIM / 128, ROWS / 128), 256, GB_SMEM>>>(
        ln1h, wqh, b_q, q2, nullptr, ROWS, DIM, DIM, 0);
    // 6) column softmax stats of k over memory rows
    col_stats_kernel<<<dim3(DIM / 32, BATCH), 256>>>(kv, colmax, colsum);
    // 7) ctx = softk^T @ v per head (n-chunked + reduce)
    cross_ctx_kernel<<<BH * NCH, 256>>>(kv, colmax, colsum, ctxp);
    ctx_reduce_kernel<<<BH, 256>>>(ctxp, ctx);
    // 8) out2 = softmax(q2) @ ctx, + res, LN2 (fused) -> fp32 + fp16
    cross_out_ln2_kernel<<<ROWS, 256>>>(q2, ctx, ln1, ln2_g, ln2_b, ln2, ln2h);
    // 9) ff1 = relu(ln2 @ W_ff1 + b) -> fp16 only
    gemm_hf<<<dim3(FF / 128, ROWS / 128), 256, GB_SMEM>>>(
        ln2h, wf1h, b_ff1, nullptr, ff1h, ROWS, FF, DIM, 1);
    // 10) pre3 = ff1 @ W_ff2 + b
    gemm_hf<<<dim3(DIM / 128, ROWS / 128), 256, GB_SMEM>>>(
        ff1h, wf2h, b_ff2, pre3, nullptr, ROWS, DIM, FF, 0);
    // 11) LN3(pre3 + ln2) -> output
    ln_res_kernel<<<ROWS, 256>>>(pre3, ln2, ln3_g, ln3_b, outp, nullptr);
}

// round 13
// speedup vs baseline: 9.3272x; 1.0250x over previous
#include <cuda_runtime.h>
#include <cuda_bf16.h>
#include <cuda_fp16.h>
#include <math.h>
#include <stdint.h>

// Problem dims
#define BATCH 2
#define SEQN 2048
#define SEQM 2048
#define DIM 512
#define NH 8
#define HE 64
#define FF 2048
#define ROWS (BATCH * SEQN)   // 4096
#define LN_EPS 1e-5f
#define ATTN_EPS 1e-6f

// chunked causal linear attention
#define CC 64
#define NC (SEQN / CC)        // 32
#define BH (BATCH * NH)       // 16
// cross-attn ctx n-split
#define NCH 8
#define CHROWS (SEQM / NCH)   // 256

// ---------------- scratch (device globals; no allocations allowed) ----------
__device__ float g_attn1[ROWS * DIM];
__device__ float g_ln1 [ROWS * DIM];
__device__ float g_q2  [ROWS * DIM];
__device__ float g_colmax[BATCH * DIM];
__device__ float g_colsum[BATCH * DIM];
__device__ float g_ctxp[BH * NCH * HE * HE];
__device__ float g_ctx [BH * HE * HE];
__device__ float g_ln2 [ROWS * DIM];
__device__ float g_pre3[ROWS * DIM];
// causal-chunk state
__device__ float g_csumK [BH * NC * HE];
__device__ float g_csumKV[BH * NC * HE * HE];
__device__ float g_kcp   [BH * NC * HE];
__device__ float g_Sp    [BH * NC * HE * HE];
// fp16 tensors
__device__ __half g_qvkh[ROWS * 3 * DIM];   // 12.5 MB
__device__ __half g_kvh [ROWS * 2 * DIM];   // 8 MB
__device__ __half g_xh [ROWS * DIM];
__device__ __half g_mh [ROWS * DIM];
__device__ __half g_ln1h[ROWS * DIM];
__device__ __half g_ln2h[ROWS * DIM];
__device__ __half g_ff1h[ROWS * FF];
__device__ __half g_wqvkh[DIM * 3 * DIM];
__device__ __half g_wkvh [DIM * 2 * DIM];
__device__ __half g_wqh  [DIM * DIM];
__device__ __half g_wf1h [DIM * FF];
__device__ __half g_wf2h [FF * DIM];

// ---------------- helpers ----------------------------------------------------
__device__ __forceinline__ uint32_t smem_u32(const void* p) {
    uint32_t a;
    asm("{ .reg .u64 t; cvta.to.shared.u64 t, %1; cvt.u32.u64 %0, t; }" : "=r"(a) : "l"(p));
    return a;
}
__device__ __forceinline__ void ldmat_x4(uint32_t& r0, uint32_t& r1, uint32_t& r2, uint32_t& r3,
                                         uint32_t addr) {
    asm volatile("ldmatrix.sync.aligned.m8n8.x4.shared.b16 {%0,%1,%2,%3}, [%4];"
                 : "=r"(r0), "=r"(r1), "=r"(r2), "=r"(r3) : "r"(addr));
}
__device__ __forceinline__ void ldmat_x4t(uint32_t& r0, uint32_t& r1, uint32_t& r2, uint32_t& r3,
                                          uint32_t addr) {
    asm volatile("ldmatrix.sync.aligned.m8n8.x4.trans.shared.b16 {%0,%1,%2,%3}, [%4];"
                 : "=r"(r0), "=r"(r1), "=r"(r2), "=r"(r3) : "r"(addr));
}
__device__ __forceinline__ void mma_f16(float* c, const uint32_t* a, const uint32_t* b) {
    asm volatile(
        "mma.sync.aligned.m16n8k16.row.col.f32.f16.f16.f32 "
        "{%0,%1,%2,%3}, {%4,%5,%6,%7}, {%8,%9}, {%0,%1,%2,%3};"
        : "+f"(c[0]), "+f"(c[1]), "+f"(c[2]), "+f"(c[3])
        : "r"(a[0]), "r"(a[1]), "r"(a[2]), "r"(a[3]), "r"(b[0]), "r"(b[1]));
}
#define CP_ASYNC16(dst, src) \
    asm volatile("cp.async.cg.shared.global [%0], [%1], 16;" :: "r"(dst), "l"(src) : "memory")
#define CP_COMMIT() asm volatile("cp.async.commit_group;" ::: "memory")

// ---------------- fp32 -> fp16 conversion, batched over 7 tensors -----------
#define NSEG 7
struct ConvBatch {
    const float4* src[NSEG];
    uint2* hi[NSEG];
    int end[NSEG];
};
__global__ void conv_multi(ConvBatch cb)
{
    int i = blockIdx.x * blockDim.x + threadIdx.x;
    if (i >= cb.end[NSEG - 1]) return;
    int s = 0;
    #pragma unroll
    for (int k = 0; k < NSEG - 1; k++) s += (i >= cb.end[k]);
    int j = i - (s ? cb.end[s - 1] : 0);
    float4 f = cb.src[s][j];
    __half2 ha = {__float2half_rn(f.x), __float2half_rn(f.y)};
    __half2 hb = {__float2half_rn(f.z), __float2half_rn(f.w)};
    cb.hi[s][j] = make_uint2(*(uint32_t*)&ha, *(uint32_t*)&hb);
}

// ================= fp16 tensor-core GEMM, 3-stage cp.async ===================
#define OFF_BH 10240      // A: 128 rows * 80B; B: 32 rows * 272B
#define PIPE_STAGE 18944
#define GB_SMEM (3 * PIPE_STAGE)   // 56,832 B

__global__ __launch_bounds__(256)
void gemm_hf(const __half* __restrict__ Ah, const __half* __restrict__ Bh,
             const float* __restrict__ bias, float* __restrict__ Cf,
             __half* __restrict__ Ch,
             int M, int N, int K, int relu)
{
    extern __shared__ char smc[];
    const uint32_t sb = smem_u32(smc);
    const int tid = threadIdx.x;
    const int lane = tid & 31, wid = tid >> 5;
    const int wm = (wid >> 2) * 64;
    const int wn = (wid & 3) * 32;
    const int row0 = blockIdx.y * 128, col0 = blockIdx.x * 128;

    const int a_r = tid >> 2, a_c = (tid & 3) * 16;
    const int a_r2 = (tid + 256) >> 2, a_c2 = ((tid + 256) & 3) * 16;
    const int b_kr = tid >> 4, b_c = (tid & 15) * 16;
    const int b_kr2 = (tid + 256) >> 4, b_c2 = ((tid + 256) & 15) * 16;

    float acc[4][4][4] = {};

    const int la_row  = wm + (lane & 15);
    const int la_colb = (lane >> 4) * 8;
    const int lb_row  = (lane & 7) + ((lane >> 3) & 1) * 8;
    const int lb_colb = wn + (lane >> 4) * 8;

    const int nblk = K / 32;

    #define PREFETCH(kb_, st_) do {                                                              \
        const int kq = (kb_) * 32;                                                               \
        uint32_t st = sb + (st_) * PIPE_STAGE;                                                   \
        CP_ASYNC16(st + a_r * 80 + a_c, Ah + (size_t)(row0 + a_r) * K + kq + a_c / 2);           \
        CP_ASYNC16(st + a_r2 * 80 + a_c2, Ah + (size_t)(row0 + a_r2) * K + kq + a_c2 / 2);       \
        CP_ASYNC16(st + OFF_BH + b_kr * 272 + b_c, Bh + (size_t)(kq + b_kr) * N + col0 + b_c / 2);\
        CP_ASYNC16(st + OFF_BH + b_kr2 * 272 + b_c2, Bh + (size_t)(kq + b_kr2) * N + col0 + b_c2 / 2);\
        CP_COMMIT();                                                                             \
    } while (0)

    PREFETCH(0, 0);
    if (nblk > 1) PREFETCH(1, 1);

    for (int kb = 0; kb < nblk; kb++) {
        if (kb + 1 < nblk) asm volatile("cp.async.wait_group 1;" ::: "memory");
        else               asm volatile("cp.async.wait_group 0;" ::: "memory");
        __syncthreads();
        if (kb + 2 < nblk) PREFETCH(kb + 2, (kb + 2) % 3);

        const uint32_t st = sb + (kb % 3) * PIPE_STAGE;
        #pragma unroll
        for (int ks = 0; ks < 2; ks++) {
            uint32_t ah[4][4], bf[4][2];
            #pragma unroll
            for (int mt = 0; mt < 4; mt++) {
                uint32_t off = (uint32_t)((la_row + mt * 16) * 40 + ks * 16 + la_colb) * 2;
                ldmat_x4(ah[mt][0], ah[mt][1], ah[mt][2], ah[mt][3], st + off);
            }
            #pragma unroll
            for (int p = 0; p < 2; p++) {
                uint32_t off = (uint32_t)((ks * 16 + lb_row) * 136 + lb_colb + p * 16) * 2;
                ldmat_x4t(bf[p * 2][0], bf[p * 2][1], bf[p * 2 + 1][0], bf[p * 2 + 1][1],
                          st + OFF_BH + off);
            }
            #pragma unroll
            for (int mt = 0; mt < 4; mt++)
                #pragma unroll
                for (int nt = 0; nt < 4; nt++)
                    mma_f16(acc[mt][nt], ah[mt], bf[nt]);
        }
    }

    const int r_l = lane >> 2, c_l = (lane & 3) * 2;
    #pragma unroll
    for (int mt = 0; mt < 4; mt++) {
        int row = row0 + wm + mt * 16 + r_l;
        #pragma unroll
        for (int nt = 0; nt < 4; nt++) {
            int col = col0 + wn + nt * 8 + c_l;
            float b0 = bias[col], b1 = bias[col + 1];
            float v00 = acc[mt][nt][0] + b0, v01 = acc[mt][nt][1] + b1;
            float v10 = acc[mt][nt][2] + b0, v11 = acc[mt][nt][3] + b1;
            if (relu) {
                v00 = fmaxf(v00, 0.f); v01 = fmaxf(v01, 0.f);
                v10 = fmaxf(v10, 0.f); v11 = fmaxf(v11, 0.f);
            }
            if (Cf) {
                *(float2*)(Cf + (size_t)row * N + col) = make_float2(v00, v01);
                *(float2*)(Cf + (size_t)(row + 8) * N + col) = make_float2(v10, v11);
            }
            if (Ch) {
                __half2 hp0 = {__float2half_rn(v00), __float2half_rn(v01)};
                __half2 hp1 = {__float2half_rn(v10), __float2half_rn(v11)};
                *(__half2*)(Ch + (size_t)row * N + col) = hp0;
                *(__half2*)(Ch + (size_t)(row + 8) * N + col) = hp1;
            }
        }
    }
}

// ---------------- causal chunk phase 1: per-chunk sums (fp16 in) ------------
__global__ __launch_bounds__(256)
void chunk_sum_kernel(const __half* __restrict__ qvk,
                      float* __restrict__ csumK, float* __restrict__ csumKV)
{
    const int blk = blockIdx.x;
    const int bh = blk / NC, c = blk % NC;
    const int b = bh >> 3, h = bh & 7;
    const int tid = threadIdx.x;

    __shared__ __align__(16) float Ks[CC][68];
    __shared__ __align__(16) float Vs[CC][68];

    const __half* base = qvk + (size_t)b * SEQN * (3 * DIM) + (size_t)c * CC * (3 * DIM) + h * HE;
    #pragma unroll
    for (int i = tid; i < CC * 16; i += 256) {
        int r = i >> 4;
        int col = (i & 15) * 4;
        const __half* rp = base + (size_t)r * (3 * DIM);
        __half2 k01 = *(const __half2*)(rp + 2 * DIM + col);
        __half2 k23 = *(const __half2*)(rp + 2 * DIM + col + 2);
        __half2 v01 = *(const __half2*)(rp + DIM + col);
        __half2 v23 = *(const __half2*)(rp + DIM + col + 2);
        Ks[r][col + 0] = expf(__half2float(k01.x)); Ks[r][col + 1] = expf(__half2float(k01.y));
        Ks[r][col + 2] = expf(__half2float(k23.x)); Ks[r][col + 3] = expf(__half2float(k23.y));
        Vs[r][col + 0] = __half2float(v01.x); Vs[r][col + 1] = __half2float(v01.y);
        Vs[r][col + 2] = __half2float(v23.x); Vs[r][col + 3] = __half2float(v23.y);
    }
    __syncthreads();

    const int ty = tid >> 4, tx = tid & 15;
    const int d0 = ty * 4, e0 = tx * 4;
    float acc[4][4] = {};
    #pragma unroll 8
    for (int n = 0; n < CC; n++) {
        float4 a = *(const float4*)&Ks[n][d0];
        float4 bb = *(const float4*)&Vs[n][e0];
        float av[4] = {a.x, a.y, a.z, a.w};
        float bv[4] = {bb.x, bb.y, bb.z, bb.w};
        #pragma unroll
        for (int i = 0; i < 4; i++)
            #pragma unroll
            for (int j = 0; j < 4; j++)
                acc[i][j] += av[i] * bv[j];
    }
    float* outKV = csumKV + ((size_t)bh * NC + c) * (HE * HE);
    #pragma unroll
    for (int i = 0; i < 4; i++) {
        float4 o = {acc[i][0], acc[i][1], acc[i][2], acc[i][3]};
        *(float4*)(outKV + (d0 + i) * HE + e0) = o;
    }
    if (tid < HE) {
        float s = 0.f;
        #pragma unroll 8
        for (int n = 0; n < CC; n++) s += Ks[n][tid];
        csumK[((size_t)bh * NC + c) * HE + tid] = s;
    }
}

// ---------------- causal chunk phase 2: exclusive prefix (parallel) ---------
__global__ __launch_bounds__(256)
void prefix_kernel(const float* __restrict__ csumK, const float* __restrict__ csumKV,
                   float* __restrict__ kcp, float* __restrict__ Sp)
{
    const int blk = blockIdx.x;
    const int bh = blk >> 4, seg = blk & 15;
    const int e = seg * 256 + threadIdx.x;
    const size_t stride = (size_t)(HE * HE);
    const float* src = csumKV + (size_t)bh * NC * stride + e;
    float v[NC];
    #pragma unroll
    for (int c = 0; c < NC; c++) v[c] = src[(size_t)c * stride];
    float* dst = Sp + (size_t)bh * NC * stride + e;
    float run = 0.f;
    #pragma unroll
    for (int c = 0; c < NC; c++) { dst[(size_t)c * stride] = run; run += v[c]; }

    if (seg == 0 && threadIdx.x < HE) {
        const int d = threadIdx.x;
        float vk[NC];
        #pragma unroll
        for (int c = 0; c < NC; c++) vk[c] = csumK[((size_t)bh * NC + c) * HE + d];
        float rk = 0.f;
        #pragma unroll
        for (int c = 0; c < NC; c++) { kcp[((size_t)bh * NC + c) * HE + d] = rk; rk += vk[c]; }
    }
}

// ---------------- causal chunk phase 3: per-chunk output (fp16 in) ----------
// smem: 4 x 64x68 fp32 arrays (A_masked aliases KsT after a barrier) = 70,144 B
// -> 3 CTAs/SM.
__global__ __launch_bounds__(256)
void causal_chunk_kernel(const __half* __restrict__ qvk,
                         const float* __restrict__ kcp, const float* __restrict__ Sp,
                         float* __restrict__ out)
{
    extern __shared__ __align__(16) float sm[];
    float (*TsT)[68] = (float(*)[68])sm;
    float (*KsT)[68] = TsT + 64;
    float (*Vs)[68]  = KsT + 64;
    float (*SpS)[68] = Vs + 64;
    float* kcpe = (float*)(SpS + 64);
    float* den  = kcpe + 64;
    float (*AT)[68] = KsT;     // aliased: valid only after the post-GEMM barrier

    const int blk = blockIdx.x;
    const int bh = blk / NC, c = blk % NC;
    const int b = bh >> 3, h = bh & 7;
    const int tid = threadIdx.x;
    const __half* base = qvk + (size_t)b * SEQN * (3 * DIM) + (size_t)c * CC * (3 * DIM) + h * HE;

    {
        int r = tid >> 2;
        int g = tid & 3;
        const __half* rp = base + (size_t)r * (3 * DIM) + g * 16;
        float qv[16];
        float m = -1e30f;
        #pragma unroll
        for (int j = 0; j < 8; j++) {
            __half2 q2v = *(const __half2*)(rp + 2 * j);
            qv[2 * j] = __half2float(q2v.x); qv[2 * j + 1] = __half2float(q2v.y);
            m = fmaxf(m, fmaxf(qv[2 * j], qv[2 * j + 1]));
        }
        m = fmaxf(m, __shfl_xor_sync(0xffffffffu, m, 1));
        m = fmaxf(m, __shfl_xor_sync(0xffffffffu, m, 2));
        #pragma unroll
        for (int j = 0; j < 16; j++) TsT[g * 16 + j][r] = expf(qv[j] - m);
        const __half* rpk = rp + 2 * DIM;
        #pragma unroll
        for (int j = 0; j < 8; j++) {
            __half2 k2v = *(const __half2*)(rpk + 2 * j);
            KsT[g * 16 + 2 * j][r] = expf(__half2float(k2v.x));
            KsT[g * 16 + 2 * j + 1][r] = expf(__half2float(k2v.y));
        }
    }
    #pragma unroll
    for (int i = tid; i < CC * 16; i += 256) {
        int r = i >> 4, col = (i & 15) * 4;
        const __half* vp = base + (size_t)r * (3 * DIM) + DIM + col;
        __half2 v01 = *(const __half2*)(vp);
        __half2 v23 = *(const __half2*)(vp + 2);
        Vs[r][col + 0] = __half2float(v01.x); Vs[r][col + 1] = __half2float(v01.y);
        Vs[r][col + 2] = __half2float(v23.x); Vs[r][col + 3] = __half2float(v23.y);
    }
    const float* spb = Sp + ((size_t)bh * NC + c) * (HE * HE);
    #pragma unroll
    for (int i = tid; i < HE * 16; i += 256) {
        int r = i >> 4, col = (i & 15) * 4;
        *(float4*)&SpS[r][col] = *(const float4*)(spb + r * HE + col);
    }
    if (tid < HE) kcpe[tid] = kcp[((size_t)bh * NC + c) * HE + tid] + ATTN_EPS;
    __syncthreads();

    const int ty = tid >> 4, tx = tid & 15;
    const int t0 = ty * 4, s0 = tx * 4;

    float acc[4][4];
    {
        #pragma unroll
        for (int i = 0; i < 4; i++)
            #pragma unroll
            for (int j = 0; j < 4; j++) acc[i][j] = 0.f;
        #pragma unroll 8
        for (int d = 0; d < HE; d++) {
            float4 a = *(const float4*)&TsT[d][t0];
            float4 bb = *(const float4*)&KsT[d][s0];
            float av[4] = {a.x, a.y, a.z, a.w};
            float bv[4] = {bb.x, bb.y, bb.z, bb.w};
            #pragma unroll
            for (int i = 0; i < 4; i++)
                #pragma unroll
                for (int j = 0; j < 4; j++)
                    acc[i][j] += av[i] * bv[j];
        }
    }
    __syncthreads();   // all reads of KsT complete before aliasing as AT
    #pragma unroll
    for (int i = 0; i < 4; i++)
        #pragma unroll
        for (int j = 0; j < 4; j++) {
            int t = t0 + i, s = s0 + j;
            AT[s][t] = (s <= t) ? acc[i][j] : 0.f;
        }
    __syncthreads();

    if (tid < 128) {
        int t = tid >> 1, half = tid & 1;
        float sd = 0.f;
        int lo = half * 32;
        #pragma unroll 8
        for (int s = lo; s < lo + 32; s++) sd += AT[s][t];
        #pragma unroll 8
        for (int d = lo; d < lo + 32; d++) sd += TsT[d][t] * kcpe[d];
        sd += __shfl_xor_sync(0xffffffffu, sd, 1);
        if (!half) den[t] = 1.0f / sd;
    }
    __syncthreads();

    {
        const int e0 = tx * 4;
        float o[4][4] = {};
        #pragma unroll 8
        for (int s = 0; s < CC; s++) {
            float4 a = *(const float4*)&AT[s][t0];
            float4 bb = *(const float4*)&Vs[s][e0];
            float av[4] = {a.x, a.y, a.z, a.w};
            float bv[4] = {bb.x, bb.y, bb.z, bb.w};
            #pragma unroll
            for (int i = 0; i < 4; i++)
                #pragma unroll
                for (int j = 0; j < 4; j++)
                    o[i][j] += av[i] * bv[j];
        }
        #pragma unroll 8
        for (int d = 0; d < HE; d++) {
            float4 a = *(const float4*)&TsT[d][t0];
            float4 bb = *(const float4*)&SpS[d][e0];
            float av[4] = {a.x, a.y, a.z, a.w};
            float bv[4] = {bb.x, bb.y, bb.z, bb.w};
            #pragma unroll
            for (int i = 0; i < 4; i++)
                #pragma unroll
                for (int j = 0; j < 4; j++)
                    o[i][j] += av[i] * bv[j];
        }
        float* ob = out + (size_t)b * SEQN * DIM + (size_t)c * CC * DIM + h * HE;
        #pragma unroll
        for (int i = 0; i < 4; i++) {
            float rcp = den[t0 + i];
            float4 ov = {o[i][0] * rcp, o[i][1] * rcp, o[i][2] * rcp, o[i][3] * rcp};
            *(float4*)(ob + (size_t)(t0 + i) * DIM + e0) = ov;
        }
    }
}

// ---------------- residual + layernorm (+ optional fp16 out) -----------------
__global__ void ln_res_kernel(const float* __restrict__ a, const float* __restrict__ r,
                              const float* __restrict__ g, const float* __restrict__ beta,
                              float* __restrict__ out, __half* __restrict__ oh)
{
    const int row = blockIdx.x;
    const int tid = threadIdx.x;
    const int w = tid >> 5, lane = tid & 31;
    __shared__ float red[16];

    float pre[2], sum = 0.f, sumsq = 0.f;
    #pragma unroll
    for (int it = 0; it < 2; it++) {
        int o = tid + it * 256;
        float p = a[(size_t)row * DIM + o] + r[(size_t)row * DIM + o];
        pre[it] = p; sum += p; sumsq += p * p;
    }
    #pragma unroll
    for (int o = 16; o > 0; o >>= 1) {
        sum   += __shfl_xor_sync(0xffffffffu, sum, o);
        sumsq += __shfl_xor_sync(0xffffffffu, sumsq, o);
    }
    if (lane == 0) { red[w] = sum; red[8 + w] = sumsq; }
    __syncthreads();
    if (tid == 0) {
        float s = 0.f, q = 0.f;
        #pragma unroll
        for (int i = 0; i < 8; i++) { s += red[i]; q += red[8 + i]; }
        float mu = s / (float)DIM;
        float var = q / (float)DIM - mu * mu;
        red[0] = mu; red[1] = rsqrtf(var + LN_EPS);
    }
    __syncthreads();
    float mu = red[0], rstd = red[1];
    #pragma unroll
    for (int it = 0; it < 2; it++) {
        int o = tid + it * 256;
        float v = (pre[it] - mu) * rstd * g[o] + beta[o];
        out[(size_t)row * DIM + o] = v;
        if (oh) oh[(size_t)row * DIM + o] = __float2half_rn(v);
    }
}

// ---------------- cross-attn: per-column softmax stats (fp16 in) ------------
__global__ void col_stats_kernel(const __half* __restrict__ kv,
                                 float* __restrict__ colmax, float* __restrict__ colsum)
{
    const int b = blockIdx.y;
    const int lane = threadIdx.x & 31;
    const int r = threadIdx.x >> 5;
    const int d = blockIdx.x * 32 + lane;
    const __half* base = kv + (size_t)b * SEQM * (2 * DIM) + d;

    __shared__ float sm[8][32];
    __shared__ float cm[32];

    float m = -1e30f;
    for (int n = r; n < SEQM; n += 8) m = fmaxf(m, __half2float(base[(size_t)n * (2 * DIM)]));
    sm[r][lane] = m;
    __syncthreads();
    if (threadIdx.x < 32) {
        float mm = sm[0][threadIdx.x];
        #pragma unroll
        for (int i = 1; i < 8; i++) mm = fmaxf(mm, sm[i][threadIdx.x]);
        cm[threadIdx.x] = mm;
        colmax[b * DIM + blockIdx.x * 32 + threadIdx.x] = mm;
    }
    __syncthreads();
    float s = 0.f;
    float mref = cm[lane];
    for (int n = r; n < SEQM; n += 8) s += expf(__half2float(base[(size_t)n * (2 * DIM)]) - mref);
    sm[r][lane] = s;
    __syncthreads();
    if (threadIdx.x < 32) {
        float ss = sm[0][threadIdx.x];
        #pragma unroll
        for (int i = 1; i < 8; i++) ss += sm[i][threadIdx.x];
        colsum[b * DIM + blockIdx.x * 32 + threadIdx.x] = ss;
    }
}

// ---------------- cross-attn: partial ctx over n-chunks (fp16 in) -----------
__global__ void cross_ctx_kernel(const __half* __restrict__ kv,
                                 const float* __restrict__ colmax, const float* __restrict__ colsum,
                                 float* __restrict__ ctxp)
{
    const int blk = blockIdx.x;
    const int bh = blk / NCH, ch = blk % NCH;
    const int b = bh >> 3, h = bh & 7;
    const int tid = threadIdx.x;
    const int tx = tid & 15, ty = tid >> 4;

    __shared__ __align__(16) float Ks[32][64];
    __shared__ __align__(16) float Vs[32][64];
    __shared__ float cm[64], ci[64];

    if (tid < 64) {
        cm[tid] = colmax[b * DIM + h * HE + tid];
        ci[tid] = 1.0f / colsum[b * DIM + h * HE + tid];
    }
    __syncthreads();

    float acc[4][4] = {};
    const __half* base = kv + (size_t)b * SEQM * (2 * DIM) + h * HE;
    const int n_lo = ch * CHROWS, n_hi = n_lo + CHROWS;
    for (int n0 = n_lo; n0 < n_hi; n0 += 32) {
        #pragma unroll
        for (int it = 0; it < 2; it++) {
            int f4 = tid + it * 256;
            int r = f4 >> 4;
            int c = (f4 & 15) * 4;
            const __half* rp = base + (size_t)(n0 + r) * (2 * DIM);
            __half2 k01 = *(const __half2*)(rp + c);
            __half2 k23 = *(const __half2*)(rp + c + 2);
            __half2 v01 = *(const __half2*)(rp + DIM + c);
            __half2 v23 = *(const __half2*)(rp + DIM + c + 2);
            Ks[r][c + 0] = expf(__half2float(k01.x) - cm[c + 0]) * ci[c + 0];
            Ks[r][c + 1] = expf(__half2float(k01.y) - cm[c + 1]) * ci[c + 1];
            Ks[r][c + 2] = expf(__half2float(k23.x) - cm[c + 2]) * ci[c + 2];
            Ks[r][c + 3] = expf(__half2float(k23.y) - cm[c + 3]) * ci[c + 3];
            Vs[r][c + 0] = __half2float(v01.x); Vs[r][c + 1] = __half2float(v01.y);
            Vs[r][c + 2] = __half2float(v23.x); Vs[r][c + 3] = __half2float(v23.y);
        }
        __syncthreads();
        #pragma unroll
        for (int r = 0; r < 32; r++) {
            float4 av = *(const float4*)&Ks[r][ty * 4];
            float4 bv = *(const float4*)&Vs[r][tx * 4];
            float a[4] = {av.x, av.y, av.z, av.w};
            float bb[4] = {bv.x, bv.y, bv.z, bv.w};
            #pragma unroll
            for (int i = 0; i < 4; i++)
                #pragma unroll
                for (int j = 0; j < 4; j++)
                    acc[i][j] += a[i] * bb[j];
        }
        __syncthreads();
    }
    float* cb = ctxp + (size_t)blk * (HE * HE);
    #pragma unroll
    for (int i = 0; i < 4; i++)
        #pragma unroll
        for (int j = 0; j < 4; j++)
            cb[(ty * 4 + i) * HE + tx * 4 + j] = acc[i][j];
}

__global__ void ctx_reduce_kernel(const float* __restrict__ ctxp, float* __restrict__ ctx)
{
    const int bh = blockIdx.x;
    const int tid = threadIdx.x;
    size_t o = (size_t)tid * 16;
    float4 s[4];
    #pragma unroll
    for (int i = 0; i < 4; i++) s[i] = make_float4(0.f, 0.f, 0.f, 0.f);
    #pragma unroll
    for (int ch = 0; ch < NCH; ch++) {
        const float4* src = (const float4*)(ctxp + ((size_t)bh * NCH + ch) * (HE * HE) + o);
        #pragma unroll
        for (int i = 0; i < 4; i++) {
            float4 v = src[i];
            s[i].x += v.x; s[i].y += v.y; s[i].z += v.z; s[i].w += v.w;
        }
    }
    float4* dst = (float4*)(ctx + (size_t)bh * (HE * HE) + o);
    #pragma unroll
    for (int i = 0; i < 4; i++) dst[i] = s[i];
}

// ---------------- cross-attn output + residual + LN2 (+ fp16 out) -----------
__global__ void cross_out_ln2_kernel(const float* __restrict__ q2, const float* __restrict__ ctx,
                                     const float* __restrict__ res, const float* __restrict__ g,
                                     const float* __restrict__ beta, float* __restrict__ out,
                                     __half* __restrict__ oh)
{
    const int row = blockIdx.x;
    const int b = row >> 11;
    const int tid = threadIdx.x;
    const int w = tid >> 5, lane = tid & 31;

    __shared__ float qs_s[DIM];
    __shared__ float red[16];

    const float* qr = q2 + (size_t)row * DIM;
    {
        float a0 = qr[w * HE + lane], a1 = qr[w * HE + 32 + lane];
        float m = fmaxf(a0, a1);
        #pragma unroll
        for (int o = 16; o > 0; o >>= 1) m = fmaxf(m, __shfl_xor_sync(0xffffffffu, m, o));
        float t0 = expf(a0 - m), t1 = expf(a1 - m);
        float s = t0 + t1;
        #pragma unroll
        for (int o = 16; o > 0; o >>= 1) s += __shfl_xor_sync(0xffffffffu, s, o);
        float sc = 0.125f / s;
        qs_s[w * HE + lane] = t0 * sc;
        qs_s[w * HE + 32 + lane] = t1 * sc;
    }
    __syncthreads();

    float pre[2], sum = 0.f, sumsq = 0.f;
    #pragma unroll
    for (int it = 0; it < 2; it++) {
        int o = tid + it * 256;
        int h = o >> 6, e = o & 63;
        const float* cb = ctx + ((size_t)(b * NH + h)) * (HE * HE) + e;
        const float* qh = qs_s + h * HE;
        float acc = 0.f;
        #pragma unroll 8
        for (int d = 0; d < HE; d++) acc += qh[d] * cb[d * HE];
        float p = acc + res[(size_t)row * DIM + o];
        pre[it] = p; sum += p; sumsq += p * p;
    }
    #pragma unroll
    for (int o = 16; o > 0; o >>= 1) {
        sum   += __shfl_xor_sync(0xffffffffu, sum, o);
        sumsq += __shfl_xor_sync(0xffffffffu, sumsq, o);
    }
    if (lane == 0) { red[w] = sum; red[8 + w] = sumsq; }
    __syncthreads();
    if (tid == 0) {
        float s = 0.f, q = 0.f;
        #pragma unroll
        for (int i = 0; i < 8; i++) { s += red[i]; q += red[8 + i]; }
        float mu = s / (float)DIM;
        float var = q / (float)DIM - mu * mu;
        red[0] = mu; red[1] = rsqrtf(var + LN_EPS);
    }
    __syncthreads();
    float mu = red[0], rstd = red[1];
    #pragma unroll
    for (int it = 0; it < 2; it++) {
        int o = tid + it * 256;
        float v = (pre[it] - mu) * rstd * g[o] + beta[o];
        out[(size_t)row * DIM + o] = v;
        oh[(size_t)row * DIM + o] = __float2half_rn(v);
    }
}

// ---------------- host launch ------------------------------------------------
extern "C" void kernel_launch(void* const* d_in, const int* in_sizes, int n_in,
                              void* d_out, int out_size)
{
    const float* x      = (const float*)d_in[0];
    const float* memory = (const float*)d_in[1];
    const float* W_qvk  = (const float*)d_in[2];
    const float* b_qvk  = (const float*)d_in[3];
    const float* W_kv   = (const float*)d_in[4];
    const float* b_kv   = (const float*)d_in[5];
    const float* W_q    = (const float*)d_in[6];
    const float* b_q    = (const float*)d_in[7];
    const float* W_ff1  = (const float*)d_in[8];
    const float* b_ff1  = (const float*)d_in[9];
    const float* W_ff2  = (const float*)d_in[10];
    const float* b_ff2  = (const float*)d_in[11];
    const float* ln1_g  = (const float*)d_in[12];
    const float* ln1_b  = (const float*)d_in[13];
    const float* ln2_g  = (const float*)d_in[14];
    const float* ln2_b  = (const float*)d_in[15];
    const float* ln3_g  = (const float*)d_in[16];
    const float* ln3_b  = (const float*)d_in[17];
    float* outp = (float*)d_out;

    float *attn1, *ln1, *q2, *colmax, *colsum, *ctxp, *ctx, *ln2, *pre3;
    float *csumK, *csumKV, *kcp, *Sp;
    __half *qvkh, *kvh, *xh, *mh, *ln1h, *ln2h, *ff1h;
    __half *wqvkh, *wkvh, *wqh, *wf1h, *wf2h;
    cudaGetSymbolAddress((void**)&attn1, g_attn1);
    cudaGetSymbolAddress((void**)&ln1,   g_ln1);
    cudaGetSymbolAddress((void**)&q2,    g_q2);
    cudaGetSymbolAddress((void**)&colmax,g_colmax);
    cudaGetSymbolAddress((void**)&colsum,g_colsum);
    cudaGetSymbolAddress((void**)&ctxp,  g_ctxp);
    cudaGetSymbolAddress((void**)&ctx,   g_ctx);
    cudaGetSymbolAddress((void**)&ln2,   g_ln2);
    cudaGetSymbolAddress((void**)&pre3,  g_pre3);
    cudaGetSymbolAddress((void**)&csumK, g_csumK);
    cudaGetSymbolAddress((void**)&csumKV,g_csumKV);
    cudaGetSymbolAddress((void**)&kcp,   g_kcp);
    cudaGetSymbolAddress((void**)&Sp,    g_Sp);
    cudaGetSymbolAddress((void**)&qvkh, g_qvkh);
    cudaGetSymbolAddress((void**)&kvh,  g_kvh);
    cudaGetSymbolAddress((void**)&xh,   g_xh);
    cudaGetSymbolAddress((void**)&mh,   g_mh);
    cudaGetSymbolAddress((void**)&ln1h, g_ln1h);
    cudaGetSymbolAddress((void**)&ln2h, g_ln2h);
    cudaGetSymbolAddress((void**)&ff1h, g_ff1h);
    cudaGetSymbolAddress((void**)&wqvkh,g_wqvkh);
    cudaGetSymbolAddress((void**)&wkvh, g_wkvh);
    cudaGetSymbolAddress((void**)&wqh,  g_wqh);
    cudaGetSymbolAddress((void**)&wf1h, g_wf1h);
    cudaGetSymbolAddress((void**)&wf2h, g_wf2h);

    const int CSMEM = (4 * 64 * 68 + 128) * (int)sizeof(float);   // 70,144 B
    cudaFuncSetAttribute(causal_chunk_kernel, cudaFuncAttributeMaxDynamicSharedMemorySize, CSMEM);
    cudaFuncSetAttribute(gemm_hf, cudaFuncAttributeMaxDynamicSharedMemorySize, GB_SMEM);

    // 0) batched fp32->fp16 conversion
    {
        ConvBatch cb;
        const float* srcs[NSEG] = {x, memory, W_qvk, W_kv, W_q, W_ff1, W_ff2};
        __half* his[NSEG] = {xh, mh, wqvkh, wkvh, wqh, wf1h, wf2h};
        int ns[NSEG] = {ROWS * DIM / 4, ROWS * DIM / 4, DIM * 3 * DIM / 4,
                        DIM * 2 * DIM / 4, DIM * DIM / 4, DIM * FF / 4, FF * DIM / 4};
        int acc_n = 0;
        for (int s = 0; s < NSEG; s++) {
            cb.src[s] = (const float4*)srcs[s];
            cb.hi[s] = (uint2*)his[s];
            acc_n += ns[s];
            cb.end[s] = acc_n;
        }
        conv_multi<<<(acc_n + 255) / 256, 256>>>(cb);
    }

    // 1) qvk = x @ W_qvk + b  -> fp16
    gemm_hf<<<dim3((3 * DIM) / 128, ROWS / 128), 256, GB_SMEM>>>(
        xh, wqvkh, b_qvk, nullptr, qvkh, ROWS, 3 * DIM, DIM, 0);
    // 2) causal linear self-attention, chunk-parallel
    chunk_sum_kernel<<<BH * NC, 256>>>(qvkh, csumK, csumKV);
    prefix_kernel<<<BH * 16, 256>>>(csumK, csumKV, kcp, Sp);
    causal_chunk_kernel<<<BH * NC, 256, CSMEM>>>(qvkh, kcp, Sp, attn1);
    // 3) LN1(attn + x) -> fp32 + fp16
    ln_res_kernel<<<ROWS, 256>>>(attn1, x, ln1_g, ln1_b, ln1, ln1h);
    // 4) kv = memory @ W_kv + b  -> fp16
    gemm_hf<<<dim3((2 * DIM) / 128, ROWS / 128), 256, GB_SMEM>>>(
        mh, wkvh, b_kv, nullptr, kvh, ROWS, 2 * DIM, DIM, 0);
    // 5) q2 = ln1 @ W_q + b
    gemm_hf<<<dim3(DIM / 128, ROWS / 128), 256, GB_SMEM>>>(
        ln1h, wqh, b_q, q2, nullptr, ROWS, DIM, DIM, 0);
    // 6) column softmax stats of k over memory rows
    col_stats_kernel<<<dim3(DIM / 32, BATCH), 256>>>(kvh, colmax, colsum);
    // 7) ctx = softk^T @ v per head (n-chunked + reduce)
    cross_ctx_kernel<<<BH * NCH, 256>>>(kvh, colmax, colsum, ctxp);
    ctx_reduce_kernel<<<BH, 256>>>(ctxp, ctx);
    // 8) out2 = softmax(q2) @ ctx, + res, LN2 (fused) -> fp32 + fp16
    cross_out_ln2_kernel<<<ROWS, 256>>>(q2, ctx, ln1, ln2_g, ln2_b, ln2, ln2h);
    // 9) ff1 = relu(ln2 @ W_ff1 + b) -> fp16 only
    gemm_hf<<<dim3(FF / 128, ROWS / 128), 256, GB_SMEM>>>(
        ln2h, wf1h, b_ff1, nullptr, ff1h, ROWS, FF, DIM, 1);
    // 10) pre3 = ff1 @ W_ff2 + b
    gemm_hf<<<dim3(DIM / 128, ROWS / 128), 256, GB_SMEM>>>(
        ff1h, wf2h, b_ff2, pre3, nullptr, ROWS, DIM, FF, 0);
    // 11) LN3(pre3 + ln2) -> output
    ln_res_kernel<<<ROWS, 256>>>(pre3, ln2, ln3_g, ln3_b, outp, nullptr);
}

// round 14
// speedup vs baseline: 10.6254x; 1.1392x over previous
#include <cuda_runtime.h>
#include <cuda_bf16.h>
#include <cuda_fp16.h>
#include <math.h>
#include <stdint.h>

// Problem dims
#define BATCH 2
#define SEQN 2048
#define SEQM 2048
#define DIM 512
#define NH 8
#define HE 64
#define FF 2048
#define ROWS (BATCH * SEQN)   // 4096
#define LN_EPS 1e-5f
#define ATTN_EPS 1e-6f

// chunked causal linear attention
#define CC 64
#define NC (SEQN / CC)        // 32
#define BH (BATCH * NH)       // 16
// cross-attn ctx n-split
#define NCH 8
#define CHROWS (SEQM / NCH)   // 256

// ---------------- scratch (device globals; no allocations allowed) ----------
__device__ float g_attn1[ROWS * DIM];
__device__ float g_ln1 [ROWS * DIM];
__device__ float g_q2  [ROWS * DIM];
__device__ float g_colmax[BATCH * DIM];
__device__ float g_colsum[BATCH * DIM];
__device__ float g_ctxp[BH * NCH * HE * HE];
__device__ float g_ctx [BH * HE * HE];
__device__ float g_ln2 [ROWS * DIM];
__device__ float g_pre3[ROWS * DIM];
// causal-chunk state
__device__ float g_csumK [BH * NC * HE];
__device__ float g_csumKV[BH * NC * HE * HE];
__device__ float g_kcp   [BH * NC * HE];
__device__ float g_Sp    [BH * NC * HE * HE];
// fp16 tensors
__device__ __half g_qvkh[ROWS * 3 * DIM];
__device__ __half g_kvh [ROWS * 2 * DIM];
__device__ __half g_xh [ROWS * DIM];
__device__ __half g_mh [ROWS * DIM];
__device__ __half g_ln1h[ROWS * DIM];
__device__ __half g_ln2h[ROWS * DIM];
__device__ __half g_ff1h[ROWS * FF];
__device__ __half g_wqvkh[DIM * 3 * DIM];
__device__ __half g_wkvh [DIM * 2 * DIM];
__device__ __half g_wqh  [DIM * DIM];
__device__ __half g_wf1h [DIM * FF];
__device__ __half g_wf2h [FF * DIM];

// ---------------- helpers ----------------------------------------------------
__device__ __forceinline__ uint32_t smem_u32(const void* p) {
    uint32_t a;
    asm("{ .reg .u64 t; cvta.to.shared.u64 t, %1; cvt.u32.u64 %0, t; }" : "=r"(a) : "l"(p));
    return a;
}
__device__ __forceinline__ void ldmat_x4(uint32_t& r0, uint32_t& r1, uint32_t& r2, uint32_t& r3,
                                         uint32_t addr) {
    asm volatile("ldmatrix.sync.aligned.m8n8.x4.shared.b16 {%0,%1,%2,%3}, [%4];"
                 : "=r"(r0), "=r"(r1), "=r"(r2), "=r"(r3) : "r"(addr));
}
__device__ __forceinline__ void ldmat_x4t(uint32_t& r0, uint32_t& r1, uint32_t& r2, uint32_t& r3,
                                          uint32_t addr) {
    asm volatile("ldmatrix.sync.aligned.m8n8.x4.trans.shared.b16 {%0,%1,%2,%3}, [%4];"
                 : "=r"(r0), "=r"(r1), "=r"(r2), "=r"(r3) : "r"(addr));
}
__device__ __forceinline__ void mma_f16(float* c, const uint32_t* a, const uint32_t* b) {
    asm volatile(
        "mma.sync.aligned.m16n8k16.row.col.f32.f16.f16.f32 "
        "{%0,%1,%2,%3}, {%4,%5,%6,%7}, {%8,%9}, {%0,%1,%2,%3};"
        : "+f"(c[0]), "+f"(c[1]), "+f"(c[2]), "+f"(c[3])
        : "r"(a[0]), "r"(a[1]), "r"(a[2]), "r"(a[3]), "r"(b[0]), "r"(b[1]));
}
#define CP_ASYNC16(dst, src) \
    asm volatile("cp.async.cg.shared.global [%0], [%1], 16;" :: "r"(dst), "l"(src) : "memory")
#define CP_COMMIT() asm volatile("cp.async.commit_group;" ::: "memory")

// ---------------- fp32 -> fp16 conversion, batched over 7 tensors -----------
#define NSEG 7
struct ConvBatch {
    const float4* src[NSEG];
    uint2* hi[NSEG];
    int end[NSEG];
};
__global__ void conv_multi(ConvBatch cb)
{
    int i = blockIdx.x * blockDim.x + threadIdx.x;
    if (i >= cb.end[NSEG - 1]) return;
    int s = 0;
    #pragma unroll
    for (int k = 0; k < NSEG - 1; k++) s += (i >= cb.end[k]);
    int j = i - (s ? cb.end[s - 1] : 0);
    float4 f = cb.src[s][j];
    __half2 ha = {__float2half_rn(f.x), __float2half_rn(f.y)};
    __half2 hb = {__float2half_rn(f.z), __float2half_rn(f.w)};
    cb.hi[s][j] = make_uint2(*(uint32_t*)&ha, *(uint32_t*)&hb);
}

// ================= fp16 tensor-core GEMM, 3-stage cp.async ===================
#define OFF_BH 10240      // A: 128 rows * 80B; B: 32 rows * 272B
#define PIPE_STAGE 18944
#define GB_SMEM (3 * PIPE_STAGE)   // 56,832 B

__global__ __launch_bounds__(256)
void gemm_hf(const __half* __restrict__ Ah, const __half* __restrict__ Bh,
             const float* __restrict__ bias, float* __restrict__ Cf,
             __half* __restrict__ Ch,
             int M, int N, int K, int relu)
{
    extern __shared__ char smc[];
    const uint32_t sb = smem_u32(smc);
    const int tid = threadIdx.x;
    const int lane = tid & 31, wid = tid >> 5;
    const int wm = (wid >> 2) * 64;
    const int wn = (wid & 3) * 32;
    const int row0 = blockIdx.y * 128, col0 = blockIdx.x * 128;

    const int a_r = tid >> 2, a_c = (tid & 3) * 16;
    const int a_r2 = (tid + 256) >> 2, a_c2 = ((tid + 256) & 3) * 16;
    const int b_kr = tid >> 4, b_c = (tid & 15) * 16;
    const int b_kr2 = (tid + 256) >> 4, b_c2 = ((tid + 256) & 15) * 16;

    float acc[4][4][4] = {};

    const int la_row  = wm + (lane & 15);
    const int la_colb = (lane >> 4) * 8;
    const int lb_row  = (lane & 7) + ((lane >> 3) & 1) * 8;
    const int lb_colb = wn + (lane >> 4) * 8;

    const int nblk = K / 32;

    #define PREFETCH(kb_, st_) do {                                                              \
        const int kq = (kb_) * 32;                                                               \
        uint32_t st = sb + (st_) * PIPE_STAGE;                                                   \
        CP_ASYNC16(st + a_r * 80 + a_c, Ah + (size_t)(row0 + a_r) * K + kq + a_c / 2);           \
        CP_ASYNC16(st + a_r2 * 80 + a_c2, Ah + (size_t)(row0 + a_r2) * K + kq + a_c2 / 2);       \
        CP_ASYNC16(st + OFF_BH + b_kr * 272 + b_c, Bh + (size_t)(kq + b_kr) * N + col0 + b_c / 2);\
        CP_ASYNC16(st + OFF_BH + b_kr2 * 272 + b_c2, Bh + (size_t)(kq + b_kr2) * N + col0 + b_c2 / 2);\
        CP_COMMIT();                                                                             \
    } while (0)

    PREFETCH(0, 0);
    if (nblk > 1) PREFETCH(1, 1);

    for (int kb = 0; kb < nblk; kb++) {
        if (kb + 1 < nblk) asm volatile("cp.async.wait_group 1;" ::: "memory");
        else               asm volatile("cp.async.wait_group 0;" ::: "memory");
        __syncthreads();
        if (kb + 2 < nblk) PREFETCH(kb + 2, (kb + 2) % 3);

        const uint32_t st = sb + (kb % 3) * PIPE_STAGE;
        #pragma unroll
        for (int ks = 0; ks < 2; ks++) {
            uint32_t ah[4][4], bf[4][2];
            #pragma unroll
            for (int mt = 0; mt < 4; mt++) {
                uint32_t off = (uint32_t)((la_row + mt * 16) * 40 + ks * 16 + la_colb) * 2;
                ldmat_x4(ah[mt][0], ah[mt][1], ah[mt][2], ah[mt][3], st + off);
            }
            #pragma unroll
            for (int p = 0; p < 2; p++) {
                uint32_t off = (uint32_t)((ks * 16 + lb_row) * 136 + lb_colb + p * 16) * 2;
                ldmat_x4t(bf[p * 2][0], bf[p * 2][1], bf[p * 2 + 1][0], bf[p * 2 + 1][1],
                          st + OFF_BH + off);
            }
            #pragma unroll
            for (int mt = 0; mt < 4; mt++)
                #pragma unroll
                for (int nt = 0; nt < 4; nt++)
                    mma_f16(acc[mt][nt], ah[mt], bf[nt]);
        }
    }

    const int r_l = lane >> 2, c_l = (lane & 3) * 2;
    #pragma unroll
    for (int mt = 0; mt < 4; mt++) {
        int row = row0 + wm + mt * 16 + r_l;
        #pragma unroll
        for (int nt = 0; nt < 4; nt++) {
            int col = col0 + wn + nt * 8 + c_l;
            float b0 = bias[col], b1 = bias[col + 1];
            float v00 = acc[mt][nt][0] + b0, v01 = acc[mt][nt][1] + b1;
            float v10 = acc[mt][nt][2] + b0, v11 = acc[mt][nt][3] + b1;
            if (relu) {
                v00 = fmaxf(v00, 0.f); v01 = fmaxf(v01, 0.f);
                v10 = fmaxf(v10, 0.f); v11 = fmaxf(v11, 0.f);
            }
            if (Cf) {
                *(float2*)(Cf + (size_t)row * N + col) = make_float2(v00, v01);
                *(float2*)(Cf + (size_t)(row + 8) * N + col) = make_float2(v10, v11);
            }
            if (Ch) {
                __half2 hp0 = {__float2half_rn(v00), __float2half_rn(v01)};
                __half2 hp1 = {__float2half_rn(v10), __float2half_rn(v11)};
                *(__half2*)(Ch + (size_t)row * N + col) = hp0;
                *(__half2*)(Ch + (size_t)(row + 8) * N + col) = hp1;
            }
        }
    }
}

// ---------------- causal chunk phase 1: per-chunk sums (fp16 in) ------------
__global__ __launch_bounds__(256)
void chunk_sum_kernel(const __half* __restrict__ qvk,
                      float* __restrict__ csumK, float* __restrict__ csumKV)
{
    const int blk = blockIdx.x;
    const int bh = blk / NC, c = blk % NC;
    const int b = bh >> 3, h = bh & 7;
    const int tid = threadIdx.x;

    __shared__ __align__(16) float Ks[CC][68];
    __shared__ __align__(16) float Vs[CC][68];

    const __half* base = qvk + (size_t)b * SEQN * (3 * DIM) + (size_t)c * CC * (3 * DIM) + h * HE;
    #pragma unroll
    for (int i = tid; i < CC * 16; i += 256) {
        int r = i >> 4;
        int col = (i & 15) * 4;
        const __half* rp = base + (size_t)r * (3 * DIM);
        __half2 k01 = *(const __half2*)(rp + 2 * DIM + col);
        __half2 k23 = *(const __half2*)(rp + 2 * DIM + col + 2);
        __half2 v01 = *(const __half2*)(rp + DIM + col);
        __half2 v23 = *(const __half2*)(rp + DIM + col + 2);
        Ks[r][col + 0] = expf(__half2float(k01.x)); Ks[r][col + 1] = expf(__half2float(k01.y));
        Ks[r][col + 2] = expf(__half2float(k23.x)); Ks[r][col + 3] = expf(__half2float(k23.y));
        Vs[r][col + 0] = __half2float(v01.x); Vs[r][col + 1] = __half2float(v01.y);
        Vs[r][col + 2] = __half2float(v23.x); Vs[r][col + 3] = __half2float(v23.y);
    }
    __syncthreads();

    const int ty = tid >> 4, tx = tid & 15;
    const int d0 = ty * 4, e0 = tx * 4;
    float acc[4][4] = {};
    #pragma unroll 8
    for (int n = 0; n < CC; n++) {
        float4 a = *(const float4*)&Ks[n][d0];
        float4 bb = *(const float4*)&Vs[n][e0];
        float av[4] = {a.x, a.y, a.z, a.w};
        float bv[4] = {bb.x, bb.y, bb.z, bb.w};
        #pragma unroll
        for (int i = 0; i < 4; i++)
            #pragma unroll
            for (int j = 0; j < 4; j++)
                acc[i][j] += av[i] * bv[j];
    }
    float* outKV = csumKV + ((size_t)bh * NC + c) * (HE * HE);
    #pragma unroll
    for (int i = 0; i < 4; i++) {
        float4 o = {acc[i][0], acc[i][1], acc[i][2], acc[i][3]};
        *(float4*)(outKV + (d0 + i) * HE + e0) = o;
    }
    if (tid < HE) {
        float s = 0.f;
        #pragma unroll 8
        for (int n = 0; n < CC; n++) s += Ks[n][tid];
        csumK[((size_t)bh * NC + c) * HE + tid] = s;
    }
}

// ---------------- causal chunk phase 2: exclusive prefix (parallel) ---------
__global__ __launch_bounds__(256)
void prefix_kernel(const float* __restrict__ csumK, const float* __restrict__ csumKV,
                   float* __restrict__ kcp, float* __restrict__ Sp)
{
    const int blk = blockIdx.x;
    const int bh = blk >> 4, seg = blk & 15;
    const int e = seg * 256 + threadIdx.x;
    const size_t stride = (size_t)(HE * HE);
    const float* src = csumKV + (size_t)bh * NC * stride + e;
    float v[NC];
    #pragma unroll
    for (int c = 0; c < NC; c++) v[c] = src[(size_t)c * stride];
    float* dst = Sp + (size_t)bh * NC * stride + e;
    float run = 0.f;
    #pragma unroll
    for (int c = 0; c < NC; c++) { dst[(size_t)c * stride] = run; run += v[c]; }

    if (seg == 0 && threadIdx.x < HE) {
        const int d = threadIdx.x;
        float vk[NC];
        #pragma unroll
        for (int c = 0; c < NC; c++) vk[c] = csumK[((size_t)bh * NC + c) * HE + d];
        float rk = 0.f;
        #pragma unroll
        for (int c = 0; c < NC; c++) { kcp[((size_t)bh * NC + c) * HE + d] = rk; rk += vk[c]; }
    }
}

// ---------------- causal chunk phase 3: per-chunk output (fp16 in) ----------
__global__ __launch_bounds__(256)
void causal_chunk_kernel(const __half* __restrict__ qvk,
                         const float* __restrict__ kcp, const float* __restrict__ Sp,
                         float* __restrict__ out)
{
    extern __shared__ __align__(16) float sm[];
    float (*TsT)[68] = (float(*)[68])sm;
    float (*KsT)[68] = TsT + 64;
    float (*Vs)[68]  = KsT + 64;
    float (*SpS)[68] = Vs + 64;
    float* kcpe = (float*)(SpS + 64);
    float* den  = kcpe + 64;
    float (*AT)[68] = KsT;     // aliased after barrier

    const int blk = blockIdx.x;
    const int bh = blk / NC, c = blk % NC;
    const int b = bh >> 3, h = bh & 7;
    const int tid = threadIdx.x;
    const __half* base = qvk + (size_t)b * SEQN * (3 * DIM) + (size_t)c * CC * (3 * DIM) + h * HE;

    {
        int r = tid >> 2;
        int g = tid & 3;
        const __half* rp = base + (size_t)r * (3 * DIM) + g * 16;
        float qv[16];
        float m = -1e30f;
        #pragma unroll
        for (int j = 0; j < 8; j++) {
            __half2 q2v = *(const __half2*)(rp + 2 * j);
            qv[2 * j] = __half2float(q2v.x); qv[2 * j + 1] = __half2float(q2v.y);
            m = fmaxf(m, fmaxf(qv[2 * j], qv[2 * j + 1]));
        }
        m = fmaxf(m, __shfl_xor_sync(0xffffffffu, m, 1));
        m = fmaxf(m, __shfl_xor_sync(0xffffffffu, m, 2));
        #pragma unroll
        for (int j = 0; j < 16; j++) TsT[g * 16 + j][r] = expf(qv[j] - m);
        const __half* rpk = rp + 2 * DIM;
        #pragma unroll
        for (int j = 0; j < 8; j++) {
            __half2 k2v = *(const __half2*)(rpk + 2 * j);
            KsT[g * 16 + 2 * j][r] = expf(__half2float(k2v.x));
            KsT[g * 16 + 2 * j + 1][r] = expf(__half2float(k2v.y));
        }
    }
    #pragma unroll
    for (int i = tid; i < CC * 16; i += 256) {
        int r = i >> 4, col = (i & 15) * 4;
        const __half* vp = base + (size_t)r * (3 * DIM) + DIM + col;
        __half2 v01 = *(const __half2*)(vp);
        __half2 v23 = *(const __half2*)(vp + 2);
        Vs[r][col + 0] = __half2float(v01.x); Vs[r][col + 1] = __half2float(v01.y);
        Vs[r][col + 2] = __half2float(v23.x); Vs[r][col + 3] = __half2float(v23.y);
    }
    const float* spb = Sp + ((size_t)bh * NC + c) * (HE * HE);
    #pragma unroll
    for (int i = tid; i < HE * 16; i += 256) {
        int r = i >> 4, col = (i & 15) * 4;
        *(float4*)&SpS[r][col] = *(const float4*)(spb + r * HE + col);
    }
    if (tid < HE) kcpe[tid] = kcp[((size_t)bh * NC + c) * HE + tid] + ATTN_EPS;
    __syncthreads();

    const int ty = tid >> 4, tx = tid & 15;
    const int t0 = ty * 4, s0 = tx * 4;

    float acc[4][4];
    {
        #pragma unroll
        for (int i = 0; i < 4; i++)
            #pragma unroll
            for (int j = 0; j < 4; j++) acc[i][j] = 0.f;
        #pragma unroll 8
        for (int d = 0; d < HE; d++) {
            float4 a = *(const float4*)&TsT[d][t0];
            float4 bb = *(const float4*)&KsT[d][s0];
            float av[4] = {a.x, a.y, a.z, a.w};
            float bv[4] = {bb.x, bb.y, bb.z, bb.w};
            #pragma unroll
            for (int i = 0; i < 4; i++)
                #pragma unroll
                for (int j = 0; j < 4; j++)
                    acc[i][j] += av[i] * bv[j];
        }
    }
    __syncthreads();
    #pragma unroll
    for (int i = 0; i < 4; i++)
        #pragma unroll
        for (int j = 0; j < 4; j++) {
            int t = t0 + i, s = s0 + j;
            AT[s][t] = (s <= t) ? acc[i][j] : 0.f;
        }
    __syncthreads();

    if (tid < 128) {
        int t = tid >> 1, half = tid & 1;
        float sd = 0.f;
        int lo = half * 32;
        #pragma unroll 8
        for (int s = lo; s < lo + 32; s++) sd += AT[s][t];
        #pragma unroll 8
        for (int d = lo; d < lo + 32; d++) sd += TsT[d][t] * kcpe[d];
        sd += __shfl_xor_sync(0xffffffffu, sd, 1);
        if (!half) den[t] = 1.0f / sd;
    }
    __syncthreads();

    {
        const int e0 = tx * 4;
        float o[4][4] = {};
        #pragma unroll 8
        for (int s = 0; s < CC; s++) {
            float4 a = *(const float4*)&AT[s][t0];
            float4 bb = *(const float4*)&Vs[s][e0];
            float av[4] = {a.x, a.y, a.z, a.w};
            float bv[4] = {bb.x, bb.y, bb.z, bb.w};
            #pragma unroll
            for (int i = 0; i < 4; i++)
                #pragma unroll
                for (int j = 0; j < 4; j++)
                    o[i][j] += av[i] * bv[j];
        }
        #pragma unroll 8
        for (int d = 0; d < HE; d++) {
            float4 a = *(const float4*)&TsT[d][t0];
            float4 bb = *(const float4*)&SpS[d][e0];
            float av[4] = {a.x, a.y, a.z, a.w};
            float bv[4] = {bb.x, bb.y, bb.z, bb.w};
            #pragma unroll
            for (int i = 0; i < 4; i++)
                #pragma unroll
                for (int j = 0; j < 4; j++)
                    o[i][j] += av[i] * bv[j];
        }
        float* ob = out + (size_t)b * SEQN * DIM + (size_t)c * CC * DIM + h * HE;
        #pragma unroll
        for (int i = 0; i < 4; i++) {
            float rcp = den[t0 + i];
            float4 ov = {o[i][0] * rcp, o[i][1] * rcp, o[i][2] * rcp, o[i][3] * rcp};
            *(float4*)(ob + (size_t)(t0 + i) * DIM + e0) = ov;
        }
    }
}

// ---------------- residual + layernorm (+ optional fp16 out) -----------------
__global__ void ln_res_kernel(const float* __restrict__ a, const float* __restrict__ r,
                              const float* __restrict__ g, const float* __restrict__ beta,
                              float* __restrict__ out, __half* __restrict__ oh)
{
    const int row = blockIdx.x;
    const int tid = threadIdx.x;
    const int w = tid >> 5, lane = tid & 31;
    __shared__ float red[16];

    float pre[2], sum = 0.f, sumsq = 0.f;
    #pragma unroll
    for (int it = 0; it < 2; it++) {
        int o = tid + it * 256;
        float p = a[(size_t)row * DIM + o] + r[(size_t)row * DIM + o];
        pre[it] = p; sum += p; sumsq += p * p;
    }
    #pragma unroll
    for (int o = 16; o > 0; o >>= 1) {
        sum   += __shfl_xor_sync(0xffffffffu, sum, o);
        sumsq += __shfl_xor_sync(0xffffffffu, sumsq, o);
    }
    if (lane == 0) { red[w] = sum; red[8 + w] = sumsq; }
    __syncthreads();
    if (tid == 0) {
        float s = 0.f, q = 0.f;
        #pragma unroll
        for (int i = 0; i < 8; i++) { s += red[i]; q += red[8 + i]; }
        float mu = s / (float)DIM;
        float var = q / (float)DIM - mu * mu;
        red[0] = mu; red[1] = rsqrtf(var + LN_EPS);
    }
    __syncthreads();
    float mu = red[0], rstd = red[1];
    #pragma unroll
    for (int it = 0; it < 2; it++) {
        int o = tid + it * 256;
        float v = (pre[it] - mu) * rstd * g[o] + beta[o];
        out[(size_t)row * DIM + o] = v;
        if (oh) oh[(size_t)row * DIM + o] = __float2half_rn(v);
    }
}

// ---------------- cross-attn: per-column softmax stats (fp16 in) ------------
__global__ void col_stats_kernel(const __half* __restrict__ kv,
                                 float* __restrict__ colmax, float* __restrict__ colsum)
{
    const int b = blockIdx.y;
    const int lane = threadIdx.x & 31;
    const int r = threadIdx.x >> 5;
    const int d = blockIdx.x * 32 + lane;
    const __half* base = kv + (size_t)b * SEQM * (2 * DIM) + d;

    __shared__ float sm[8][32];
    __shared__ float cm[32];

    float m = -1e30f;
    for (int n = r; n < SEQM; n += 8) m = fmaxf(m, __half2float(base[(size_t)n * (2 * DIM)]));
    sm[r][lane] = m;
    __syncthreads();
    if (threadIdx.x < 32) {
        float mm = sm[0][threadIdx.x];
        #pragma unroll
        for (int i = 1; i < 8; i++) mm = fmaxf(mm, sm[i][threadIdx.x]);
        cm[threadIdx.x] = mm;
        colmax[b * DIM + blockIdx.x * 32 + threadIdx.x] = mm;
    }
    __syncthreads();
    float s = 0.f;
    float mref = cm[lane];
    for (int n = r; n < SEQM; n += 8) s += expf(__half2float(base[(size_t)n * (2 * DIM)]) - mref);
    sm[r][lane] = s;
    __syncthreads();
    if (threadIdx.x < 32) {
        float ss = sm[0][threadIdx.x];
        #pragma unroll
        for (int i = 1; i < 8; i++) ss += sm[i][threadIdx.x];
        colsum[b * DIM + blockIdx.x * 32 + threadIdx.x] = ss;
    }
}

// ---------------- cross-attn: partial ctx over n-chunks (fp16 in) -----------
__global__ void cross_ctx_kernel(const __half* __restrict__ kv,
                                 const float* __restrict__ colmax, const float* __restrict__ colsum,
                                 float* __restrict__ ctxp)
{
    const int blk = blockIdx.x;
    const int bh = blk / NCH, ch = blk % NCH;
    const int b = bh >> 3, h = bh & 7;
    const int tid = threadIdx.x;
    const int tx = tid & 15, ty = tid >> 4;

    __shared__ __align__(16) float Ks[32][64];
    __shared__ __align__(16) float Vs[32][64];
    __shared__ float cm[64], ci[64];

    if (tid < 64) {
        cm[tid] = colmax[b * DIM + h * HE + tid];
        ci[tid] = 1.0f / colsum[b * DIM + h * HE + tid];
    }
    __syncthreads();

    float acc[4][4] = {};
    const __half* base = kv + (size_t)b * SEQM * (2 * DIM) + h * HE;
    const int n_lo = ch * CHROWS, n_hi = n_lo + CHROWS;
    for (int n0 = n_lo; n0 < n_hi; n0 += 32) {
        #pragma unroll
        for (int it = 0; it < 2; it++) {
            int f4 = tid + it * 256;
            int r = f4 >> 4;
            int c = (f4 & 15) * 4;
            const __half* rp = base + (size_t)(n0 + r) * (2 * DIM);
            __half2 k01 = *(const __half2*)(rp + c);
            __half2 k23 = *(const __half2*)(rp + c + 2);
            __half2 v01 = *(const __half2*)(rp + DIM + c);
            __half2 v23 = *(const __half2*)(rp + DIM + c + 2);
            Ks[r][c + 0] = expf(__half2float(k01.x) - cm[c + 0]) * ci[c + 0];
            Ks[r][c + 1] = expf(__half2float(k01.y) - cm[c + 1]) * ci[c + 1];
            Ks[r][c + 2] = expf(__half2float(k23.x) - cm[c + 2]) * ci[c + 2];
            Ks[r][c + 3] = expf(__half2float(k23.y) - cm[c + 3]) * ci[c + 3];
            Vs[r][c + 0] = __half2float(v01.x); Vs[r][c + 1] = __half2float(v01.y);
            Vs[r][c + 2] = __half2float(v23.x); Vs[r][c + 3] = __half2float(v23.y);
        }
        __syncthreads();
        #pragma unroll
        for (int r = 0; r < 32; r++) {
            float4 av = *(const float4*)&Ks[r][ty * 4];
            float4 bv = *(const float4*)&Vs[r][tx * 4];
            float a[4] = {av.x, av.y, av.z, av.w};
            float bb[4] = {bv.x, bv.y, bv.z, bv.w};
            #pragma unroll
            for (int i = 0; i < 4; i++)
                #pragma unroll
                for (int j = 0; j < 4; j++)
                    acc[i][j] += a[i] * bb[j];
        }
        __syncthreads();
    }
    float* cb = ctxp + (size_t)blk * (HE * HE);
    #pragma unroll
    for (int i = 0; i < 4; i++)
        #pragma unroll
        for (int j = 0; j < 4; j++)
            cb[(ty * 4 + i) * HE + tx * 4 + j] = acc[i][j];
}

__global__ void ctx_reduce_kernel(const float* __restrict__ ctxp, float* __restrict__ ctx)
{
    const int bh = blockIdx.x;
    const int tid = threadIdx.x;
    size_t o = (size_t)tid * 16;
    float4 s[4];
    #pragma unroll
    for (int i = 0; i < 4; i++) s[i] = make_float4(0.f, 0.f, 0.f, 0.f);
    #pragma unroll
    for (int ch = 0; ch < NCH; ch++) {
        const float4* src = (const float4*)(ctxp + ((size_t)bh * NCH + ch) * (HE * HE) + o);
        #pragma unroll
        for (int i = 0; i < 4; i++) {
            float4 v = src[i];
            s[i].x += v.x; s[i].y += v.y; s[i].z += v.z; s[i].w += v.w;
        }
    }
    float4* dst = (float4*)(ctx + (size_t)bh * (HE * HE) + o);
    #pragma unroll
    for (int i = 0; i < 4; i++) dst[i] = s[i];
}

// ---------------- cross-attn output + residual + LN2 (+ fp16 out) -----------
__global__ void cross_out_ln2_kernel(const float* __restrict__ q2, const float* __restrict__ ctx,
                                     const float* __restrict__ res, const float* __restrict__ g,
                                     const float* __restrict__ beta, float* __restrict__ out,
                                     __half* __restrict__ oh)
{
    const int row = blockIdx.x;
    const int b = row >> 11;
    const int tid = threadIdx.x;
    const int w = tid >> 5, lane = tid & 31;

    __shared__ float qs_s[DIM];
    __shared__ float red[16];

    const float* qr = q2 + (size_t)row * DIM;
    {
        float a0 = qr[w * HE + lane], a1 = qr[w * HE + 32 + lane];
        float m = fmaxf(a0, a1);
        #pragma unroll
        for (int o = 16; o > 0; o >>= 1) m = fmaxf(m, __shfl_xor_sync(0xffffffffu, m, o));
        float t0 = expf(a0 - m), t1 = expf(a1 - m);
        float s = t0 + t1;
        #pragma unroll
        for (int o = 16; o > 0; o >>= 1) s += __shfl_xor_sync(0xffffffffu, s, o);
        float sc = 0.125f / s;
        qs_s[w * HE + lane] = t0 * sc;
        qs_s[w * HE + 32 + lane] = t1 * sc;
    }
    __syncthreads();

    float pre[2], sum = 0.f, sumsq = 0.f;
    #pragma unroll
    for (int it = 0; it < 2; it++) {
        int o = tid + it * 256;
        int h = o >> 6, e = o & 63;
        const float* cb = ctx + ((size_t)(b * NH + h)) * (HE * HE) + e;
        const float* qh = qs_s + h * HE;
        float acc = 0.f;
        #pragma unroll 8
        for (int d = 0; d < HE; d++) acc += qh[d] * cb[d * HE];
        float p = acc + res[(size_t)row * DIM + o];
        pre[it] = p; sum += p; sumsq += p * p;
    }
    #pragma unroll
    for (int o = 16; o > 0; o >>= 1) {
        sum   += __shfl_xor_sync(0xffffffffu, sum, o);
        sumsq += __shfl_xor_sync(0xffffffffu, sumsq, o);
    }
    if (lane == 0) { red[w] = sum; red[8 + w] = sumsq; }
    __syncthreads();
    if (tid == 0) {
        float s = 0.f, q = 0.f;
        #pragma unroll
        for (int i = 0; i < 8; i++) { s += red[i]; q += red[8 + i]; }
        float mu = s / (float)DIM;
        float var = q / (float)DIM - mu * mu;
        red[0] = mu; red[1] = rsqrtf(var + LN_EPS);
    }
    __syncthreads();
    float mu = red[0], rstd = red[1];
    #pragma unroll
    for (int it = 0; it < 2; it++) {
        int o = tid + it * 256;
        float v = (pre[it] - mu) * rstd * g[o] + beta[o];
        out[(size_t)row * DIM + o] = v;
        oh[(size_t)row * DIM + o] = __float2half_rn(v);
    }
}

// ---------------- host launch ------------------------------------------------
extern "C" void kernel_launch(void* const* d_in, const int* in_sizes, int n_in,
                              void* d_out, int out_size)
{
    const float* x      = (const float*)d_in[0];
    const float* memory = (const float*)d_in[1];
    const float* W_qvk  = (const float*)d_in[2];
    const float* b_qvk  = (const float*)d_in[3];
    const float* W_kv   = (const float*)d_in[4];
    const float* b_kv   = (const float*)d_in[5];
    const float* W_q    = (const float*)d_in[6];
    const float* b_q    = (const float*)d_in[7];
    const float* W_ff1  = (const float*)d_in[8];
    const float* b_ff1  = (const float*)d_in[9];
    const float* W_ff2  = (const float*)d_in[10];
    const float* b_ff2  = (const float*)d_in[11];
    const float* ln1_g  = (const float*)d_in[12];
    const float* ln1_b  = (const float*)d_in[13];
    const float* ln2_g  = (const float*)d_in[14];
    const float* ln2_b  = (const float*)d_in[15];
    const float* ln3_g  = (const float*)d_in[16];
    const float* ln3_b  = (const float*)d_in[17];
    float* outp = (float*)d_out;

    float *attn1, *ln1, *q2, *colmax, *colsum, *ctxp, *ctx, *ln2, *pre3;
    float *csumK, *csumKV, *kcp, *Sp;
    __half *qvkh, *kvh, *xh, *mh, *ln1h, *ln2h, *ff1h;
    __half *wqvkh, *wkvh, *wqh, *wf1h, *wf2h;
    cudaGetSymbolAddress((void**)&attn1, g_attn1);
    cudaGetSymbolAddress((void**)&ln1,   g_ln1);
    cudaGetSymbolAddress((void**)&q2,    g_q2);
    cudaGetSymbolAddress((void**)&colmax,g_colmax);
    cudaGetSymbolAddress((void**)&colsum,g_colsum);
    cudaGetSymbolAddress((void**)&ctxp,  g_ctxp);
    cudaGetSymbolAddress((void**)&ctx,   g_ctx);
    cudaGetSymbolAddress((void**)&ln2,   g_ln2);
    cudaGetSymbolAddress((void**)&pre3,  g_pre3);
    cudaGetSymbolAddress((void**)&csumK, g_csumK);
    cudaGetSymbolAddress((void**)&csumKV,g_csumKV);
    cudaGetSymbolAddress((void**)&kcp,   g_kcp);
    cudaGetSymbolAddress((void**)&Sp,    g_Sp);
    cudaGetSymbolAddress((void**)&qvkh, g_qvkh);
    cudaGetSymbolAddress((void**)&kvh,  g_kvh);
    cudaGetSymbolAddress((void**)&xh,   g_xh);
    cudaGetSymbolAddress((void**)&mh,   g_mh);
    cudaGetSymbolAddress((void**)&ln1h, g_ln1h);
    cudaGetSymbolAddress((void**)&ln2h, g_ln2h);
    cudaGetSymbolAddress((void**)&ff1h, g_ff1h);
    cudaGetSymbolAddress((void**)&wqvkh,g_wqvkh);
    cudaGetSymbolAddress((void**)&wkvh, g_wkvh);
    cudaGetSymbolAddress((void**)&wqh,  g_wqh);
    cudaGetSymbolAddress((void**)&wf1h, g_wf1h);
    cudaGetSymbolAddress((void**)&wf2h, g_wf2h);

    const int CSMEM = (4 * 64 * 68 + 128) * (int)sizeof(float);   // 70,144 B
    cudaFuncSetAttribute(causal_chunk_kernel, cudaFuncAttributeMaxDynamicSharedMemorySize, CSMEM);
    cudaFuncSetAttribute(gemm_hf, cudaFuncAttributeMaxDynamicSharedMemorySize, GB_SMEM);

    // Fork/join side stream for the independent kv/cross-attn branch.
    // Created fresh per call (kernel_launch runs only a handful of times:
    // correctness + capture), non-blocking to avoid legacy-stream sync during
    // capture; never destroyed (graph retains references).
    cudaStream_t s2;
    cudaStreamCreateWithFlags(&s2, cudaStreamNonBlocking);
    cudaEvent_t evRoot, evB;
    cudaEventCreateWithFlags(&evRoot, cudaEventDisableTiming);
    cudaEventCreateWithFlags(&evB, cudaEventDisableTiming);

    // 0) batched fp32->fp16 conversion (both branches depend on it)
    {
        ConvBatch cb;
        const float* srcs[NSEG] = {x, memory, W_qvk, W_kv, W_q, W_ff1, W_ff2};
        __half* his[NSEG] = {xh, mh, wqvkh, wkvh, wqh, wf1h, wf2h};
        int ns[NSEG] = {ROWS * DIM / 4, ROWS * DIM / 4, DIM * 3 * DIM / 4,
                        DIM * 2 * DIM / 4, DIM * DIM / 4, DIM * FF / 4, FF * DIM / 4};
        int acc_n = 0;
        for (int s = 0; s < NSEG; s++) {
            cb.src[s] = (const float4*)srcs[s];
            cb.hi[s] = (uint2*)his[s];
            acc_n += ns[s];
            cb.end[s] = acc_n;
        }
        conv_multi<<<(acc_n + 255) / 256, 256>>>(cb);
    }
    cudaEventRecord(evRoot, 0);
    cudaStreamWaitEvent(s2, evRoot, 0);

    // ---- Branch B (side stream): kv GEMM -> cross-attn ctx ----
    gemm_hf<<<dim3((2 * DIM) / 128, ROWS / 128), 256, GB_SMEM, s2>>>(
        mh, wkvh, b_kv, nullptr, kvh, ROWS, 2 * DIM, DIM, 0);
    col_stats_kernel<<<dim3(DIM / 32, BATCH), 256, 0, s2>>>(kvh, colmax, colsum);
    cross_ctx_kernel<<<BH * NCH, 256, 0, s2>>>(kvh, colmax, colsum, ctxp);
    ctx_reduce_kernel<<<BH, 256, 0, s2>>>(ctxp, ctx);
    cudaEventRecord(evB, s2);

    // ---- Branch A (main stream): causal self-attention path ----
    gemm_hf<<<dim3((3 * DIM) / 128, ROWS / 128), 256, GB_SMEM>>>(
        xh, wqvkh, b_qvk, nullptr, qvkh, ROWS, 3 * DIM, DIM, 0);
    chunk_sum_kernel<<<BH * NC, 256>>>(qvkh, csumK, csumKV);
    prefix_kernel<<<BH * 16, 256>>>(csumK, csumKV, kcp, Sp);
    causal_chunk_kernel<<<BH * NC, 256, CSMEM>>>(qvkh, kcp, Sp, attn1);
    ln_res_kernel<<<ROWS, 256>>>(attn1, x, ln1_g, ln1_b, ln1, ln1h);
    gemm_hf<<<dim3(DIM / 128, ROWS / 128), 256, GB_SMEM>>>(
        ln1h, wqh, b_q, q2, nullptr, ROWS, DIM, DIM, 0);

    // ---- Join: cross-attn output needs q2 (A) + ctx (B) ----
    cudaStreamWaitEvent(0, evB, 0);
    cross_out_ln2_kernel<<<ROWS, 256>>>(q2, ctx, ln1, ln2_g, ln2_b, ln2, ln2h);
    // FFN
    gemm_hf<<<dim3(FF / 128, ROWS / 128), 256, GB_SMEM>>>(
        ln2h, wf1h, b_ff1, nullptr, ff1h, ROWS, FF, DIM, 1);
    gemm_hf<<<dim3(DIM / 128, ROWS / 128), 256, GB_SMEM>>>(
        ff1h, wf2h, b_ff2, pre3, nullptr, ROWS, DIM, FF, 0);
    ln_res_kernel<<<ROWS, 256>>>(pre3, ln2, ln3_g, ln3_b, outp, nullptr);
}